// round 1
// baseline (speedup 1.0000x reference)
#include <cuda_runtime.h>

#define BATCH 8
#define HW    2304        // 48*48
#define CH    256
#define SPLIT 8
#define MSLICE (HW / SPLIT)   // 288

// Scratch (device globals: allocation-free rule)
__device__ float g_Gpart[SPLIT][BATCH][CH][CH];   // 16 MB
__device__ float g_G[BATCH][CH][CH];              // 2 MB
__device__ float g_S[BATCH][HW];                  // 72 KB

// ---------------------------------------------------------------------------
// Kernel 1: partial Gram matrices.  G_part[s][b] = sum_{m in slice s} A_m A_m^T
// 64x64 output tile per block, K-loop over the m-slice.
// ---------------------------------------------------------------------------
__global__ __launch_bounds__(256) void gram_partial_kernel(const float* __restrict__ A)
{
    const int b     = blockIdx.z;
    const int slice = blockIdx.y;
    const int c1_0  = (blockIdx.x >> 2) * 64;
    const int c2_0  = (blockIdx.x & 3)  * 64;
    const float* Ab = A + (size_t)b * HW * CH;

    __shared__ float As[16][68];
    __shared__ float Bs[16][68];

    const int tid = threadIdx.x;
    const int lr  = tid >> 4;         // k-row within tile (0..15)
    const int lc  = (tid & 15) * 4;   // c-col (0..60)
    const int tx  = tid & 15;
    const int ty  = tid >> 4;

    float acc[4][4] = {};

    for (int it = 0; it < MSLICE / 16; ++it) {
        const int m0 = slice * MSLICE + it * 16;
        float4 a = *(const float4*)&Ab[(size_t)(m0 + lr) * CH + c1_0 + lc];
        float4 c = *(const float4*)&Ab[(size_t)(m0 + lr) * CH + c2_0 + lc];
        __syncthreads();
        *(float4*)&As[lr][lc] = a;
        *(float4*)&Bs[lr][lc] = c;
        __syncthreads();
        #pragma unroll
        for (int k = 0; k < 16; ++k) {
            float4 av = *(float4*)&As[k][ty * 4];
            float4 bv = *(float4*)&Bs[k][tx * 4];
            float ar[4] = {av.x, av.y, av.z, av.w};
            float br[4] = {bv.x, bv.y, bv.z, bv.w};
            #pragma unroll
            for (int i = 0; i < 4; ++i)
                #pragma unroll
                for (int j = 0; j < 4; ++j)
                    acc[i][j] += ar[i] * br[j];
        }
    }

    #pragma unroll
    for (int i = 0; i < 4; ++i) {
        float4 v = make_float4(acc[i][0], acc[i][1], acc[i][2], acc[i][3]);
        *(float4*)&g_Gpart[slice][b][c1_0 + ty * 4 + i][c2_0 + tx * 4] = v;
    }
}

// ---------------------------------------------------------------------------
// Kernel 2: deterministic reduction of the SPLIT partial Gram slices.
// ---------------------------------------------------------------------------
__global__ __launch_bounds__(256) void gram_reduce_kernel()
{
    const int total = BATCH * CH * CH;
    const float* p = &g_Gpart[0][0][0][0];
    float* g = &g_G[0][0][0];
    for (int i = blockIdx.x * blockDim.x + threadIdx.x; i < total;
         i += gridDim.x * blockDim.x) {
        float s = 0.f;
        #pragma unroll
        for (int k = 0; k < SPLIT; ++k) s += p[k * total + i];
        g[i] = s;
    }
}

// ---------------------------------------------------------------------------
// Kernel 3: column scales  s[b][n] = rsqrt( u^T G_b u ),  u = B_b[n].
// 32 rows of B per block; G accessed by COLUMN (G symmetric) so LDGs coalesce.
// Deterministic reduction via warp shuffles (no float atomics).
// ---------------------------------------------------------------------------
__global__ __launch_bounds__(256) void scale_kernel(const float* __restrict__ B)
{
    const int b  = blockIdx.y;
    const int n0 = blockIdx.x * 32;
    const float* Bb = B + (size_t)b * HW * CH;

    __shared__ float U[32][CH];     // 32 KB
    __shared__ float wq[8][32];

    const int tid = threadIdx.x;

    // load 32 rows of B (8 float4 per thread, coalesced)
    #pragma unroll
    for (int j = 0; j < 8; ++j) {
        int f = j * 256 + tid;           // float4 index, 0..2047
        int n = f >> 6;                  // row 0..31
        int c4 = (f & 63) * 4;
        *(float4*)&U[n][c4] = *(const float4*)&Bb[(size_t)(n0 + n) * CH + c4];
    }
    __syncthreads();

    // v2[n] = sum_c2 G[c2][c] * U[n][c2]   (c = tid; symmetric G -> column read)
    const float* Gb = &g_G[b][0][0];
    const int c = tid;
    float acc[32] = {};
    for (int c2 = 0; c2 < CH; c2 += 4) {
        float g0 = Gb[(c2 + 0) * CH + c];
        float g1 = Gb[(c2 + 1) * CH + c];
        float g2 = Gb[(c2 + 2) * CH + c];
        float g3 = Gb[(c2 + 3) * CH + c];
        #pragma unroll
        for (int n = 0; n < 32; ++n) {
            float4 u = *(const float4*)&U[n][c2];
            acc[n] += g0 * u.x + g1 * u.y + g2 * u.z + g3 * u.w;
        }
    }

    // q[n] = sum_c U[n][c] * v2[n]  -- componentwise butterfly reduce
    const int warp = tid >> 5, lane = tid & 31;
    #pragma unroll
    for (int n = 0; n < 32; ++n) {
        float v = U[n][c] * acc[n];
        #pragma unroll
        for (int off = 16; off > 0; off >>= 1)
            v += __shfl_xor_sync(0xffffffffu, v, off);
        if (lane == 0) wq[warp][n] = v;
    }
    __syncthreads();
    if (tid < 32) {
        float q = 0.f;
        #pragma unroll
        for (int w = 0; w < 8; ++w) q += wq[w][tid];
        g_S[b][n0 + tid] = rsqrtf(q);
    }
}

// ---------------------------------------------------------------------------
// Kernel 4: main batched GEMM  out[b][m][n] = (A_m . B_n) * s[b][n]
// 128x128 tile, BK=16, 256 threads, 8x8 per thread, fused scale epilogue.
// ---------------------------------------------------------------------------
__global__ __launch_bounds__(256, 2) void corr_kernel(const float* __restrict__ A,
                                                      const float* __restrict__ B,
                                                      float* __restrict__ out)
{
    const int b  = blockIdx.z;
    const int m0 = blockIdx.y * 128;
    const int n0 = blockIdx.x * 128;
    const float* Ab = A + (size_t)b * HW * CH;
    const float* Bb = B + (size_t)b * HW * CH;

    __shared__ float As[16][132];   // [k][m], padded
    __shared__ float Bs[16][132];   // [k][n], padded

    const int tid = threadIdx.x;
    const int lr  = tid >> 2;          // 0..63
    const int lc  = (tid & 3) * 4;     // 0,4,8,12
    const int tx  = tid & 15;
    const int ty  = tid >> 4;

    float acc[8][8] = {};

    for (int k0 = 0; k0 < CH; k0 += 16) {
        float4 a0 = *(const float4*)&Ab[(size_t)(m0 + lr)      * CH + k0 + lc];
        float4 a1 = *(const float4*)&Ab[(size_t)(m0 + lr + 64) * CH + k0 + lc];
        float4 b0 = *(const float4*)&Bb[(size_t)(n0 + lr)      * CH + k0 + lc];
        float4 b1 = *(const float4*)&Bb[(size_t)(n0 + lr + 64) * CH + k0 + lc];
        __syncthreads();
        As[lc + 0][lr] = a0.x; As[lc + 1][lr] = a0.y;
        As[lc + 2][lr] = a0.z; As[lc + 3][lr] = a0.w;
        As[lc + 0][lr + 64] = a1.x; As[lc + 1][lr + 64] = a1.y;
        As[lc + 2][lr + 64] = a1.z; As[lc + 3][lr + 64] = a1.w;
        Bs[lc + 0][lr] = b0.x; Bs[lc + 1][lr] = b0.y;
        Bs[lc + 2][lr] = b0.z; Bs[lc + 3][lr] = b0.w;
        Bs[lc + 0][lr + 64] = b1.x; Bs[lc + 1][lr + 64] = b1.y;
        Bs[lc + 2][lr + 64] = b1.z; Bs[lc + 3][lr + 64] = b1.w;
        __syncthreads();

        #pragma unroll
        for (int k = 0; k < 16; ++k) {
            float4 av0 = *(float4*)&As[k][ty * 8];
            float4 av1 = *(float4*)&As[k][ty * 8 + 4];
            float4 bv0 = *(float4*)&Bs[k][tx * 8];
            float4 bv1 = *(float4*)&Bs[k][tx * 8 + 4];
            float ar[8] = {av0.x, av0.y, av0.z, av0.w, av1.x, av1.y, av1.z, av1.w};
            float br[8] = {bv0.x, bv0.y, bv0.z, bv0.w, bv1.x, bv1.y, bv1.z, bv1.w};
            #pragma unroll
            for (int i = 0; i < 8; ++i)
                #pragma unroll
                for (int j = 0; j < 8; ++j)
                    acc[i][j] += ar[i] * br[j];
        }
    }

    // fused epilogue: column scale then store (output written exactly once)
    float4 s0 = *(const float4*)&g_S[b][n0 + tx * 8];
    float4 s1 = *(const float4*)&g_S[b][n0 + tx * 8 + 4];
    float sv[8] = {s0.x, s0.y, s0.z, s0.w, s1.x, s1.y, s1.z, s1.w};

    float* ob = out + (size_t)b * HW * HW;
    #pragma unroll
    for (int i = 0; i < 8; ++i) {
        const size_t row = (size_t)(m0 + ty * 8 + i) * HW + n0 + tx * 8;
        float4 v0 = make_float4(acc[i][0] * sv[0], acc[i][1] * sv[1],
                                acc[i][2] * sv[2], acc[i][3] * sv[3]);
        float4 v1 = make_float4(acc[i][4] * sv[4], acc[i][5] * sv[5],
                                acc[i][6] * sv[6], acc[i][7] * sv[7]);
        *(float4*)&ob[row]     = v0;
        *(float4*)&ob[row + 4] = v1;
    }
}

// ---------------------------------------------------------------------------
extern "C" void kernel_launch(void* const* d_in, const int* in_sizes, int n_in,
                              void* d_out, int out_size)
{
    const float* A = (const float*)d_in[0];
    const float* B = (const float*)d_in[1];
    float* out = (float*)d_out;

    gram_partial_kernel<<<dim3(16, SPLIT, BATCH), 256>>>(A);
    gram_reduce_kernel<<<1024, 256>>>();
    scale_kernel<<<dim3(HW / 32, BATCH), 256>>>(B);
    corr_kernel<<<dim3(HW / 128, HW / 128, BATCH), 256>>>(A, B, out);
}

// round 4
// speedup vs baseline: 1.7490x; 1.7490x over previous
#include <cuda_runtime.h>
#include <cuda_bf16.h>
#include <cstdint>

#define BATCH 8
#define HW    2304        // 48*48
#define CH    256
#define K2    512         // scratch layout: [hi(256) | lo(256)]
#define SPLIT 8
#define MSLICE (HW / SPLIT)

// ---------------- scratch (device globals: allocation-free rule) -----------
__device__ float g_Gpart[SPLIT][BATCH][CH][CH];   // 16 MB
__device__ float g_G[BATCH][CH][CH];              // 2 MB
__device__ float g_S[BATCH][HW];                  // 72 KB
__device__ __nv_bfloat16 g_Abf[(size_t)BATCH * HW * K2];  // 18.9 MB
__device__ __nv_bfloat16 g_Bbf[(size_t)BATCH * HW * K2];  // 18.9 MB

__device__ __forceinline__ uint32_t smem_u32(const void* p) {
    return (uint32_t)__cvta_generic_to_shared((void*)p);
}
__device__ __forceinline__ uint32_t sw128(uint32_t off) {
    return off ^ ((off >> 3) & 0x70);
}

// ---------------------------------------------------------------------------
// convert: fp32 [B*HW, CH] -> bf16 split [B*HW, K2] ([0,256)=hi, [256,512)=lo)
// ---------------------------------------------------------------------------
__global__ __launch_bounds__(256) void convert_kernel(const float* __restrict__ X,
                                                      __nv_bfloat16* __restrict__ Y)
{
    const size_t total4 = (size_t)BATCH * HW * CH / 4;
    for (size_t i = (size_t)blockIdx.x * blockDim.x + threadIdx.x; i < total4;
         i += (size_t)gridDim.x * blockDim.x) {
        float4 v = ((const float4*)X)[i];
        size_t row = i >> 6;
        int c = (int)(i & 63) * 4;
        float vv[4] = {v.x, v.y, v.z, v.w};
        __nv_bfloat16 hi[4], lo[4];
        #pragma unroll
        for (int j = 0; j < 4; ++j) {
            hi[j] = __float2bfloat16(vv[j]);
            lo[j] = __float2bfloat16(vv[j] - __bfloat162float(hi[j]));
        }
        __nv_bfloat162* ph = (__nv_bfloat162*)&Y[row * K2 + c];
        __nv_bfloat162* pl = (__nv_bfloat162*)&Y[row * K2 + CH + c];
        ph[0] = __nv_bfloat162{hi[0], hi[1]};
        ph[1] = __nv_bfloat162{hi[2], hi[3]};
        pl[0] = __nv_bfloat162{lo[0], lo[1]};
        pl[1] = __nv_bfloat162{lo[2], lo[3]};
    }
}

// ---------------------------------------------------------------------------
// Kernel 1: partial Gram matrices
// ---------------------------------------------------------------------------
__global__ __launch_bounds__(256) void gram_partial_kernel(const float* __restrict__ A)
{
    const int b     = blockIdx.z;
    const int slice = blockIdx.y;
    const int c1_0  = (blockIdx.x >> 2) * 64;
    const int c2_0  = (blockIdx.x & 3)  * 64;
    const float* Ab = A + (size_t)b * HW * CH;

    __shared__ float As[16][68];
    __shared__ float Bs[16][68];

    const int tid = threadIdx.x;
    const int lr  = tid >> 4;
    const int lc  = (tid & 15) * 4;
    const int tx  = tid & 15;
    const int ty  = tid >> 4;

    float acc[4][4] = {};

    for (int it = 0; it < MSLICE / 16; ++it) {
        const int m0 = slice * MSLICE + it * 16;
        float4 a = *(const float4*)&Ab[(size_t)(m0 + lr) * CH + c1_0 + lc];
        float4 c = *(const float4*)&Ab[(size_t)(m0 + lr) * CH + c2_0 + lc];
        __syncthreads();
        *(float4*)&As[lr][lc] = a;
        *(float4*)&Bs[lr][lc] = c;
        __syncthreads();
        #pragma unroll
        for (int k = 0; k < 16; ++k) {
            float4 av = *(float4*)&As[k][ty * 4];
            float4 bv = *(float4*)&Bs[k][tx * 4];
            float ar[4] = {av.x, av.y, av.z, av.w};
            float br[4] = {bv.x, bv.y, bv.z, bv.w};
            #pragma unroll
            for (int i = 0; i < 4; ++i)
                #pragma unroll
                for (int j = 0; j < 4; ++j)
                    acc[i][j] += ar[i] * br[j];
        }
    }

    #pragma unroll
    for (int i = 0; i < 4; ++i) {
        float4 v = make_float4(acc[i][0], acc[i][1], acc[i][2], acc[i][3]);
        *(float4*)&g_Gpart[slice][b][c1_0 + ty * 4 + i][c2_0 + tx * 4] = v;
    }
}

// ---------------------------------------------------------------------------
// Kernel 2: deterministic Gram reduce
// ---------------------------------------------------------------------------
__global__ __launch_bounds__(256) void gram_reduce_kernel()
{
    const int total = BATCH * CH * CH;
    const float* p = &g_Gpart[0][0][0][0];
    float* g = &g_G[0][0][0];
    for (int i = blockIdx.x * blockDim.x + threadIdx.x; i < total;
         i += gridDim.x * blockDim.x) {
        float s = 0.f;
        #pragma unroll
        for (int k = 0; k < SPLIT; ++k) s += p[k * total + i];
        g[i] = s;
    }
}

// ---------------------------------------------------------------------------
// Kernel 3: column scales  s[b][n] = rsqrt( u^T G_b u )
// ---------------------------------------------------------------------------
__global__ __launch_bounds__(256) void scale_kernel(const float* __restrict__ B)
{
    const int b  = blockIdx.y;
    const int n0 = blockIdx.x * 32;
    const float* Bb = B + (size_t)b * HW * CH;

    __shared__ float U[32][CH];
    __shared__ float wq[8][32];

    const int tid = threadIdx.x;

    #pragma unroll
    for (int j = 0; j < 8; ++j) {
        int f = j * 256 + tid;
        int n = f >> 6;
        int c4 = (f & 63) * 4;
        *(float4*)&U[n][c4] = *(const float4*)&Bb[(size_t)(n0 + n) * CH + c4];
    }
    __syncthreads();

    const float* Gb = &g_G[b][0][0];
    const int c = tid;
    float acc[32] = {};
    for (int c2 = 0; c2 < CH; c2 += 4) {
        float g0 = Gb[(c2 + 0) * CH + c];
        float g1 = Gb[(c2 + 1) * CH + c];
        float g2 = Gb[(c2 + 2) * CH + c];
        float g3 = Gb[(c2 + 3) * CH + c];
        #pragma unroll
        for (int n = 0; n < 32; ++n) {
            float4 u = *(const float4*)&U[n][c2];
            acc[n] += g0 * u.x + g1 * u.y + g2 * u.z + g3 * u.w;
        }
    }

    const int warp = tid >> 5, lane = tid & 31;
    #pragma unroll
    for (int n = 0; n < 32; ++n) {
        float v = U[n][c] * acc[n];
        #pragma unroll
        for (int off = 16; off > 0; off >>= 1)
            v += __shfl_xor_sync(0xffffffffu, v, off);
        if (lane == 0) wq[warp][n] = v;
    }
    __syncthreads();
    if (tid < 32) {
        float q = 0.f;
        #pragma unroll
        for (int w = 0; w < 8; ++w) q += wq[w][tid];
        g_S[b][n0 + tid] = rsqrtf(q);
    }
}

// ---------------------------------------------------------------------------
// Kernel 4: mma.sync (HMMA) main GEMM with fused column-scale epilogue.
// 128x128 CTA tile, 8 warps (4 x-m, 2 x-n).
// 3-term split product over 12 K-chunks of 64 bf16:
//   c 0-3: Ahi*Bhi   c 4-7: Alo*Bhi   c 8-11: Ahi*Blo   (lo*lo dropped)
// cp.async double-buffered SW128 smem, ldmatrix fragments.
// ---------------------------------------------------------------------------
#define CHUNK_BYTES 16384                 // 128 rows x 128 B
#define BUF_BYTES   (2 * CHUNK_BYTES)     // A + B tiles per stage
#define SMEM_TOTAL  (2 * BUF_BYTES)       // 65536
#define NCHUNK      12

__device__ __forceinline__ void ldsm_x4(uint32_t* r, uint32_t addr) {
    asm volatile("ldmatrix.sync.aligned.m8n8.x4.shared.b16 {%0,%1,%2,%3}, [%4];"
                 : "=r"(r[0]), "=r"(r[1]), "=r"(r[2]), "=r"(r[3]) : "r"(addr));
}
__device__ __forceinline__ void mma16816(float* c, const uint32_t* a,
                                         uint32_t b0, uint32_t b1) {
    asm volatile("mma.sync.aligned.m16n8k16.row.col.f32.bf16.bf16.f32 "
                 "{%0,%1,%2,%3}, {%4,%5,%6,%7}, {%8,%9}, {%0,%1,%2,%3};"
                 : "+f"(c[0]), "+f"(c[1]), "+f"(c[2]), "+f"(c[3])
                 : "r"(a[0]), "r"(a[1]), "r"(a[2]), "r"(a[3]), "r"(b0), "r"(b1));
}
__device__ __forceinline__ void cp_async16(uint32_t dst, const void* src) {
    asm volatile("cp.async.cg.shared.global [%0], [%1], 16;" :: "r"(dst), "l"(src));
}
__device__ __forceinline__ void cp_commit() {
    asm volatile("cp.async.commit_group;" ::: "memory");
}
template <int N> __device__ __forceinline__ void cp_wait() {
    asm volatile("cp.async.wait_group %0;" :: "n"(N) : "memory");
}

__global__ __launch_bounds__(256, 2) void corr_mma_kernel(float* __restrict__ out)
{
    extern __shared__ char smem[];
    const uint32_t smem_base = smem_u32(smem);
    const int tid  = threadIdx.x;
    const int wid  = tid >> 5;
    const int lane = tid & 31;

    const int b  = blockIdx.z;
    const int m0 = blockIdx.y * 128;
    const int n0 = blockIdx.x * 128;

    const __nv_bfloat16* Ab = g_Abf + ((size_t)b * HW + m0) * K2;
    const __nv_bfloat16* Bb = g_Bbf + ((size_t)b * HW + n0) * K2;

    // per-chunk K offsets (elements) into the [hi|lo] scratch rows
    // c 0-3: (hi,hi)  c 4-7: (lo,hi)  c 8-11: (hi,lo)
    const int a_k0[NCHUNK] = {0,64,128,192, 256,320,384,448, 0,64,128,192};
    const int b_k0[NCHUNK] = {0,64,128,192, 0,64,128,192, 256,320,384,448};

    // ---- per-thread cp.async slots (8 x 16B per stage) ----
    uint32_t dstoff[8];
    const __nv_bfloat16* srcp[8];   // base of row (without chunk K offset)
    bool isA[8];
    #pragma unroll
    for (int it = 0; it < 8; ++it) {
        int idx = it * 256 + tid;            // 0..2047
        int li  = idx & 1023;
        int row = li >> 3;
        int seg = li & 7;
        isA[it] = (idx < 1024);
        dstoff[it] = (isA[it] ? 0u : (uint32_t)CHUNK_BYTES)
                   + sw128((uint32_t)(row * 128 + seg * 16));
        srcp[it] = (isA[it] ? Ab : Bb) + (size_t)row * K2 + seg * 8;
    }

    auto load_chunk = [&](int c, int buf) {
        const uint32_t base = smem_base + buf * BUF_BYTES;
        const int ao = a_k0[c], bo = b_k0[c];
        #pragma unroll
        for (int it = 0; it < 8; ++it)
            cp_async16(base + dstoff[it], srcp[it] + (isA[it] ? ao : bo));
        cp_commit();
    };

    const int wm = (wid & 3) * 32;   // warp m-offset
    const int wn = (wid >> 2) * 64;  // warp n-offset

    float acc[2][8][4] = {};

    load_chunk(0, 0);

    for (int c = 0; c < NCHUNK; ++c) {
        if (c + 1 < NCHUNK) load_chunk(c + 1, (c + 1) & 1);
        if (c + 1 < NCHUNK) cp_wait<1>(); else cp_wait<0>();
        __syncthreads();

        const uint32_t aBase = smem_base + (c & 1) * BUF_BYTES;
        const uint32_t bBase = aBase + CHUNK_BYTES;
        const int i8 = lane & 7;
        const int g  = lane >> 3;

        #pragma unroll
        for (int ks = 0; ks < 4; ++ks) {
            const int kb = ks * 32;   // byte offset within 128B row
            uint32_t afr[2][4];
            #pragma unroll
            for (int mi = 0; mi < 2; ++mi) {
                int row = wm + mi * 16 + i8 + (g & 1) * 8;
                int col = kb + (g >> 1) * 16;
                ldsm_x4(afr[mi], aBase + sw128((uint32_t)(row * 128 + col)));
            }
            uint32_t bfr[4][4];
            #pragma unroll
            for (int p = 0; p < 4; ++p) {
                int row = wn + p * 16 + i8 + (g >> 1) * 8;
                int col = kb + (g & 1) * 16;
                ldsm_x4(bfr[p], bBase + sw128((uint32_t)(row * 128 + col)));
            }
            #pragma unroll
            for (int mi = 0; mi < 2; ++mi)
                #pragma unroll
                for (int nj = 0; nj < 8; ++nj)
                    mma16816(acc[mi][nj], afr[mi],
                             bfr[nj >> 1][(nj & 1) * 2],
                             bfr[nj >> 1][(nj & 1) * 2 + 1]);
        }
        __syncthreads();
    }

    // ---- fused epilogue: scale columns, write once ----
    float* sSc = (float*)smem;
    if (tid < 128) sSc[tid] = g_S[b][n0 + tid];
    __syncthreads();

    const int r    = lane >> 2;
    const int cpos = (lane & 3) * 2;
    #pragma unroll
    for (int mi = 0; mi < 2; ++mi) {
        const int mrow = m0 + wm + mi * 16 + r;
        float* o0 = out + ((size_t)b * HW + mrow) * HW + n0 + wn;
        float* o1 = o0 + (size_t)8 * HW;
        #pragma unroll
        for (int nj = 0; nj < 8; ++nj) {
            const int nc = wn + nj * 8 + cpos;
            const float s0 = sSc[nc], s1 = sSc[nc + 1];
            float2 v0 = make_float2(acc[mi][nj][0] * s0, acc[mi][nj][1] * s1);
            float2 v1 = make_float2(acc[mi][nj][2] * s0, acc[mi][nj][3] * s1);
            *(float2*)&o0[nj * 8 + cpos] = v0;
            *(float2*)&o1[nj * 8 + cpos] = v1;
        }
    }
}

// ---------------------------------------------------------------------------
extern "C" void kernel_launch(void* const* d_in, const int* in_sizes, int n_in,
                              void* d_out, int out_size)
{
    const float* A = (const float*)d_in[0];
    const float* B = (const float*)d_in[1];
    float* out = (float*)d_out;

    static __nv_bfloat16* abf_ptr = nullptr;
    static __nv_bfloat16* bbf_ptr = nullptr;
    if (!abf_ptr) {   // address lookup only (no allocation, deterministic)
        cudaGetSymbolAddress((void**)&abf_ptr, g_Abf);
        cudaGetSymbolAddress((void**)&bbf_ptr, g_Bbf);
    }

    cudaFuncSetAttribute(corr_mma_kernel,
                         cudaFuncAttributeMaxDynamicSharedMemorySize, SMEM_TOTAL);

    convert_kernel<<<1024, 256>>>(A, abf_ptr);
    convert_kernel<<<1024, 256>>>(B, bbf_ptr);
    gram_partial_kernel<<<dim3(16, SPLIT, BATCH), 256>>>(A);
    gram_reduce_kernel<<<1024, 256>>>();
    scale_kernel<<<dim3(HW / 32, BATCH), 256>>>(B);
    corr_mma_kernel<<<dim3(HW / 128, HW / 128, BATCH), 256, SMEM_TOTAL>>>(out);
}

// round 5
// speedup vs baseline: 2.4856x; 1.4212x over previous
#include <cuda_runtime.h>
#include <cuda_bf16.h>
#include <cstdint>

#define BATCH 8
#define HW    2304        // 48*48
#define CH    256
#define K2    512         // scratch layout: [hi(256) | lo(256)]
#define GSLICES 4
#define GK     (HW / GSLICES)   // 576 m-rows per gram split-K slice

// ---------------- scratch (device globals: allocation-free rule) -----------
__device__ float g_Gpart[GSLICES][BATCH][CH][CH];          // 8 MB
__device__ float g_G[BATCH][CH][CH];                       // 2 MB
__device__ float g_S[BATCH][HW];                           // 72 KB
__device__ float g_Qpart[BATCH][2][HW];                    // 147 KB
__device__ __nv_bfloat16 g_Abf[(size_t)BATCH * HW * K2];   // 18.9 MB
__device__ __nv_bfloat16 g_Bbf[(size_t)BATCH * HW * K2];   // 18.9 MB
__device__ __nv_bfloat16 g_AbfT[(size_t)BATCH * K2 * HW];  // 18.9 MB  [c(hi|lo)][m]
__device__ __nv_bfloat16 g_Gbf[(size_t)BATCH * K2 * CH];   // 2 MB     [c(hi|lo)][c2]

__device__ __forceinline__ uint32_t smem_u32(const void* p) {
    return (uint32_t)__cvta_generic_to_shared((void*)p);
}
__device__ __forceinline__ uint32_t sw128(uint32_t off) {
    return off ^ ((off >> 3) & 0x70);
}

// ---------------- mma.sync / ldmatrix / cp.async helpers -------------------
__device__ __forceinline__ void ldsm_x4(uint32_t* r, uint32_t addr) {
    asm volatile("ldmatrix.sync.aligned.m8n8.x4.shared.b16 {%0,%1,%2,%3}, [%4];"
                 : "=r"(r[0]), "=r"(r[1]), "=r"(r[2]), "=r"(r[3]) : "r"(addr));
}
__device__ __forceinline__ void mma16816(float* c, const uint32_t* a,
                                         uint32_t b0, uint32_t b1) {
    asm volatile("mma.sync.aligned.m16n8k16.row.col.f32.bf16.bf16.f32 "
                 "{%0,%1,%2,%3}, {%4,%5,%6,%7}, {%8,%9}, {%0,%1,%2,%3};"
                 : "+f"(c[0]), "+f"(c[1]), "+f"(c[2]), "+f"(c[3])
                 : "r"(a[0]), "r"(a[1]), "r"(a[2]), "r"(a[3]), "r"(b0), "r"(b1));
}
__device__ __forceinline__ void cp_async16(uint32_t dst, const void* src) {
    asm volatile("cp.async.cg.shared.global [%0], [%1], 16;" :: "r"(dst), "l"(src));
}
__device__ __forceinline__ void cp_commit() {
    asm volatile("cp.async.commit_group;" ::: "memory");
}
template <int N> __device__ __forceinline__ void cp_wait() {
    asm volatile("cp.async.wait_group %0;" :: "n"(N) : "memory");
}

#define CHUNK_BYTES 16384                 // 128 rows x 128 B
#define BUF_BYTES   (2 * CHUNK_BYTES)
#define SMEM_TOTAL  (2 * BUF_BYTES)       // 65536

// ---------------------------------------------------------------------------
// convert: fp32 [B*HW, CH] -> bf16 split [B*HW, K2]
// ---------------------------------------------------------------------------
__global__ __launch_bounds__(256) void convert_kernel(const float* __restrict__ X,
                                                      __nv_bfloat16* __restrict__ Y)
{
    const size_t total4 = (size_t)BATCH * HW * CH / 4;
    for (size_t i = (size_t)blockIdx.x * blockDim.x + threadIdx.x; i < total4;
         i += (size_t)gridDim.x * blockDim.x) {
        float4 v = ((const float4*)X)[i];
        size_t row = i >> 6;
        int c = (int)(i & 63) * 4;
        float vv[4] = {v.x, v.y, v.z, v.w};
        __nv_bfloat16 hi[4], lo[4];
        #pragma unroll
        for (int j = 0; j < 4; ++j) {
            hi[j] = __float2bfloat16(vv[j]);
            lo[j] = __float2bfloat16(vv[j] - __bfloat162float(hi[j]));
        }
        __nv_bfloat162* ph = (__nv_bfloat162*)&Y[row * K2 + c];
        __nv_bfloat162* pl = (__nv_bfloat162*)&Y[row * K2 + CH + c];
        ph[0] = __nv_bfloat162{hi[0], hi[1]};
        ph[1] = __nv_bfloat162{hi[2], hi[3]};
        pl[0] = __nv_bfloat162{lo[0], lo[1]};
        pl[1] = __nv_bfloat162{lo[2], lo[3]};
    }
}

// ---------------------------------------------------------------------------
// transpose-convert: A fp32 [m, c] -> At bf16 [c(hi) | c+256(lo)][m]
// ---------------------------------------------------------------------------
__global__ __launch_bounds__(256) void transpose_split_kernel(const float* __restrict__ X)
{
    __shared__ float T[32][33];
    const int b  = blockIdx.z;
    const int m0 = blockIdx.x * 32;
    const int c0 = blockIdx.y * 32;
    const int tx = threadIdx.x & 31;
    const int ty = threadIdx.x >> 5;      // 0..7

    #pragma unroll
    for (int k = 0; k < 4; ++k) {
        int row = ty + k * 8;
        T[row][tx] = X[((size_t)b * HW + m0 + row) * CH + c0 + tx];
    }
    __syncthreads();

    __nv_bfloat16* At = g_AbfT + (size_t)b * K2 * HW;
    #pragma unroll
    for (int k = 0; k < 4; ++k) {
        int c = ty + k * 8;
        float v = T[tx][c];
        __nv_bfloat16 hi = __float2bfloat16(v);
        __nv_bfloat16 lo = __float2bfloat16(v - __bfloat162float(hi));
        At[(size_t)(c0 + c) * HW + m0 + tx]        = hi;
        At[(size_t)(c0 + c + CH) * HW + m0 + tx]   = lo;
    }
}

// ---------------------------------------------------------------------------
// gram_mma: G_part[slice][b] = 3-term (hi*hi + lo*hi + hi*lo) over m in slice.
// Output tile 128x128 of G[c1,c2]; operands = rows of At, K = m.
// ---------------------------------------------------------------------------
__global__ __launch_bounds__(256, 2) void gram_mma_kernel()
{
    extern __shared__ char smem[];
    const uint32_t smem_base = smem_u32(smem);
    const int tid  = threadIdx.x;
    const int wid  = tid >> 5;
    const int lane = tid & 31;

    const int b     = blockIdx.z >> 2;
    const int slice = blockIdx.z & 3;
    const int c1_0  = blockIdx.y * 128;
    const int c2_0  = blockIdx.x * 128;

    const __nv_bfloat16* At = g_AbfT + (size_t)b * K2 * HW;

    // per-thread cp.async slots
    uint32_t dstoff[8];
    const __nv_bfloat16* srcp[8];
    bool isA[8];
    #pragma unroll
    for (int it = 0; it < 8; ++it) {
        int idx = it * 256 + tid;
        int li  = idx & 1023;
        int row = li >> 3;
        int seg = li & 7;
        isA[it] = (idx < 1024);
        dstoff[it] = (isA[it] ? 0u : (uint32_t)CHUNK_BYTES)
                   + sw128((uint32_t)(row * 128 + seg * 16));
        srcp[it] = At + (size_t)((isA[it] ? c1_0 : c2_0) + row) * HW + seg * 8;
    }

    // 27 chunk iters: term = it/9 (0:hi*hi 1:lo*hi 2:hi*lo), kc = it%9
    auto load_chunk = [&](int it, int buf) {
        const int term = it / 9, kc = it - term * 9;
        const size_t aoff = (size_t)(term == 1 ? CH : 0) * HW + slice * GK + kc * 64;
        const size_t boff = (size_t)(term == 2 ? CH : 0) * HW + slice * GK + kc * 64;
        const uint32_t base = smem_base + buf * BUF_BYTES;
        #pragma unroll
        for (int s = 0; s < 8; ++s)
            cp_async16(base + dstoff[s], srcp[s] + (isA[s] ? aoff : boff));
        cp_commit();
    };

    const int wm = (wid & 3) * 32;
    const int wn = (wid >> 2) * 64;
    float acc[2][8][4] = {};

    load_chunk(0, 0);
    for (int c = 0; c < 27; ++c) {
        if (c + 1 < 27) load_chunk(c + 1, (c + 1) & 1);
        if (c + 1 < 27) cp_wait<1>(); else cp_wait<0>();
        __syncthreads();

        const uint32_t aBase = smem_base + (c & 1) * BUF_BYTES;
        const uint32_t bBase = aBase + CHUNK_BYTES;
        const int i8 = lane & 7;
        const int g  = lane >> 3;
        #pragma unroll
        for (int ks = 0; ks < 4; ++ks) {
            const int kb = ks * 32;
            uint32_t afr[2][4];
            #pragma unroll
            for (int mi = 0; mi < 2; ++mi) {
                int row = wm + mi * 16 + i8 + (g & 1) * 8;
                int col = kb + (g >> 1) * 16;
                ldsm_x4(afr[mi], aBase + sw128((uint32_t)(row * 128 + col)));
            }
            uint32_t bfr[4][4];
            #pragma unroll
            for (int p = 0; p < 4; ++p) {
                int row = wn + p * 16 + i8 + (g >> 1) * 8;
                int col = kb + (g & 1) * 16;
                ldsm_x4(bfr[p], bBase + sw128((uint32_t)(row * 128 + col)));
            }
            #pragma unroll
            for (int mi = 0; mi < 2; ++mi)
                #pragma unroll
                for (int nj = 0; nj < 8; ++nj)
                    mma16816(acc[mi][nj], afr[mi],
                             bfr[nj >> 1][(nj & 1) * 2],
                             bfr[nj >> 1][(nj & 1) * 2 + 1]);
        }
        __syncthreads();
    }

    const int r    = lane >> 2;
    const int cpos = (lane & 3) * 2;
    #pragma unroll
    for (int mi = 0; mi < 2; ++mi) {
        const int row = c1_0 + wm + mi * 16 + r;
        float* o0 = &g_Gpart[slice][b][row][c2_0 + wn];
        float* o1 = o0 + 8 * CH;
        #pragma unroll
        for (int nj = 0; nj < 8; ++nj) {
            *(float2*)&o0[nj * 8 + cpos] = make_float2(acc[mi][nj][0], acc[mi][nj][1]);
            *(float2*)&o1[nj * 8 + cpos] = make_float2(acc[mi][nj][2], acc[mi][nj][3]);
        }
    }
}

// ---------------------------------------------------------------------------
// gram_reduce: G = sum of 4 partial slices (deterministic)
// ---------------------------------------------------------------------------
__global__ __launch_bounds__(256) void gram_reduce_kernel()
{
    const int total = BATCH * CH * CH;
    const float* p = &g_Gpart[0][0][0][0];
    float* g = &g_G[0][0][0];
    for (int i = blockIdx.x * blockDim.x + threadIdx.x; i < total;
         i += gridDim.x * blockDim.x) {
        float s = 0.f;
        #pragma unroll
        for (int k = 0; k < GSLICES; ++k) s += p[k * total + i];
        g[i] = s;
    }
}

// ---------------------------------------------------------------------------
// g2bf: split G fp32 -> bf16 hi/lo  ([c][c2] hi rows 0-255, lo rows 256-511)
// ---------------------------------------------------------------------------
__global__ __launch_bounds__(256) void g2bf_kernel()
{
    const int total = BATCH * CH * CH;
    for (int i = blockIdx.x * blockDim.x + threadIdx.x; i < total;
         i += gridDim.x * blockDim.x) {
        int b  = i / (CH * CH);
        int li = i - b * CH * CH;
        int c  = li >> 8;
        int c2 = li & 255;
        float v = g_G[b][c][c2];
        __nv_bfloat16 hi = __float2bfloat16(v);
        __nv_bfloat16 lo = __float2bfloat16(v - __bfloat162float(hi));
        g_Gbf[((size_t)b * K2 + c) * CH + c2]      = hi;
        g_Gbf[((size_t)b * K2 + CH + c) * CH + c2] = lo;
    }
}

// ---------------------------------------------------------------------------
// qrow_mma: V = U G (3-term HMMA), fused epilogue q_part = rowsum(V .* U_fp32).
// grid (ctile 2, ntile 18, b). A-op = g_Bbf rows (U), B-op = g_Gbf rows.
// ---------------------------------------------------------------------------
__global__ __launch_bounds__(256, 2) void qrow_mma_kernel(const float* __restrict__ Bin)
{
    extern __shared__ char smem[];
    const uint32_t smem_base = smem_u32(smem);
    const int tid  = threadIdx.x;
    const int wid  = tid >> 5;
    const int lane = tid & 31;

    const int ctile = blockIdx.x;
    const int n0    = blockIdx.y * 128;
    const int b     = blockIdx.z;

    const __nv_bfloat16* Ub = g_Bbf + ((size_t)b * HW + n0) * K2;
    const __nv_bfloat16* Gb = g_Gbf + (size_t)b * K2 * CH + (size_t)ctile * 128 * CH;

    uint32_t dstoff[8];
    const __nv_bfloat16* srcp[8];
    bool isA[8];
    #pragma unroll
    for (int it = 0; it < 8; ++it) {
        int idx = it * 256 + tid;
        int li  = idx & 1023;
        int row = li >> 3;
        int seg = li & 7;
        isA[it] = (idx < 1024);
        dstoff[it] = (isA[it] ? 0u : (uint32_t)CHUNK_BYTES)
                   + sw128((uint32_t)(row * 128 + seg * 16));
        srcp[it] = (isA[it] ? Ub + (size_t)row * K2 : Gb + (size_t)row * CH) + seg * 8;
    }

    // 12 iters: term = it>>2 (0:UhiGhi 1:UloGhi 2:UhiGlo), kc = it&3
    auto load_chunk = [&](int it, int buf) {
        const int term = it >> 2, kc = it & 3;
        const size_t uoff = (size_t)(term == 1 ? CH : 0) + kc * 64;
        const size_t goff = (size_t)(term == 2 ? CH : 0) * CH + kc * 64;
        const uint32_t base = smem_base + buf * BUF_BYTES;
        #pragma unroll
        for (int s = 0; s < 8; ++s)
            cp_async16(base + dstoff[s], srcp[s] + (isA[s] ? uoff : goff));
        cp_commit();
    };

    const int wm = (wid & 3) * 32;
    const int wn = (wid >> 2) * 64;
    float acc[2][8][4] = {};

    load_chunk(0, 0);
    for (int c = 0; c < 12; ++c) {
        if (c + 1 < 12) load_chunk(c + 1, (c + 1) & 1);
        if (c + 1 < 12) cp_wait<1>(); else cp_wait<0>();
        __syncthreads();

        const uint32_t aBase = smem_base + (c & 1) * BUF_BYTES;
        const uint32_t bBase = aBase + CHUNK_BYTES;
        const int i8 = lane & 7;
        const int g  = lane >> 3;
        #pragma unroll
        for (int ks = 0; ks < 4; ++ks) {
            const int kb = ks * 32;
            uint32_t afr[2][4];
            #pragma unroll
            for (int mi = 0; mi < 2; ++mi) {
                int row = wm + mi * 16 + i8 + (g & 1) * 8;
                int col = kb + (g >> 1) * 16;
                ldsm_x4(afr[mi], aBase + sw128((uint32_t)(row * 128 + col)));
            }
            uint32_t bfr[4][4];
            #pragma unroll
            for (int p = 0; p < 4; ++p) {
                int row = wn + p * 16 + i8 + (g >> 1) * 8;
                int col = kb + (g & 1) * 16;
                ldsm_x4(bfr[p], bBase + sw128((uint32_t)(row * 128 + col)));
            }
            #pragma unroll
            for (int mi = 0; mi < 2; ++mi)
                #pragma unroll
                for (int nj = 0; nj < 8; ++nj)
                    mma16816(acc[mi][nj], afr[mi],
                             bfr[nj >> 1][(nj & 1) * 2],
                             bfr[nj >> 1][(nj & 1) * 2 + 1]);
        }
        __syncthreads();
    }

    // epilogue: q partial = sum_c V[n,c] * U[n,c]  (fixed-order, deterministic)
    float* qs = (float*)smem;    // qs[2][128] overlay; safe after last sync
    const int r    = lane >> 2;
    const int cpos = (lane & 3) * 2;

    float rs[2][2] = {};
    #pragma unroll
    for (int mi = 0; mi < 2; ++mi) {
        const size_t row0 = (size_t)b * HW + n0 + wm + mi * 16 + r;
        #pragma unroll
        for (int nj = 0; nj < 8; ++nj) {
            const int cc = ctile * 128 + wn + nj * 8 + cpos;
            float2 u0 = *(const float2*)&Bin[row0 * CH + cc];
            float2 u1 = *(const float2*)&Bin[(row0 + 8) * CH + cc];
            rs[mi][0] += acc[mi][nj][0] * u0.x + acc[mi][nj][1] * u0.y;
            rs[mi][1] += acc[mi][nj][2] * u1.x + acc[mi][nj][3] * u1.y;
        }
    }
    #pragma unroll
    for (int mi = 0; mi < 2; ++mi)
        #pragma unroll
        for (int h = 0; h < 2; ++h) {
            float v = rs[mi][h];
            v += __shfl_xor_sync(0xffffffffu, v, 1);
            v += __shfl_xor_sync(0xffffffffu, v, 2);
            rs[mi][h] = v;
        }
    if ((lane & 3) == 0) {
        #pragma unroll
        for (int mi = 0; mi < 2; ++mi)
            #pragma unroll
            for (int h = 0; h < 2; ++h)
                qs[(wid >> 2) * 128 + wm + mi * 16 + r + h * 8] = rs[mi][h];
    }
    __syncthreads();
    if (tid < 128)
        g_Qpart[b][ctile][n0 + tid] = qs[tid] + qs[128 + tid];
}

// ---------------------------------------------------------------------------
// qcombine: s = rsqrt(qp0 + qp1)
// ---------------------------------------------------------------------------
__global__ __launch_bounds__(256) void qcombine_kernel()
{
    int i = blockIdx.x * blockDim.x + threadIdx.x;
    if (i < BATCH * HW) {
        int b = i / HW, n = i - b * HW;
        g_S[b][n] = rsqrtf(g_Qpart[b][0][n] + g_Qpart[b][1][n]);
    }
}

// ---------------------------------------------------------------------------
// corr_mma: main GEMM (unchanged from round 4)
// ---------------------------------------------------------------------------
#define NCHUNK 12
__global__ __launch_bounds__(256, 2) void corr_mma_kernel(float* __restrict__ out)
{
    extern __shared__ char smem[];
    const uint32_t smem_base = smem_u32(smem);
    const int tid  = threadIdx.x;
    const int wid  = tid >> 5;
    const int lane = tid & 31;

    const int b  = blockIdx.z;
    const int m0 = blockIdx.y * 128;
    const int n0 = blockIdx.x * 128;

    const __nv_bfloat16* Ab = g_Abf + ((size_t)b * HW + m0) * K2;
    const __nv_bfloat16* Bb = g_Bbf + ((size_t)b * HW + n0) * K2;

    const int a_k0[NCHUNK] = {0,64,128,192, 256,320,384,448, 0,64,128,192};
    const int b_k0[NCHUNK] = {0,64,128,192, 0,64,128,192, 256,320,384,448};

    uint32_t dstoff[8];
    const __nv_bfloat16* srcp[8];
    bool isA[8];
    #pragma unroll
    for (int it = 0; it < 8; ++it) {
        int idx = it * 256 + tid;
        int li  = idx & 1023;
        int row = li >> 3;
        int seg = li & 7;
        isA[it] = (idx < 1024);
        dstoff[it] = (isA[it] ? 0u : (uint32_t)CHUNK_BYTES)
                   + sw128((uint32_t)(row * 128 + seg * 16));
        srcp[it] = (isA[it] ? Ab : Bb) + (size_t)row * K2 + seg * 8;
    }

    auto load_chunk = [&](int c, int buf) {
        const uint32_t base = smem_base + buf * BUF_BYTES;
        const int ao = a_k0[c], bo = b_k0[c];
        #pragma unroll
        for (int it = 0; it < 8; ++it)
            cp_async16(base + dstoff[it], srcp[it] + (isA[it] ? ao : bo));
        cp_commit();
    };

    const int wm = (wid & 3) * 32;
    const int wn = (wid >> 2) * 64;
    float acc[2][8][4] = {};

    load_chunk(0, 0);
    for (int c = 0; c < NCHUNK; ++c) {
        if (c + 1 < NCHUNK) load_chunk(c + 1, (c + 1) & 1);
        if (c + 1 < NCHUNK) cp_wait<1>(); else cp_wait<0>();
        __syncthreads();

        const uint32_t aBase = smem_base + (c & 1) * BUF_BYTES;
        const uint32_t bBase = aBase + CHUNK_BYTES;
        const int i8 = lane & 7;
        const int g  = lane >> 3;
        #pragma unroll
        for (int ks = 0; ks < 4; ++ks) {
            const int kb = ks * 32;
            uint32_t afr[2][4];
            #pragma unroll
            for (int mi = 0; mi < 2; ++mi) {
                int row = wm + mi * 16 + i8 + (g & 1) * 8;
                int col = kb + (g >> 1) * 16;
                ldsm_x4(afr[mi], aBase + sw128((uint32_t)(row * 128 + col)));
            }
            uint32_t bfr[4][4];
            #pragma unroll
            for (int p = 0; p < 4; ++p) {
                int row = wn + p * 16 + i8 + (g >> 1) * 8;
                int col = kb + (g & 1) * 16;
                ldsm_x4(bfr[p], bBase + sw128((uint32_t)(row * 128 + col)));
            }
            #pragma unroll
            for (int mi = 0; mi < 2; ++mi)
                #pragma unroll
                for (int nj = 0; nj < 8; ++nj)
                    mma16816(acc[mi][nj], afr[mi],
                             bfr[nj >> 1][(nj & 1) * 2],
                             bfr[nj >> 1][(nj & 1) * 2 + 1]);
        }
        __syncthreads();
    }

    float* sSc = (float*)smem;
    if (tid < 128) sSc[tid] = g_S[b][n0 + tid];
    __syncthreads();

    const int r    = lane >> 2;
    const int cpos = (lane & 3) * 2;
    #pragma unroll
    for (int mi = 0; mi < 2; ++mi) {
        const int mrow = m0 + wm + mi * 16 + r;
        float* o0 = out + ((size_t)b * HW + mrow) * HW + n0 + wn;
        float* o1 = o0 + (size_t)8 * HW;
        #pragma unroll
        for (int nj = 0; nj < 8; ++nj) {
            const int nc = wn + nj * 8 + cpos;
            const float s0 = sSc[nc], s1 = sSc[nc + 1];
            float2 v0 = make_float2(acc[mi][nj][0] * s0, acc[mi][nj][1] * s1);
            float2 v1 = make_float2(acc[mi][nj][2] * s0, acc[mi][nj][3] * s1);
            *(float2*)&o0[nj * 8 + cpos] = v0;
            *(float2*)&o1[nj * 8 + cpos] = v1;
        }
    }
}

// ---------------------------------------------------------------------------
extern "C" void kernel_launch(void* const* d_in, const int* in_sizes, int n_in,
                              void* d_out, int out_size)
{
    const float* A = (const float*)d_in[0];
    const float* B = (const float*)d_in[1];
    float* out = (float*)d_out;

    static __nv_bfloat16* abf_ptr = nullptr;
    static __nv_bfloat16* bbf_ptr = nullptr;
    if (!abf_ptr) {
        cudaGetSymbolAddress((void**)&abf_ptr, g_Abf);
        cudaGetSymbolAddress((void**)&bbf_ptr, g_Bbf);
        cudaFuncSetAttribute(corr_mma_kernel,
                             cudaFuncAttributeMaxDynamicSharedMemorySize, SMEM_TOTAL);
        cudaFuncSetAttribute(gram_mma_kernel,
                             cudaFuncAttributeMaxDynamicSharedMemorySize, SMEM_TOTAL);
        cudaFuncSetAttribute(qrow_mma_kernel,
                             cudaFuncAttributeMaxDynamicSharedMemorySize, SMEM_TOTAL);
    }

    convert_kernel<<<1024, 256>>>(A, abf_ptr);
    convert_kernel<<<1024, 256>>>(B, bbf_ptr);
    transpose_split_kernel<<<dim3(HW / 32, CH / 32, BATCH), 256>>>(A);
    gram_mma_kernel<<<dim3(2, 2, BATCH * GSLICES), 256, SMEM_TOTAL>>>();
    gram_reduce_kernel<<<1024, 256>>>();
    g2bf_kernel<<<512, 256>>>();
    qrow_mma_kernel<<<dim3(2, HW / 128, BATCH), 256, SMEM_TOTAL>>>(B);
    qcombine_kernel<<<(BATCH * HW + 255) / 256, 256>>>();
    corr_mma_kernel<<<dim3(HW / 128, HW / 128, BATCH), 256, SMEM_TOTAL>>>(out);
}

// round 6
// speedup vs baseline: 2.5191x; 1.0135x over previous
#include <cuda_runtime.h>
#include <cuda_bf16.h>
#include <cstdint>

#define BATCH 8
#define HW    2304        // 48*48
#define CH    256
#define K2    512         // scratch layout: [hi(256) | lo(256)]
#define GSLICES 12
#define GK     (HW / GSLICES)   // 192 m-rows per gram split-K slice

// ---------------- scratch (device globals: allocation-free rule) -----------
__device__ float g_Gpart[GSLICES][BATCH][CH][CH];          // 24 MB
__device__ float g_G[BATCH][CH][CH];                       // 2 MB
__device__ float g_S[BATCH][HW];                           // 72 KB
__device__ float g_Qpart[BATCH][2][HW];                    // 147 KB
__device__ __nv_bfloat16 g_Abf[(size_t)BATCH * HW * K2];   // 18.9 MB
__device__ __nv_bfloat16 g_Bbf[(size_t)BATCH * HW * K2];   // 18.9 MB
__device__ __nv_bfloat16 g_AbfT[(size_t)BATCH * K2 * HW];  // 18.9 MB  [c(hi|lo)][m]
__device__ __nv_bfloat16 g_Gbf[(size_t)BATCH * K2 * CH];   // 2 MB     [c(hi|lo)][c2]

__device__ __forceinline__ uint32_t smem_u32(const void* p) {
    return (uint32_t)__cvta_generic_to_shared((void*)p);
}
__device__ __forceinline__ uint32_t sw128(uint32_t off) {
    return off ^ ((off >> 3) & 0x70);
}

// ---------------- mma.sync / ldmatrix / cp.async helpers -------------------
__device__ __forceinline__ void ldsm_x4(uint32_t* r, uint32_t addr) {
    asm volatile("ldmatrix.sync.aligned.m8n8.x4.shared.b16 {%0,%1,%2,%3}, [%4];"
                 : "=r"(r[0]), "=r"(r[1]), "=r"(r[2]), "=r"(r[3]) : "r"(addr));
}
__device__ __forceinline__ void mma16816(float* c, const uint32_t* a,
                                         uint32_t b0, uint32_t b1) {
    asm volatile("mma.sync.aligned.m16n8k16.row.col.f32.bf16.bf16.f32 "
                 "{%0,%1,%2,%3}, {%4,%5,%6,%7}, {%8,%9}, {%0,%1,%2,%3};"
                 : "+f"(c[0]), "+f"(c[1]), "+f"(c[2]), "+f"(c[3])
                 : "r"(a[0]), "r"(a[1]), "r"(a[2]), "r"(a[3]), "r"(b0), "r"(b1));
}
__device__ __forceinline__ void cp_async16(uint32_t dst, const void* src) {
    asm volatile("cp.async.cg.shared.global [%0], [%1], 16;" :: "r"(dst), "l"(src));
}
__device__ __forceinline__ void cp_commit() {
    asm volatile("cp.async.commit_group;" ::: "memory");
}
template <int N> __device__ __forceinline__ void cp_wait() {
    asm volatile("cp.async.wait_group %0;" :: "n"(N) : "memory");
}

#define CHUNK_BYTES 16384                 // 128 rows x 128 B
#define BUF_BYTES   (2 * CHUNK_BYTES)     // A + B tile per stage
#define NSTAGE      3
#define SMEM_TOTAL  (NSTAGE * BUF_BYTES)  // 98304

// Shared compute step: one 64-K chunk of the 128x128 tile (8 warps, 4x2)
__device__ __forceinline__ void mma_chunk(uint32_t aBase, uint32_t bBase,
                                          int wm, int wn, int lane,
                                          float acc[2][8][4])
{
    const int i8 = lane & 7;
    const int g  = lane >> 3;
    #pragma unroll
    for (int ks = 0; ks < 4; ++ks) {
        const int kb = ks * 32;
        uint32_t afr[2][4];
        #pragma unroll
        for (int mi = 0; mi < 2; ++mi) {
            int row = wm + mi * 16 + i8 + (g & 1) * 8;
            int col = kb + (g >> 1) * 16;
            ldsm_x4(afr[mi], aBase + sw128((uint32_t)(row * 128 + col)));
        }
        uint32_t bfr[4][4];
        #pragma unroll
        for (int p = 0; p < 4; ++p) {
            int row = wn + p * 16 + i8 + (g >> 1) * 8;
            int col = kb + (g & 1) * 16;
            ldsm_x4(bfr[p], bBase + sw128((uint32_t)(row * 128 + col)));
        }
        #pragma unroll
        for (int mi = 0; mi < 2; ++mi)
            #pragma unroll
            for (int nj = 0; nj < 8; ++nj)
                mma16816(acc[mi][nj], afr[mi],
                         bfr[nj >> 1][(nj & 1) * 2],
                         bfr[nj >> 1][(nj & 1) * 2 + 1]);
    }
}

// ---------------------------------------------------------------------------
// convert (B only): fp32 [B*HW, CH] -> bf16 split [B*HW, K2]
// ---------------------------------------------------------------------------
__global__ __launch_bounds__(256) void convert_kernel(const float* __restrict__ X,
                                                      __nv_bfloat16* __restrict__ Y)
{
    const size_t total4 = (size_t)BATCH * HW * CH / 4;
    for (size_t i = (size_t)blockIdx.x * blockDim.x + threadIdx.x; i < total4;
         i += (size_t)gridDim.x * blockDim.x) {
        float4 v = ((const float4*)X)[i];
        size_t row = i >> 6;
        int c = (int)(i & 63) * 4;
        float vv[4] = {v.x, v.y, v.z, v.w};
        __nv_bfloat16 hi[4], lo[4];
        #pragma unroll
        for (int j = 0; j < 4; ++j) {
            hi[j] = __float2bfloat16(vv[j]);
            lo[j] = __float2bfloat16(vv[j] - __bfloat162float(hi[j]));
        }
        __nv_bfloat162* ph = (__nv_bfloat162*)&Y[row * K2 + c];
        __nv_bfloat162* pl = (__nv_bfloat162*)&Y[row * K2 + CH + c];
        ph[0] = __nv_bfloat162{hi[0], hi[1]};
        ph[1] = __nv_bfloat162{hi[2], hi[3]};
        pl[0] = __nv_bfloat162{lo[0], lo[1]};
        pl[1] = __nv_bfloat162{lo[2], lo[3]};
    }
}

// ---------------------------------------------------------------------------
// fused A pass: read A once -> g_Abf (row-major split) + g_AbfT (transposed)
// ---------------------------------------------------------------------------
__global__ __launch_bounds__(256) void convertA_kernel(const float* __restrict__ X)
{
    __shared__ float T[32][33];
    const int b  = blockIdx.z;
    const int m0 = blockIdx.x * 32;
    const int c0 = blockIdx.y * 32;
    const int tx = threadIdx.x & 31;
    const int ty = threadIdx.x >> 5;      // 0..7

    __nv_bfloat16* Ar = g_Abf + (size_t)b * HW * K2;
    #pragma unroll
    for (int k = 0; k < 4; ++k) {
        int row = ty + k * 8;
        float v = X[((size_t)b * HW + m0 + row) * CH + c0 + tx];
        T[row][tx] = v;
        __nv_bfloat16 hi = __float2bfloat16(v);
        __nv_bfloat16 lo = __float2bfloat16(v - __bfloat162float(hi));
        Ar[(size_t)(m0 + row) * K2 + c0 + tx]      = hi;
        Ar[(size_t)(m0 + row) * K2 + CH + c0 + tx] = lo;
    }
    __syncthreads();

    __nv_bfloat16* At = g_AbfT + (size_t)b * K2 * HW;
    #pragma unroll
    for (int k = 0; k < 4; ++k) {
        int c = ty + k * 8;
        float v = T[tx][c];
        __nv_bfloat16 hi = __float2bfloat16(v);
        __nv_bfloat16 lo = __float2bfloat16(v - __bfloat162float(hi));
        At[(size_t)(c0 + c) * HW + m0 + tx]      = hi;
        At[(size_t)(c0 + c + CH) * HW + m0 + tx] = lo;
    }
}

// ---------------------------------------------------------------------------
// gram_mma: G_part[slice][b], 3-term over m in slice (GK=192 -> 9 chunk iters)
// ---------------------------------------------------------------------------
__global__ __launch_bounds__(256, 2) void gram_mma_kernel()
{
    extern __shared__ char smem[];
    const uint32_t smem_base = smem_u32(smem);
    const int tid  = threadIdx.x;
    const int wid  = tid >> 5;
    const int lane = tid & 31;

    const int b     = blockIdx.z / GSLICES;
    const int slice = blockIdx.z % GSLICES;
    const int c1_0  = blockIdx.y * 128;
    const int c2_0  = blockIdx.x * 128;

    const __nv_bfloat16* At = g_AbfT + (size_t)b * K2 * HW;

    uint32_t dstoff[8];
    const __nv_bfloat16* srcp[8];
    bool isA[8];
    #pragma unroll
    for (int it = 0; it < 8; ++it) {
        int idx = it * 256 + tid;
        int li  = idx & 1023;
        int row = li >> 3;
        int seg = li & 7;
        isA[it] = (idx < 1024);
        dstoff[it] = (isA[it] ? 0u : (uint32_t)CHUNK_BYTES)
                   + sw128((uint32_t)(row * 128 + seg * 16));
        srcp[it] = At + (size_t)((isA[it] ? c1_0 : c2_0) + row) * HW + seg * 8;
    }

    const int NIT = 9;   // 3 terms x 3 chunks of 64 within GK=192
    auto load_chunk = [&](int it, int buf) {
        const int term = it / 3, kc = it - term * 3;
        const size_t aoff = (size_t)(term == 1 ? CH : 0) * HW + slice * GK + kc * 64;
        const size_t boff = (size_t)(term == 2 ? CH : 0) * HW + slice * GK + kc * 64;
        const uint32_t base = smem_base + buf * BUF_BYTES;
        #pragma unroll
        for (int s = 0; s < 8; ++s)
            cp_async16(base + dstoff[s], srcp[s] + (isA[s] ? aoff : boff));
        cp_commit();
    };

    const int wm = (wid & 3) * 32;
    const int wn = (wid >> 2) * 64;
    float acc[2][8][4] = {};

    load_chunk(0, 0);
    load_chunk(1, 1);
    for (int c = 0; c < NIT; ++c) {
        if (c < NIT - 1) cp_wait<1>(); else cp_wait<0>();
        __syncthreads();
        const uint32_t aBase = smem_base + (c % NSTAGE) * BUF_BYTES;
        mma_chunk(aBase, aBase + CHUNK_BYTES, wm, wn, lane, acc);
        if (c + 2 < NIT) load_chunk(c + 2, (c + 2) % NSTAGE);
    }

    const int r    = lane >> 2;
    const int cpos = (lane & 3) * 2;
    #pragma unroll
    for (int mi = 0; mi < 2; ++mi) {
        const int row = c1_0 + wm + mi * 16 + r;
        float* o0 = &g_Gpart[slice][b][row][c2_0 + wn];
        float* o1 = o0 + 8 * CH;
        #pragma unroll
        for (int nj = 0; nj < 8; ++nj) {
            *(float2*)&o0[nj * 8 + cpos] = make_float2(acc[mi][nj][0], acc[mi][nj][1]);
            *(float2*)&o1[nj * 8 + cpos] = make_float2(acc[mi][nj][2], acc[mi][nj][3]);
        }
    }
}

// ---------------------------------------------------------------------------
// gram_reduce: G = sum of GSLICES partial slices (deterministic)
// ---------------------------------------------------------------------------
__global__ __launch_bounds__(256) void gram_reduce_kernel()
{
    const int total = BATCH * CH * CH;
    const float* p = &g_Gpart[0][0][0][0];
    float* g = &g_G[0][0][0];
    for (int i = blockIdx.x * blockDim.x + threadIdx.x; i < total;
         i += gridDim.x * blockDim.x) {
        float s = 0.f;
        #pragma unroll
        for (int k = 0; k < GSLICES; ++k) s += p[k * total + i];
        g[i] = s;
    }
}

// ---------------------------------------------------------------------------
// g2bf: split G fp32 -> bf16 hi/lo
// ---------------------------------------------------------------------------
__global__ __launch_bounds__(256) void g2bf_kernel()
{
    const int total = BATCH * CH * CH;
    for (int i = blockIdx.x * blockDim.x + threadIdx.x; i < total;
         i += gridDim.x * blockDim.x) {
        int b  = i / (CH * CH);
        int li = i - b * CH * CH;
        int c  = li >> 8;
        int c2 = li & 255;
        float v = g_G[b][c][c2];
        __nv_bfloat16 hi = __float2bfloat16(v);
        __nv_bfloat16 lo = __float2bfloat16(v - __bfloat162float(hi));
        g_Gbf[((size_t)b * K2 + c) * CH + c2]      = hi;
        g_Gbf[((size_t)b * K2 + CH + c) * CH + c2] = lo;
    }
}

// ---------------------------------------------------------------------------
// qrow_mma: V = U G (3-term), fused epilogue q_part = rowsum(V .* U_fp32)
// ---------------------------------------------------------------------------
__global__ __launch_bounds__(256, 2) void qrow_mma_kernel(const float* __restrict__ Bin)
{
    extern __shared__ char smem[];
    const uint32_t smem_base = smem_u32(smem);
    const int tid  = threadIdx.x;
    const int wid  = tid >> 5;
    const int lane = tid & 31;

    const int ctile = blockIdx.x;
    const int n0    = blockIdx.y * 128;
    const int b     = blockIdx.z;

    const __nv_bfloat16* Ub = g_Bbf + ((size_t)b * HW + n0) * K2;
    const __nv_bfloat16* Gb = g_Gbf + (size_t)b * K2 * CH + (size_t)ctile * 128 * CH;

    uint32_t dstoff[8];
    const __nv_bfloat16* srcp[8];
    bool isA[8];
    #pragma unroll
    for (int it = 0; it < 8; ++it) {
        int idx = it * 256 + tid;
        int li  = idx & 1023;
        int row = li >> 3;
        int seg = li & 7;
        isA[it] = (idx < 1024);
        dstoff[it] = (isA[it] ? 0u : (uint32_t)CHUNK_BYTES)
                   + sw128((uint32_t)(row * 128 + seg * 16));
        srcp[it] = (isA[it] ? Ub + (size_t)row * K2 : Gb + (size_t)row * CH) + seg * 8;
    }

    const int NIT = 12;
    auto load_chunk = [&](int it, int buf) {
        const int term = it >> 2, kc = it & 3;
        const size_t uoff = (size_t)(term == 1 ? CH : 0) + kc * 64;
        const size_t goff = (size_t)(term == 2 ? CH : 0) * CH + kc * 64;
        const uint32_t base = smem_base + buf * BUF_BYTES;
        #pragma unroll
        for (int s = 0; s < 8; ++s)
            cp_async16(base + dstoff[s], srcp[s] + (isA[s] ? uoff : goff));
        cp_commit();
    };

    const int wm = (wid & 3) * 32;
    const int wn = (wid >> 2) * 64;
    float acc[2][8][4] = {};

    load_chunk(0, 0);
    load_chunk(1, 1);
    for (int c = 0; c < NIT; ++c) {
        if (c < NIT - 1) cp_wait<1>(); else cp_wait<0>();
        __syncthreads();
        const uint32_t aBase = smem_base + (c % NSTAGE) * BUF_BYTES;
        mma_chunk(aBase, aBase + CHUNK_BYTES, wm, wn, lane, acc);
        if (c + 2 < NIT) load_chunk(c + 2, (c + 2) % NSTAGE);
    }
    __syncthreads();

    // epilogue: q partial = sum_c V[n,c] * U[n,c]
    float* qs = (float*)smem;
    const int r    = lane >> 2;
    const int cpos = (lane & 3) * 2;

    float rs[2][2] = {};
    #pragma unroll
    for (int mi = 0; mi < 2; ++mi) {
        const size_t row0 = (size_t)b * HW + n0 + wm + mi * 16 + r;
        #pragma unroll
        for (int nj = 0; nj < 8; ++nj) {
            const int cc = ctile * 128 + wn + nj * 8 + cpos;
            float2 u0 = *(const float2*)&Bin[row0 * CH + cc];
            float2 u1 = *(const float2*)&Bin[(row0 + 8) * CH + cc];
            rs[mi][0] += acc[mi][nj][0] * u0.x + acc[mi][nj][1] * u0.y;
            rs[mi][1] += acc[mi][nj][2] * u1.x + acc[mi][nj][3] * u1.y;
        }
    }
    #pragma unroll
    for (int mi = 0; mi < 2; ++mi)
        #pragma unroll
        for (int h = 0; h < 2; ++h) {
            float v = rs[mi][h];
            v += __shfl_xor_sync(0xffffffffu, v, 1);
            v += __shfl_xor_sync(0xffffffffu, v, 2);
            rs[mi][h] = v;
        }
    if ((lane & 3) == 0) {
        #pragma unroll
        for (int mi = 0; mi < 2; ++mi)
            #pragma unroll
            for (int h = 0; h < 2; ++h)
                qs[(wid >> 2) * 128 + wm + mi * 16 + r + h * 8] = rs[mi][h];
    }
    __syncthreads();
    if (tid < 128)
        g_Qpart[b][ctile][n0 + tid] = qs[tid] + qs[128 + tid];
}

// ---------------------------------------------------------------------------
// qcombine: s = rsqrt(qp0 + qp1)
// ---------------------------------------------------------------------------
__global__ __launch_bounds__(256) void qcombine_kernel()
{
    int i = blockIdx.x * blockDim.x + threadIdx.x;
    if (i < BATCH * HW) {
        int b = i / HW, n = i - b * HW;
        g_S[b][n] = rsqrtf(g_Qpart[b][0][n] + g_Qpart[b][1][n]);
    }
}

// ---------------------------------------------------------------------------
// corr_mma: main GEMM, 3-stage pipeline, fused column-scale epilogue
// ---------------------------------------------------------------------------
#define NCHUNK 12
__global__ __launch_bounds__(256, 2) void corr_mma_kernel(float* __restrict__ out)
{
    extern __shared__ char smem[];
    const uint32_t smem_base = smem_u32(smem);
    const int tid  = threadIdx.x;
    const int wid  = tid >> 5;
    const int lane = tid & 31;

    const int b  = blockIdx.z;
    const int m0 = blockIdx.y * 128;
    const int n0 = blockIdx.x * 128;

    const __nv_bfloat16* Ab = g_Abf + ((size_t)b * HW + m0) * K2;
    const __nv_bfloat16* Bb = g_Bbf + ((size_t)b * HW + n0) * K2;

    const int a_k0[NCHUNK] = {0,64,128,192, 256,320,384,448, 0,64,128,192};
    const int b_k0[NCHUNK] = {0,64,128,192, 0,64,128,192, 256,320,384,448};

    uint32_t dstoff[8];
    const __nv_bfloat16* srcp[8];
    bool isA[8];
    #pragma unroll
    for (int it = 0; it < 8; ++it) {
        int idx = it * 256 + tid;
        int li  = idx & 1023;
        int row = li >> 3;
        int seg = li & 7;
        isA[it] = (idx < 1024);
        dstoff[it] = (isA[it] ? 0u : (uint32_t)CHUNK_BYTES)
                   + sw128((uint32_t)(row * 128 + seg * 16));
        srcp[it] = (isA[it] ? Ab : Bb) + (size_t)row * K2 + seg * 8;
    }

    auto load_chunk = [&](int c, int buf) {
        const uint32_t base = smem_base + buf * BUF_BYTES;
        const int ao = a_k0[c], bo = b_k0[c];
        #pragma unroll
        for (int it = 0; it < 8; ++it)
            cp_async16(base + dstoff[it], srcp[it] + (isA[it] ? ao : bo));
        cp_commit();
    };

    const int wm = (wid & 3) * 32;
    const int wn = (wid >> 2) * 64;
    float acc[2][8][4] = {};

    load_chunk(0, 0);
    load_chunk(1, 1);
    for (int c = 0; c < NCHUNK; ++c) {
        if (c < NCHUNK - 1) cp_wait<1>(); else cp_wait<0>();
        __syncthreads();
        const uint32_t aBase = smem_base + (c % NSTAGE) * BUF_BYTES;
        mma_chunk(aBase, aBase + CHUNK_BYTES, wm, wn, lane, acc);
        if (c + 2 < NCHUNK) load_chunk(c + 2, (c + 2) % NSTAGE);
    }
    __syncthreads();

    float* sSc = (float*)smem;
    if (tid < 128) sSc[tid] = g_S[b][n0 + tid];
    __syncthreads();

    const int r    = lane >> 2;
    const int cpos = (lane & 3) * 2;
    #pragma unroll
    for (int mi = 0; mi < 2; ++mi) {
        const int mrow = m0 + wm + mi * 16 + r;
        float* o0 = out + ((size_t)b * HW + mrow) * HW + n0 + wn;
        float* o1 = o0 + (size_t)8 * HW;
        #pragma unroll
        for (int nj = 0; nj < 8; ++nj) {
            const int nc = wn + nj * 8 + cpos;
            const float s0 = sSc[nc], s1 = sSc[nc + 1];
            float2 v0 = make_float2(acc[mi][nj][0] * s0, acc[mi][nj][1] * s1);
            float2 v1 = make_float2(acc[mi][nj][2] * s0, acc[mi][nj][3] * s1);
            *(float2*)&o0[nj * 8 + cpos] = v0;
            *(float2*)&o1[nj * 8 + cpos] = v1;
        }
    }
}

// ---------------------------------------------------------------------------
extern "C" void kernel_launch(void* const* d_in, const int* in_sizes, int n_in,
                              void* d_out, int out_size)
{
    const float* A = (const float*)d_in[0];
    const float* B = (const float*)d_in[1];
    float* out = (float*)d_out;

    static __nv_bfloat16* bbf_ptr = nullptr;
    if (!bbf_ptr) {
        cudaGetSymbolAddress((void**)&bbf_ptr, g_Bbf);
        cudaFuncSetAttribute(corr_mma_kernel,
                             cudaFuncAttributeMaxDynamicSharedMemorySize, SMEM_TOTAL);
        cudaFuncSetAttribute(gram_mma_kernel,
                             cudaFuncAttributeMaxDynamicSharedMemorySize, SMEM_TOTAL);
        cudaFuncSetAttribute(qrow_mma_kernel,
                             cudaFuncAttributeMaxDynamicSharedMemorySize, SMEM_TOTAL);
    }

    convert_kernel<<<1024, 256>>>(B, bbf_ptr);
    convertA_kernel<<<dim3(HW / 32, CH / 32, BATCH), 256>>>(A);
    gram_mma_kernel<<<dim3(2, 2, BATCH * GSLICES), 256, SMEM_TOTAL>>>();
    gram_reduce_kernel<<<1024, 256>>>();
    g2bf_kernel<<<512, 256>>>();
    qrow_mma_kernel<<<dim3(2, HW / 128, BATCH), 256, SMEM_TOTAL>>>(B);
    qcombine_kernel<<<(BATCH * HW + 255) / 256, 256>>>();
    corr_mma_kernel<<<dim3(HW / 128, HW / 128, BATCH), 256, SMEM_TOTAL>>>(out);
}

// round 7
// speedup vs baseline: 2.5318x; 1.0050x over previous
#include <cuda_runtime.h>
#include <cuda_bf16.h>
#include <cstdint>

#define BATCH 8
#define HW    2304        // 48*48
#define CH    256
#define K2    512         // scratch layout: [hi(256) | lo(256)]
#define GSLICES 12
#define GK     (HW / GSLICES)   // 192

// ---------------- scratch (device globals: allocation-free rule) -----------
__device__ float g_Gpart[GSLICES][BATCH][CH][CH];          // 24 MB
__device__ float g_Qpart[BATCH][2][HW];                    // 147 KB
__device__ __nv_bfloat16 g_Abf[(size_t)BATCH * HW * K2];   // 18.9 MB
__device__ __nv_bfloat16 g_Bbf[(size_t)BATCH * HW * K2];   // 18.9 MB
__device__ __nv_bfloat16 g_AbfT[(size_t)BATCH * K2 * HW];  // 18.9 MB
__device__ __nv_bfloat16 g_Gbf[(size_t)BATCH * K2 * CH];   // 2 MB

__device__ __forceinline__ uint32_t smem_u32(const void* p) {
    return (uint32_t)__cvta_generic_to_shared((void*)p);
}
__device__ __forceinline__ uint32_t sw128(uint32_t off) {
    return off ^ ((off >> 3) & 0x70);
}

__device__ __forceinline__ void ldsm_x4(uint32_t* r, uint32_t addr) {
    asm volatile("ldmatrix.sync.aligned.m8n8.x4.shared.b16 {%0,%1,%2,%3}, [%4];"
                 : "=r"(r[0]), "=r"(r[1]), "=r"(r[2]), "=r"(r[3]) : "r"(addr));
}
__device__ __forceinline__ void mma16816(float* c, const uint32_t* a,
                                         uint32_t b0, uint32_t b1) {
    asm volatile("mma.sync.aligned.m16n8k16.row.col.f32.bf16.bf16.f32 "
                 "{%0,%1,%2,%3}, {%4,%5,%6,%7}, {%8,%9}, {%0,%1,%2,%3};"
                 : "+f"(c[0]), "+f"(c[1]), "+f"(c[2]), "+f"(c[3])
                 : "r"(a[0]), "r"(a[1]), "r"(a[2]), "r"(a[3]), "r"(b0), "r"(b1));
}
__device__ __forceinline__ void cp_async16(uint32_t dst, const void* src) {
    asm volatile("cp.async.cg.shared.global [%0], [%1], 16;" :: "r"(dst), "l"(src));
}
__device__ __forceinline__ void cp_commit() {
    asm volatile("cp.async.commit_group;" ::: "memory");
}
template <int N> __device__ __forceinline__ void cp_wait() {
    asm volatile("cp.async.wait_group %0;" :: "n"(N) : "memory");
}

// ---- small-GEMM (128x128 tile, 8 warps 4x2) shared pieces -----------------
#define CHUNK_BYTES 16384
#define BUF_BYTES   (2 * CHUNK_BYTES)
#define NSTAGE      3
#define SMEM_AUX    (NSTAGE * BUF_BYTES)    // 98304

__device__ __forceinline__ void mma_chunk(uint32_t aBase, uint32_t bBase,
                                          int wm, int wn, int lane,
                                          float acc[2][8][4])
{
    const int i8 = lane & 7;
    const int g  = lane >> 3;
    #pragma unroll
    for (int ks = 0; ks < 4; ++ks) {
        const int kb = ks * 32;
        uint32_t afr[2][4];
        #pragma unroll
        for (int mi = 0; mi < 2; ++mi) {
            int row = wm + mi * 16 + i8 + (g & 1) * 8;
            int col = kb + (g >> 1) * 16;
            ldsm_x4(afr[mi], aBase + sw128((uint32_t)(row * 128 + col)));
        }
        uint32_t bfr[4][4];
        #pragma unroll
        for (int p = 0; p < 4; ++p) {
            int row = wn + p * 16 + i8 + (g >> 1) * 8;
            int col = kb + (g & 1) * 16;
            ldsm_x4(bfr[p], bBase + sw128((uint32_t)(row * 128 + col)));
        }
        #pragma unroll
        for (int mi = 0; mi < 2; ++mi)
            #pragma unroll
            for (int nj = 0; nj < 8; ++nj)
                mma16816(acc[mi][nj], afr[mi],
                         bfr[nj >> 1][(nj & 1) * 2],
                         bfr[nj >> 1][(nj & 1) * 2 + 1]);
    }
}

// ---------------------------------------------------------------------------
// convert (B): fp32 -> bf16 split
// ---------------------------------------------------------------------------
__global__ __launch_bounds__(256) void convert_kernel(const float* __restrict__ X,
                                                      __nv_bfloat16* __restrict__ Y)
{
    const size_t total4 = (size_t)BATCH * HW * CH / 4;
    for (size_t i = (size_t)blockIdx.x * blockDim.x + threadIdx.x; i < total4;
         i += (size_t)gridDim.x * blockDim.x) {
        float4 v = ((const float4*)X)[i];
        size_t row = i >> 6;
        int c = (int)(i & 63) * 4;
        float vv[4] = {v.x, v.y, v.z, v.w};
        __nv_bfloat16 hi[4], lo[4];
        #pragma unroll
        for (int j = 0; j < 4; ++j) {
            hi[j] = __float2bfloat16(vv[j]);
            lo[j] = __float2bfloat16(vv[j] - __bfloat162float(hi[j]));
        }
        __nv_bfloat162* ph = (__nv_bfloat162*)&Y[row * K2 + c];
        __nv_bfloat162* pl = (__nv_bfloat162*)&Y[row * K2 + CH + c];
        ph[0] = __nv_bfloat162{hi[0], hi[1]};
        ph[1] = __nv_bfloat162{hi[2], hi[3]};
        pl[0] = __nv_bfloat162{lo[0], lo[1]};
        pl[1] = __nv_bfloat162{lo[2], lo[3]};
    }
}

// ---------------------------------------------------------------------------
// fused A pass: read A once -> g_Abf + g_AbfT
// ---------------------------------------------------------------------------
__global__ __launch_bounds__(256) void convertA_kernel(const float* __restrict__ X)
{
    __shared__ float T[32][33];
    const int b  = blockIdx.z;
    const int m0 = blockIdx.x * 32;
    const int c0 = blockIdx.y * 32;
    const int tx = threadIdx.x & 31;
    const int ty = threadIdx.x >> 5;

    __nv_bfloat16* Ar = g_Abf + (size_t)b * HW * K2;
    #pragma unroll
    for (int k = 0; k < 4; ++k) {
        int row = ty + k * 8;
        float v = X[((size_t)b * HW + m0 + row) * CH + c0 + tx];
        T[row][tx] = v;
        __nv_bfloat16 hi = __float2bfloat16(v);
        __nv_bfloat16 lo = __float2bfloat16(v - __bfloat162float(hi));
        Ar[(size_t)(m0 + row) * K2 + c0 + tx]      = hi;
        Ar[(size_t)(m0 + row) * K2 + CH + c0 + tx] = lo;
    }
    __syncthreads();

    __nv_bfloat16* At = g_AbfT + (size_t)b * K2 * HW;
    #pragma unroll
    for (int k = 0; k < 4; ++k) {
        int c = ty + k * 8;
        float v = T[tx][c];
        __nv_bfloat16 hi = __float2bfloat16(v);
        __nv_bfloat16 lo = __float2bfloat16(v - __bfloat162float(hi));
        At[(size_t)(c0 + c) * HW + m0 + tx]      = hi;
        At[(size_t)(c0 + c + CH) * HW + m0 + tx] = lo;
    }
}

// ---------------------------------------------------------------------------
// gram_mma: G_part[slice][b], 3-term over m slice (9 chunk iters)
// ---------------------------------------------------------------------------
__global__ __launch_bounds__(256, 2) void gram_mma_kernel()
{
    extern __shared__ char smem[];
    const uint32_t smem_base = smem_u32(smem);
    const int tid  = threadIdx.x;
    const int wid  = tid >> 5;
    const int lane = tid & 31;

    const int b     = blockIdx.z / GSLICES;
    const int slice = blockIdx.z % GSLICES;
    const int c1_0  = blockIdx.y * 128;
    const int c2_0  = blockIdx.x * 128;

    const __nv_bfloat16* At = g_AbfT + (size_t)b * K2 * HW;

    uint32_t dstoff[8];
    const __nv_bfloat16* srcp[8];
    bool isA[8];
    #pragma unroll
    for (int it = 0; it < 8; ++it) {
        int idx = it * 256 + tid;
        int li  = idx & 1023;
        int row = li >> 3;
        int seg = li & 7;
        isA[it] = (idx < 1024);
        dstoff[it] = (isA[it] ? 0u : (uint32_t)CHUNK_BYTES)
                   + sw128((uint32_t)(row * 128 + seg * 16));
        srcp[it] = At + (size_t)((isA[it] ? c1_0 : c2_0) + row) * HW + seg * 8;
    }

    const int NIT = 9;
    auto load_chunk = [&](int it, int buf) {
        const int term = it / 3, kc = it - term * 3;
        const size_t aoff = (size_t)(term == 1 ? CH : 0) * HW + slice * GK + kc * 64;
        const size_t boff = (size_t)(term == 2 ? CH : 0) * HW + slice * GK + kc * 64;
        const uint32_t base = smem_base + buf * BUF_BYTES;
        #pragma unroll
        for (int s = 0; s < 8; ++s)
            cp_async16(base + dstoff[s], srcp[s] + (isA[s] ? aoff : boff));
        cp_commit();
    };

    const int wm = (wid & 3) * 32;
    const int wn = (wid >> 2) * 64;
    float acc[2][8][4] = {};

    load_chunk(0, 0);
    load_chunk(1, 1);
    for (int c = 0; c < NIT; ++c) {
        if (c < NIT - 1) cp_wait<1>(); else cp_wait<0>();
        __syncthreads();
        const uint32_t aBase = smem_base + (c % NSTAGE) * BUF_BYTES;
        mma_chunk(aBase, aBase + CHUNK_BYTES, wm, wn, lane, acc);
        if (c + 2 < NIT) load_chunk(c + 2, (c + 2) % NSTAGE);
    }

    const int r    = lane >> 2;
    const int cpos = (lane & 3) * 2;
    #pragma unroll
    for (int mi = 0; mi < 2; ++mi) {
        const int row = c1_0 + wm + mi * 16 + r;
        float* o0 = &g_Gpart[slice][b][row][c2_0 + wn];
        float* o1 = o0 + 8 * CH;
        #pragma unroll
        for (int nj = 0; nj < 8; ++nj) {
            *(float2*)&o0[nj * 8 + cpos] = make_float2(acc[mi][nj][0], acc[mi][nj][1]);
            *(float2*)&o1[nj * 8 + cpos] = make_float2(acc[mi][nj][2], acc[mi][nj][3]);
        }
    }
}

// ---------------------------------------------------------------------------
// greduce_bf: G = sum partials, write bf16 hi/lo directly (fused g2bf)
// ---------------------------------------------------------------------------
__global__ __launch_bounds__(256) void greduce_bf_kernel()
{
    const int total = BATCH * CH * CH;
    const float* p = &g_Gpart[0][0][0][0];
    for (int i = blockIdx.x * blockDim.x + threadIdx.x; i < total;
         i += gridDim.x * blockDim.x) {
        float s = 0.f;
        #pragma unroll
        for (int k = 0; k < GSLICES; ++k) s += p[k * total + i];
        int b  = i / (CH * CH);
        int li = i - b * CH * CH;
        int c  = li >> 8;
        int c2 = li & 255;
        __nv_bfloat16 hi = __float2bfloat16(s);
        __nv_bfloat16 lo = __float2bfloat16(s - __bfloat162float(hi));
        g_Gbf[((size_t)b * K2 + c) * CH + c2]      = hi;
        g_Gbf[((size_t)b * K2 + CH + c) * CH + c2] = lo;
    }
}

// ---------------------------------------------------------------------------
// qrow_mma: V = U G (3-term), fused epilogue q_part = rowsum(V .* U_fp32)
// ---------------------------------------------------------------------------
__global__ __launch_bounds__(256, 2) void qrow_mma_kernel(const float* __restrict__ Bin)
{
    extern __shared__ char smem[];
    const uint32_t smem_base = smem_u32(smem);
    const int tid  = threadIdx.x;
    const int wid  = tid >> 5;
    const int lane = tid & 31;

    const int ctile = blockIdx.x;
    const int n0    = blockIdx.y * 128;
    const int b     = blockIdx.z;

    const __nv_bfloat16* Ub = g_Bbf + ((size_t)b * HW + n0) * K2;
    const __nv_bfloat16* Gb = g_Gbf + (size_t)b * K2 * CH + (size_t)ctile * 128 * CH;

    uint32_t dstoff[8];
    const __nv_bfloat16* srcp[8];
    bool isA[8];
    #pragma unroll
    for (int it = 0; it < 8; ++it) {
        int idx = it * 256 + tid;
        int li  = idx & 1023;
        int row = li >> 3;
        int seg = li & 7;
        isA[it] = (idx < 1024);
        dstoff[it] = (isA[it] ? 0u : (uint32_t)CHUNK_BYTES)
                   + sw128((uint32_t)(row * 128 + seg * 16));
        srcp[it] = (isA[it] ? Ub + (size_t)row * K2 : Gb + (size_t)row * CH) + seg * 8;
    }

    const int NIT = 12;
    auto load_chunk = [&](int it, int buf) {
        const int term = it >> 2, kc = it & 3;
        const size_t uoff = (size_t)(term == 1 ? CH : 0) + kc * 64;
        const size_t goff = (size_t)(term == 2 ? CH : 0) * CH + kc * 64;
        const uint32_t base = smem_base + buf * BUF_BYTES;
        #pragma unroll
        for (int s = 0; s < 8; ++s)
            cp_async16(base + dstoff[s], srcp[s] + (isA[s] ? uoff : goff));
        cp_commit();
    };

    const int wm = (wid & 3) * 32;
    const int wn = (wid >> 2) * 64;
    float acc[2][8][4] = {};

    load_chunk(0, 0);
    load_chunk(1, 1);
    for (int c = 0; c < NIT; ++c) {
        if (c < NIT - 1) cp_wait<1>(); else cp_wait<0>();
        __syncthreads();
        const uint32_t aBase = smem_base + (c % NSTAGE) * BUF_BYTES;
        mma_chunk(aBase, aBase + CHUNK_BYTES, wm, wn, lane, acc);
        if (c + 2 < NIT) load_chunk(c + 2, (c + 2) % NSTAGE);
    }
    __syncthreads();

    float* qs = (float*)smem;
    const int r    = lane >> 2;
    const int cpos = (lane & 3) * 2;

    float rs[2][2] = {};
    #pragma unroll
    for (int mi = 0; mi < 2; ++mi) {
        const size_t row0 = (size_t)b * HW + n0 + wm + mi * 16 + r;
        #pragma unroll
        for (int nj = 0; nj < 8; ++nj) {
            const int cc = ctile * 128 + wn + nj * 8 + cpos;
            float2 u0 = *(const float2*)&Bin[row0 * CH + cc];
            float2 u1 = *(const float2*)&Bin[(row0 + 8) * CH + cc];
            rs[mi][0] += acc[mi][nj][0] * u0.x + acc[mi][nj][1] * u0.y;
            rs[mi][1] += acc[mi][nj][2] * u1.x + acc[mi][nj][3] * u1.y;
        }
    }
    #pragma unroll
    for (int mi = 0; mi < 2; ++mi)
        #pragma unroll
        for (int h = 0; h < 2; ++h) {
            float v = rs[mi][h];
            v += __shfl_xor_sync(0xffffffffu, v, 1);
            v += __shfl_xor_sync(0xffffffffu, v, 2);
            rs[mi][h] = v;
        }
    if ((lane & 3) == 0) {
        #pragma unroll
        for (int mi = 0; mi < 2; ++mi)
            #pragma unroll
            for (int h = 0; h < 2; ++h)
                qs[(wid >> 2) * 128 + wm + mi * 16 + r + h * 8] = rs[mi][h];
    }
    __syncthreads();
    if (tid < 128)
        g_Qpart[b][ctile][n0 + tid] = qs[tid] + qs[128 + tid];
}

// ---------------------------------------------------------------------------
// corr_mma: 128x256 CTA tile, 8 warps of 64x64, 3-stage pipeline,
// fused rsqrt(q)-scale epilogue.
// ---------------------------------------------------------------------------
#define C_ABYTES 16384                       // 128 x 128B
#define C_BBYTES 32768                       // 256 x 128B
#define C_STAGE  (C_ABYTES + C_BBYTES)       // 49152
#define C_SMEM   (3 * C_STAGE)               // 147456
#define NCHUNK   12

__global__ __launch_bounds__(256, 1) void corr_mma_kernel(float* __restrict__ out)
{
    extern __shared__ char smem[];
    const uint32_t smem_base = smem_u32(smem);
    const int tid  = threadIdx.x;
    const int wid  = tid >> 5;
    const int lane = tid & 31;

    const int b  = blockIdx.z;
    const int m0 = blockIdx.y * 128;
    const int n0 = blockIdx.x * 256;

    const __nv_bfloat16* Ab = g_Abf + ((size_t)b * HW + m0) * K2;
    const __nv_bfloat16* Bb = g_Bbf + ((size_t)b * HW + n0) * K2;

    const int a_k0[NCHUNK] = {0,64,128,192, 256,320,384,448, 0,64,128,192};
    const int b_k0[NCHUNK] = {0,64,128,192, 0,64,128,192, 256,320,384,448};

    auto load_chunk = [&](int c, int buf) {
        const uint32_t sb = smem_base + buf * C_STAGE;
        const int ao = a_k0[c], bo = b_k0[c];
        #pragma unroll
        for (int s = 0; s < 4; ++s) {          // A: 128 rows
            int li = s * 256 + tid;
            int row = li >> 3, seg = li & 7;
            cp_async16(sb + sw128((uint32_t)(row * 128 + seg * 16)),
                       Ab + (size_t)row * K2 + seg * 8 + ao);
        }
        #pragma unroll
        for (int s = 0; s < 8; ++s) {          // B: 256 rows
            int li = s * 256 + tid;
            int row = li >> 3, seg = li & 7;
            cp_async16(sb + C_ABYTES + sw128((uint32_t)(row * 128 + seg * 16)),
                       Bb + (size_t)row * K2 + seg * 8 + bo);
        }
        cp_commit();
    };

    const int wm = (wid & 1) * 64;   // 2 m-warps
    const int wn = (wid >> 1) * 64;  // 4 n-warps
    float acc[4][8][4] = {};

    load_chunk(0, 0);
    load_chunk(1, 1);
    for (int c = 0; c < NCHUNK; ++c) {
        if (c < NCHUNK - 1) cp_wait<1>(); else cp_wait<0>();
        __syncthreads();

        const uint32_t aB = smem_base + (c % 3) * C_STAGE;
        const uint32_t bB = aB + C_ABYTES;
        const int i8 = lane & 7;
        const int g  = lane >> 3;

        #pragma unroll
        for (int ks = 0; ks < 4; ++ks) {
            const int kb = ks * 32;
            uint32_t afr[4][4];
            #pragma unroll
            for (int mi = 0; mi < 4; ++mi) {
                int row = wm + mi * 16 + i8 + (g & 1) * 8;
                int col = kb + (g >> 1) * 16;
                ldsm_x4(afr[mi], aB + sw128((uint32_t)(row * 128 + col)));
            }
            #pragma unroll
            for (int p = 0; p < 4; ++p) {
                uint32_t bfr[4];
                int row = wn + p * 16 + i8 + (g >> 1) * 8;
                int col = kb + (g & 1) * 16;
                ldsm_x4(bfr, bB + sw128((uint32_t)(row * 128 + col)));
                #pragma unroll
                for (int mi = 0; mi < 4; ++mi) {
                    mma16816(acc[mi][2 * p],     afr[mi], bfr[0], bfr[1]);
                    mma16816(acc[mi][2 * p + 1], afr[mi], bfr[2], bfr[3]);
                }
            }
        }
        if (c + 2 < NCHUNK) load_chunk(c + 2, (c + 2) % 3);
    }
    __syncthreads();

    // fused scale: s = rsqrt(qp0+qp1), staged in smem
    float* sSc = (float*)smem;
    sSc[tid] = rsqrtf(g_Qpart[b][0][n0 + tid] + g_Qpart[b][1][n0 + tid]);
    __syncthreads();

    const int r    = lane >> 2;
    const int cpos = (lane & 3) * 2;
    #pragma unroll
    for (int mi = 0; mi < 4; ++mi) {
        const int mrow = m0 + wm + mi * 16 + r;
        float* o0 = out + ((size_t)b * HW + mrow) * HW + n0 + wn;
        float* o1 = o0 + (size_t)8 * HW;
        #pragma unroll
        for (int nj = 0; nj < 8; ++nj) {
            const int nc = wn + nj * 8 + cpos;
            const float s0 = sSc[nc], s1 = sSc[nc + 1];
            float2 v0 = make_float2(acc[mi][nj][0] * s0, acc[mi][nj][1] * s1);
            float2 v1 = make_float2(acc[mi][nj][2] * s0, acc[mi][nj][3] * s1);
            *(float2*)&o0[nj * 8 + cpos] = v0;
            *(float2*)&o1[nj * 8 + cpos] = v1;
        }
    }
}

// ---------------------------------------------------------------------------
extern "C" void kernel_launch(void* const* d_in, const int* in_sizes, int n_in,
                              void* d_out, int out_size)
{
    const float* A = (const float*)d_in[0];
    const float* B = (const float*)d_in[1];
    float* out = (float*)d_out;

    static __nv_bfloat16* bbf_ptr = nullptr;
    if (!bbf_ptr) {
        cudaGetSymbolAddress((void**)&bbf_ptr, g_Bbf);
        cudaFuncSetAttribute(corr_mma_kernel,
                             cudaFuncAttributeMaxDynamicSharedMemorySize, C_SMEM);
        cudaFuncSetAttribute(gram_mma_kernel,
                             cudaFuncAttributeMaxDynamicSharedMemorySize, SMEM_AUX);
        cudaFuncSetAttribute(qrow_mma_kernel,
                             cudaFuncAttributeMaxDynamicSharedMemorySize, SMEM_AUX);
    }

    convert_kernel<<<1024, 256>>>(B, bbf_ptr);
    convertA_kernel<<<dim3(HW / 32, CH / 32, BATCH), 256>>>(A);
    gram_mma_kernel<<<dim3(2, 2, BATCH * GSLICES), 256, SMEM_AUX>>>();
    greduce_bf_kernel<<<1024, 256>>>();
    qrow_mma_kernel<<<dim3(2, HW / 128, BATCH), 256, SMEM_AUX>>>(B);
    corr_mma_kernel<<<dim3(HW / 256, HW / 128, BATCH), 256, C_SMEM>>>(out);
}

// round 8
// speedup vs baseline: 3.0588x; 1.2081x over previous
#include <cuda_runtime.h>
#include <cuda_fp16.h>
#include <cstdint>

#define BATCH 8
#define HW    2304        // 48*48
#define CH    256
#define K2    512         // scratch layout: [hi(256) | lo(256)]
#define GSLICES 6
#define GK     (HW / GSLICES)   // 384

// ---------------- scratch (device globals: allocation-free rule) -----------
__device__ float g_Gpart[GSLICES][BATCH][CH][CH];   // 12 MB
__device__ float g_Qpart[BATCH][2][HW];             // 147 KB
__device__ __half g_Ah[(size_t)BATCH * HW * K2];    // 18.9 MB
__device__ __half g_Bh[(size_t)BATCH * HW * K2];    // 18.9 MB
__device__ __half g_AhT[(size_t)BATCH * K2 * HW];   // 18.9 MB  [c(hi|lo)][m]
__device__ __half g_Gh[(size_t)BATCH * K2 * CH];    // 2 MB     [c(hi|lo)][c2]

__device__ __forceinline__ uint32_t smem_u32(const void* p) {
    return (uint32_t)__cvta_generic_to_shared((void*)p);
}
__device__ __forceinline__ uint32_t sw128(uint32_t off) {
    return off ^ ((off >> 3) & 0x70);
}

__device__ __forceinline__ void ldsm_x4(uint32_t* r, uint32_t addr) {
    asm volatile("ldmatrix.sync.aligned.m8n8.x4.shared.b16 {%0,%1,%2,%3}, [%4];"
                 : "=r"(r[0]), "=r"(r[1]), "=r"(r[2]), "=r"(r[3]) : "r"(addr));
}
__device__ __forceinline__ void mma16816(float* c, const uint32_t* a,
                                         uint32_t b0, uint32_t b1) {
    asm volatile("mma.sync.aligned.m16n8k16.row.col.f32.f16.f16.f32 "
                 "{%0,%1,%2,%3}, {%4,%5,%6,%7}, {%8,%9}, {%0,%1,%2,%3};"
                 : "+f"(c[0]), "+f"(c[1]), "+f"(c[2]), "+f"(c[3])
                 : "r"(a[0]), "r"(a[1]), "r"(a[2]), "r"(a[3]), "r"(b0), "r"(b1));
}
__device__ __forceinline__ void cp_async16(uint32_t dst, const void* src) {
    asm volatile("cp.async.cg.shared.global [%0], [%1], 16;" :: "r"(dst), "l"(src));
}
__device__ __forceinline__ void cp_commit() {
    asm volatile("cp.async.commit_group;" ::: "memory");
}
template <int N> __device__ __forceinline__ void cp_wait() {
    asm volatile("cp.async.wait_group %0;" :: "n"(N) : "memory");
}

// ---- small-GEMM (128x128 tile, 8 warps 4x2) shared pieces -----------------
#define CHUNK_BYTES 16384
#define BUF_BYTES   (2 * CHUNK_BYTES)
#define NSTAGE      3
#define SMEM_AUX    (NSTAGE * BUF_BYTES)    // 98304

__device__ __forceinline__ void mma_chunk(uint32_t aBase, uint32_t bBase,
                                          int wm, int wn, int lane,
                                          float acc[2][8][4])
{
    const int i8 = lane & 7;
    const int g  = lane >> 3;
    #pragma unroll
    for (int ks = 0; ks < 4; ++ks) {
        const int kb = ks * 32;
        uint32_t afr[2][4];
        #pragma unroll
        for (int mi = 0; mi < 2; ++mi) {
            int row = wm + mi * 16 + i8 + (g & 1) * 8;
            int col = kb + (g >> 1) * 16;
            ldsm_x4(afr[mi], aBase + sw128((uint32_t)(row * 128 + col)));
        }
        uint32_t bfr[4][4];
        #pragma unroll
        for (int p = 0; p < 4; ++p) {
            int row = wn + p * 16 + i8 + (g >> 1) * 8;
            int col = kb + (g & 1) * 16;
            ldsm_x4(bfr[p], bBase + sw128((uint32_t)(row * 128 + col)));
        }
        #pragma unroll
        for (int mi = 0; mi < 2; ++mi)
            #pragma unroll
            for (int nj = 0; nj < 8; ++nj)
                mma16816(acc[mi][nj], afr[mi],
                         bfr[nj >> 1][(nj & 1) * 2],
                         bfr[nj >> 1][(nj & 1) * 2 + 1]);
    }
}

// ---------------------------------------------------------------------------
// convert (B): fp32 -> fp16 split [hi | lo]
// ---------------------------------------------------------------------------
__global__ __launch_bounds__(256) void convert_kernel(const float* __restrict__ X,
                                                      __half* __restrict__ Y)
{
    const size_t total4 = (size_t)BATCH * HW * CH / 4;
    for (size_t i = (size_t)blockIdx.x * blockDim.x + threadIdx.x; i < total4;
         i += (size_t)gridDim.x * blockDim.x) {
        float4 v = ((const float4*)X)[i];
        size_t row = i >> 6;
        int c = (int)(i & 63) * 4;
        float vv[4] = {v.x, v.y, v.z, v.w};
        __half hi[4], lo[4];
        #pragma unroll
        for (int j = 0; j < 4; ++j) {
            hi[j] = __float2half(vv[j]);
            lo[j] = __float2half(vv[j] - __half2float(hi[j]));
        }
        __half2* ph = (__half2*)&Y[row * K2 + c];
        __half2* pl = (__half2*)&Y[row * K2 + CH + c];
        ph[0] = __half2{hi[0], hi[1]};
        ph[1] = __half2{hi[2], hi[3]};
        pl[0] = __half2{lo[0], lo[1]};
        pl[1] = __half2{lo[2], lo[3]};
    }
}

// ---------------------------------------------------------------------------
// fused A pass: read A once -> g_Ah (row-major split) + g_AhT (transposed)
// ---------------------------------------------------------------------------
__global__ __launch_bounds__(256) void convertA_kernel(const float* __restrict__ X)
{
    __shared__ float T[32][33];
    const int b  = blockIdx.z;
    const int m0 = blockIdx.x * 32;
    const int c0 = blockIdx.y * 32;
    const int tx = threadIdx.x & 31;
    const int ty = threadIdx.x >> 5;

    __half* Ar = g_Ah + (size_t)b * HW * K2;
    #pragma unroll
    for (int k = 0; k < 4; ++k) {
        int row = ty + k * 8;
        float v = X[((size_t)b * HW + m0 + row) * CH + c0 + tx];
        T[row][tx] = v;
        __half hi = __float2half(v);
        __half lo = __float2half(v - __half2float(hi));
        Ar[(size_t)(m0 + row) * K2 + c0 + tx]      = hi;
        Ar[(size_t)(m0 + row) * K2 + CH + c0 + tx] = lo;
    }
    __syncthreads();

    __half* At = g_AhT + (size_t)b * K2 * HW;
    #pragma unroll
    for (int k = 0; k < 4; ++k) {
        int c = ty + k * 8;
        float v = T[tx][c];
        __half hi = __float2half(v);
        __half lo = __float2half(v - __half2float(hi));
        At[(size_t)(c0 + c) * HW + m0 + tx]      = hi;
        At[(size_t)(c0 + c + CH) * HW + m0 + tx] = lo;
    }
}

// ---------------------------------------------------------------------------
// gram_mma: G_part[slice][b], 3-term fp16 over m slice (18 chunk iters)
// ---------------------------------------------------------------------------
__global__ __launch_bounds__(256, 2) void gram_mma_kernel()
{
    extern __shared__ char smem[];
    const uint32_t smem_base = smem_u32(smem);
    const int tid  = threadIdx.x;
    const int wid  = tid >> 5;
    const int lane = tid & 31;

    const int b     = blockIdx.z / GSLICES;
    const int slice = blockIdx.z % GSLICES;
    const int c1_0  = blockIdx.y * 128;
    const int c2_0  = blockIdx.x * 128;

    const __half* At = g_AhT + (size_t)b * K2 * HW;

    uint32_t dstoff[8];
    const __half* srcp[8];
    bool isA[8];
    #pragma unroll
    for (int it = 0; it < 8; ++it) {
        int idx = it * 256 + tid;
        int li  = idx & 1023;
        int row = li >> 3;
        int seg = li & 7;
        isA[it] = (idx < 1024);
        dstoff[it] = (isA[it] ? 0u : (uint32_t)CHUNK_BYTES)
                   + sw128((uint32_t)(row * 128 + seg * 16));
        srcp[it] = At + (size_t)((isA[it] ? c1_0 : c2_0) + row) * HW + seg * 8;
    }

    const int NIT = 18;   // 3 terms x 6 chunks of 64 within GK=384
    auto load_chunk = [&](int it, int buf) {
        const int term = it / 6, kc = it - term * 6;
        const size_t aoff = (size_t)(term == 1 ? CH : 0) * HW + slice * GK + kc * 64;
        const size_t boff = (size_t)(term == 2 ? CH : 0) * HW + slice * GK + kc * 64;
        const uint32_t base = smem_base + buf * BUF_BYTES;
        #pragma unroll
        for (int s = 0; s < 8; ++s)
            cp_async16(base + dstoff[s], srcp[s] + (isA[s] ? aoff : boff));
        cp_commit();
    };

    const int wm = (wid & 3) * 32;
    const int wn = (wid >> 2) * 64;
    float acc[2][8][4] = {};

    load_chunk(0, 0);
    load_chunk(1, 1);
    for (int c = 0; c < NIT; ++c) {
        if (c < NIT - 1) cp_wait<1>(); else cp_wait<0>();
        __syncthreads();
        const uint32_t aBase = smem_base + (c % NSTAGE) * BUF_BYTES;
        mma_chunk(aBase, aBase + CHUNK_BYTES, wm, wn, lane, acc);
        if (c + 2 < NIT) load_chunk(c + 2, (c + 2) % NSTAGE);
    }

    const int r    = lane >> 2;
    const int cpos = (lane & 3) * 2;
    #pragma unroll
    for (int mi = 0; mi < 2; ++mi) {
        const int row = c1_0 + wm + mi * 16 + r;
        float* o0 = &g_Gpart[slice][b][row][c2_0 + wn];
        float* o1 = o0 + 8 * CH;
        #pragma unroll
        for (int nj = 0; nj < 8; ++nj) {
            *(float2*)&o0[nj * 8 + cpos] = make_float2(acc[mi][nj][0], acc[mi][nj][1]);
            *(float2*)&o1[nj * 8 + cpos] = make_float2(acc[mi][nj][2], acc[mi][nj][3]);
        }
    }
}

// ---------------------------------------------------------------------------
// greduce: G = sum partials, write fp16 hi/lo split directly
// ---------------------------------------------------------------------------
__global__ __launch_bounds__(256) void greduce_kernel()
{
    const int total = BATCH * CH * CH;
    const float* p = &g_Gpart[0][0][0][0];
    for (int i = blockIdx.x * blockDim.x + threadIdx.x; i < total;
         i += gridDim.x * blockDim.x) {
        float s = 0.f;
        #pragma unroll
        for (int k = 0; k < GSLICES; ++k) s += p[k * total + i];
        int b  = i / (CH * CH);
        int li = i - b * CH * CH;
        int c  = li >> 8;
        int c2 = li & 255;
        __half hi = __float2half(s);
        __half lo = __float2half(s - __half2float(hi));
        g_Gh[((size_t)b * K2 + c) * CH + c2]      = hi;
        g_Gh[((size_t)b * K2 + CH + c) * CH + c2] = lo;
    }
}

// ---------------------------------------------------------------------------
// qrow_mma: V = U G (3-term fp16), fused epilogue q_part = rowsum(V .* U_fp32)
// ---------------------------------------------------------------------------
__global__ __launch_bounds__(256, 2) void qrow_mma_kernel(const float* __restrict__ Bin)
{
    extern __shared__ char smem[];
    const uint32_t smem_base = smem_u32(smem);
    const int tid  = threadIdx.x;
    const int wid  = tid >> 5;
    const int lane = tid & 31;

    const int ctile = blockIdx.x;
    const int n0    = blockIdx.y * 128;
    const int b     = blockIdx.z;

    const __half* Ub = g_Bh + ((size_t)b * HW + n0) * K2;
    const __half* Gb = g_Gh + (size_t)b * K2 * CH + (size_t)ctile * 128 * CH;

    uint32_t dstoff[8];
    const __half* srcp[8];
    bool isA[8];
    #pragma unroll
    for (int it = 0; it < 8; ++it) {
        int idx = it * 256 + tid;
        int li  = idx & 1023;
        int row = li >> 3;
        int seg = li & 7;
        isA[it] = (idx < 1024);
        dstoff[it] = (isA[it] ? 0u : (uint32_t)CHUNK_BYTES)
                   + sw128((uint32_t)(row * 128 + seg * 16));
        srcp[it] = (isA[it] ? Ub + (size_t)row * K2 : Gb + (size_t)row * CH) + seg * 8;
    }

    const int NIT = 12;
    auto load_chunk = [&](int it, int buf) {
        const int term = it >> 2, kc = it & 3;
        const size_t uoff = (size_t)(term == 1 ? CH : 0) + kc * 64;
        const size_t goff = (size_t)(term == 2 ? CH : 0) * CH + kc * 64;
        const uint32_t base = smem_base + buf * BUF_BYTES;
        #pragma unroll
        for (int s = 0; s < 8; ++s)
            cp_async16(base + dstoff[s], srcp[s] + (isA[s] ? uoff : goff));
        cp_commit();
    };

    const int wm = (wid & 3) * 32;
    const int wn = (wid >> 2) * 64;
    float acc[2][8][4] = {};

    load_chunk(0, 0);
    load_chunk(1, 1);
    for (int c = 0; c < NIT; ++c) {
        if (c < NIT - 1) cp_wait<1>(); else cp_wait<0>();
        __syncthreads();
        const uint32_t aBase = smem_base + (c % NSTAGE) * BUF_BYTES;
        mma_chunk(aBase, aBase + CHUNK_BYTES, wm, wn, lane, acc);
        if (c + 2 < NIT) load_chunk(c + 2, (c + 2) % NSTAGE);
    }
    __syncthreads();

    float* qs = (float*)smem;
    const int r    = lane >> 2;
    const int cpos = (lane & 3) * 2;

    float rs[2][2] = {};
    #pragma unroll
    for (int mi = 0; mi < 2; ++mi) {
        const size_t row0 = (size_t)b * HW + n0 + wm + mi * 16 + r;
        #pragma unroll
        for (int nj = 0; nj < 8; ++nj) {
            const int cc = ctile * 128 + wn + nj * 8 + cpos;
            float2 u0 = *(const float2*)&Bin[row0 * CH + cc];
            float2 u1 = *(const float2*)&Bin[(row0 + 8) * CH + cc];
            rs[mi][0] += acc[mi][nj][0] * u0.x + acc[mi][nj][1] * u0.y;
            rs[mi][1] += acc[mi][nj][2] * u1.x + acc[mi][nj][3] * u1.y;
        }
    }
    #pragma unroll
    for (int mi = 0; mi < 2; ++mi)
        #pragma unroll
        for (int h = 0; h < 2; ++h) {
            float v = rs[mi][h];
            v += __shfl_xor_sync(0xffffffffu, v, 1);
            v += __shfl_xor_sync(0xffffffffu, v, 2);
            rs[mi][h] = v;
        }
    if ((lane & 3) == 0) {
        #pragma unroll
        for (int mi = 0; mi < 2; ++mi)
            #pragma unroll
            for (int h = 0; h < 2; ++h)
                qs[(wid >> 2) * 128 + wm + mi * 16 + r + h * 8] = rs[mi][h];
    }
    __syncthreads();
    if (tid < 128)
        g_Qpart[b][ctile][n0 + tid] = qs[tid] + qs[128 + tid];
}

// ---------------------------------------------------------------------------
// corr_mma: 128x256 CTA tile, 8 warps of 64x64.
// 2-term fp16 split: 8 K-chunks — A {hi,lo}, B {hi,hi}. Fused rsqrt-scale.
// ---------------------------------------------------------------------------
#define C_ABYTES 16384
#define C_BBYTES 32768
#define C_STAGE  (C_ABYTES + C_BBYTES)
#define C_SMEM   (3 * C_STAGE)
#define NCHUNK   8

__global__ __launch_bounds__(256, 1) void corr_mma_kernel(float* __restrict__ out)
{
    extern __shared__ char smem[];
    const uint32_t smem_base = smem_u32(smem);
    const int tid  = threadIdx.x;
    const int wid  = tid >> 5;
    const int lane = tid & 31;

    const int b  = blockIdx.z;
    const int m0 = blockIdx.y * 128;
    const int n0 = blockIdx.x * 256;

    const __half* Ab = g_Ah + ((size_t)b * HW + m0) * K2;
    const __half* Bb = g_Bh + ((size_t)b * HW + n0) * K2;

    // A: hi then lo; B: hi twice (2-term split, Ahi*Blo dropped)
    const int a_k0[NCHUNK] = {0,64,128,192, 256,320,384,448};
    const int b_k0[NCHUNK] = {0,64,128,192, 0,64,128,192};

    auto load_chunk = [&](int c, int buf) {
        const uint32_t sb = smem_base + buf * C_STAGE;
        const int ao = a_k0[c], bo = b_k0[c];
        #pragma unroll
        for (int s = 0; s < 4; ++s) {          // A: 128 rows
            int li = s * 256 + tid;
            int row = li >> 3, seg = li & 7;
            cp_async16(sb + sw128((uint32_t)(row * 128 + seg * 16)),
                       Ab + (size_t)row * K2 + seg * 8 + ao);
        }
        #pragma unroll
        for (int s = 0; s < 8; ++s) {          // B: 256 rows
            int li = s * 256 + tid;
            int row = li >> 3, seg = li & 7;
            cp_async16(sb + C_ABYTES + sw128((uint32_t)(row * 128 + seg * 16)),
                       Bb + (size_t)row * K2 + seg * 8 + bo);
        }
        cp_commit();
    };

    const int wm = (wid & 1) * 64;
    const int wn = (wid >> 1) * 64;
    float acc[4][8][4] = {};

    load_chunk(0, 0);
    load_chunk(1, 1);
    for (int c = 0; c < NCHUNK; ++c) {
        if (c < NCHUNK - 1) cp_wait<1>(); else cp_wait<0>();
        __syncthreads();

        const uint32_t aB = smem_base + (c % 3) * C_STAGE;
        const uint32_t bB = aB + C_ABYTES;
        const int i8 = lane & 7;
        const int g  = lane >> 3;

        #pragma unroll
        for (int ks = 0; ks < 4; ++ks) {
            const int kb = ks * 32;
            uint32_t afr[4][4];
            #pragma unroll
            for (int mi = 0; mi < 4; ++mi) {
                int row = wm + mi * 16 + i8 + (g & 1) * 8;
                int col = kb + (g >> 1) * 16;
                ldsm_x4(afr[mi], aB + sw128((uint32_t)(row * 128 + col)));
            }
            #pragma unroll
            for (int p = 0; p < 4; ++p) {
                uint32_t bfr[4];
                int row = wn + p * 16 + i8 + (g >> 1) * 8;
                int col = kb + (g & 1) * 16;
                ldsm_x4(bfr, bB + sw128((uint32_t)(row * 128 + col)));
                #pragma unroll
                for (int mi = 0; mi < 4; ++mi) {
                    mma16816(acc[mi][2 * p],     afr[mi], bfr[0], bfr[1]);
                    mma16816(acc[mi][2 * p + 1], afr[mi], bfr[2], bfr[3]);
                }
            }
        }
        if (c + 2 < NCHUNK) load_chunk(c + 2, (c + 2) % 3);
    }
    __syncthreads();

    float* sSc = (float*)smem;
    sSc[tid] = rsqrtf(g_Qpart[b][0][n0 + tid] + g_Qpart[b][1][n0 + tid]);
    __syncthreads();

    const int r    = lane >> 2;
    const int cpos = (lane & 3) * 2;
    #pragma unroll
    for (int mi = 0; mi < 4; ++mi) {
        const int mrow = m0 + wm + mi * 16 + r;
        float* o0 = out + ((size_t)b * HW + mrow) * HW + n0 + wn;
        float* o1 = o0 + (size_t)8 * HW;
        #pragma unroll
        for (int nj = 0; nj < 8; ++nj) {
            const int nc = wn + nj * 8 + cpos;
            const float s0 = sSc[nc], s1 = sSc[nc + 1];
            float2 v0 = make_float2(acc[mi][nj][0] * s0, acc[mi][nj][1] * s1);
            float2 v1 = make_float2(acc[mi][nj][2] * s0, acc[mi][nj][3] * s1);
            *(float2*)&o0[nj * 8 + cpos] = v0;
            *(float2*)&o1[nj * 8 + cpos] = v1;
        }
    }
}

// ---------------------------------------------------------------------------
extern "C" void kernel_launch(void* const* d_in, const int* in_sizes, int n_in,
                              void* d_out, int out_size)
{
    const float* A = (const float*)d_in[0];
    const float* B = (const float*)d_in[1];
    float* out = (float*)d_out;

    static __half* bh_ptr = nullptr;
    if (!bh_ptr) {
        cudaGetSymbolAddress((void**)&bh_ptr, g_Bh);
        cudaFuncSetAttribute(corr_mma_kernel,
                             cudaFuncAttributeMaxDynamicSharedMemorySize, C_SMEM);
        cudaFuncSetAttribute(gram_mma_kernel,
                             cudaFuncAttributeMaxDynamicSharedMemorySize, SMEM_AUX);
        cudaFuncSetAttribute(qrow_mma_kernel,
                             cudaFuncAttributeMaxDynamicSharedMemorySize, SMEM_AUX);
    }

    convert_kernel<<<1024, 256>>>(B, bh_ptr);
    convertA_kernel<<<dim3(HW / 32, CH / 32, BATCH), 256>>>(A);
    gram_mma_kernel<<<dim3(2, 2, BATCH * GSLICES), 256, SMEM_AUX>>>();
    greduce_kernel<<<1024, 256>>>();
    qrow_mma_kernel<<<dim3(2, HW / 128, BATCH), 256, SMEM_AUX>>>(B);
    corr_mma_kernel<<<dim3(HW / 256, HW / 128, BATCH), 256, C_SMEM>>>(out);
}

// round 9
// speedup vs baseline: 3.1021x; 1.0142x over previous
#include <cuda_runtime.h>
#include <cuda_fp16.h>
#include <cstdint>

#define BATCH 8
#define HW    2304        // 48*48
#define CH    256
#define K2    512         // scratch layout: [hi(256) | lo(256)]
#define GSLICES 6
#define GK     (HW / GSLICES)   // 384

// ---------------- scratch (device globals: allocation-free rule) -----------
__device__ float g_Gpart[GSLICES][BATCH][CH][CH];   // 12 MB
__device__ float g_Qpart[BATCH][2][HW];             // 147 KB
__device__ __half g_Ah[(size_t)BATCH * HW * K2];    // 18.9 MB
__device__ __half g_Bh[(size_t)BATCH * HW * K2];    // 18.9 MB
__device__ __half g_AhT[(size_t)BATCH * K2 * HW];   // 18.9 MB  [c(hi|lo)][m]
__device__ __half g_Gh[(size_t)BATCH * K2 * CH];    // 2 MB     [c(hi|lo)][c2]

__device__ __forceinline__ uint32_t smem_u32(const void* p) {
    return (uint32_t)__cvta_generic_to_shared((void*)p);
}
__device__ __forceinline__ uint32_t sw128(uint32_t off) {
    return off ^ ((off >> 3) & 0x70);
}

__device__ __forceinline__ void ldsm_x4(uint32_t* r, uint32_t addr) {
    asm volatile("ldmatrix.sync.aligned.m8n8.x4.shared.b16 {%0,%1,%2,%3}, [%4];"
                 : "=r"(r[0]), "=r"(r[1]), "=r"(r[2]), "=r"(r[3]) : "r"(addr));
}
__device__ __forceinline__ void mma16816(float* c, const uint32_t* a,
                                         uint32_t b0, uint32_t b1) {
    asm volatile("mma.sync.aligned.m16n8k16.row.col.f32.f16.f16.f32 "
                 "{%0,%1,%2,%3}, {%4,%5,%6,%7}, {%8,%9}, {%0,%1,%2,%3};"
                 : "+f"(c[0]), "+f"(c[1]), "+f"(c[2]), "+f"(c[3])
                 : "r"(a[0]), "r"(a[1]), "r"(a[2]), "r"(a[3]), "r"(b0), "r"(b1));
}
__device__ __forceinline__ void cp_async16(uint32_t dst, const void* src) {
    asm volatile("cp.async.cg.shared.global [%0], [%1], 16;" :: "r"(dst), "l"(src));
}
__device__ __forceinline__ void cp_commit() {
    asm volatile("cp.async.commit_group;" ::: "memory");
}
template <int N> __device__ __forceinline__ void cp_wait() {
    asm volatile("cp.async.wait_group %0;" :: "n"(N) : "memory");
}

// ---- shared 128x128-tile GEMM pieces (8 warps, 4x2) -----------------------
#define CHUNK_BYTES 16384
#define BUF_BYTES   (2 * CHUNK_BYTES)
#define NSTAGE      3
#define SMEM_AUX    (NSTAGE * BUF_BYTES)    // 98304

__device__ __forceinline__ void mma_chunk(uint32_t aBase, uint32_t bBase,
                                          int wm, int wn, int lane,
                                          float acc[2][8][4])
{
    const int i8 = lane & 7;
    const int g  = lane >> 3;
    #pragma unroll
    for (int ks = 0; ks < 4; ++ks) {
        const int kb = ks * 32;
        uint32_t afr[2][4];
        #pragma unroll
        for (int mi = 0; mi < 2; ++mi) {
            int row = wm + mi * 16 + i8 + (g & 1) * 8;
            int col = kb + (g >> 1) * 16;
            ldsm_x4(afr[mi], aBase + sw128((uint32_t)(row * 128 + col)));
        }
        uint32_t bfr[4][4];
        #pragma unroll
        for (int p = 0; p < 4; ++p) {
            int row = wn + p * 16 + i8 + (g >> 1) * 8;
            int col = kb + (g & 1) * 16;
            ldsm_x4(bfr[p], bBase + sw128((uint32_t)(row * 128 + col)));
        }
        #pragma unroll
        for (int mi = 0; mi < 2; ++mi)
            #pragma unroll
            for (int nj = 0; nj < 8; ++nj)
                mma16816(acc[mi][nj], afr[mi],
                         bfr[nj >> 1][(nj & 1) * 2],
                         bfr[nj >> 1][(nj & 1) * 2 + 1]);
    }
}

// ---------------------------------------------------------------------------
// convert (B): fp32 -> fp16 split [hi | lo]
// ---------------------------------------------------------------------------
__global__ __launch_bounds__(256) void convert_kernel(const float* __restrict__ X,
                                                      __half* __restrict__ Y)
{
    const size_t total4 = (size_t)BATCH * HW * CH / 4;
    for (size_t i = (size_t)blockIdx.x * blockDim.x + threadIdx.x; i < total4;
         i += (size_t)gridDim.x * blockDim.x) {
        float4 v = ((const float4*)X)[i];
        size_t row = i >> 6;
        int c = (int)(i & 63) * 4;
        float vv[4] = {v.x, v.y, v.z, v.w};
        __half hi[4], lo[4];
        #pragma unroll
        for (int j = 0; j < 4; ++j) {
            hi[j] = __float2half(vv[j]);
            lo[j] = __float2half(vv[j] - __half2float(hi[j]));
        }
        __half2* ph = (__half2*)&Y[row * K2 + c];
        __half2* pl = (__half2*)&Y[row * K2 + CH + c];
        ph[0] = __half2{hi[0], hi[1]};
        ph[1] = __half2{hi[2], hi[3]};
        pl[0] = __half2{lo[0], lo[1]};
        pl[1] = __half2{lo[2], lo[3]};
    }
}

// ---------------------------------------------------------------------------
// fused A pass: read A once -> g_Ah (row-major split) + g_AhT (transposed)
// ---------------------------------------------------------------------------
__global__ __launch_bounds__(256) void convertA_kernel(const float* __restrict__ X)
{
    __shared__ float T[32][33];
    const int b  = blockIdx.z;
    const int m0 = blockIdx.x * 32;
    const int c0 = blockIdx.y * 32;
    const int tx = threadIdx.x & 31;
    const int ty = threadIdx.x >> 5;

    __half* Ar = g_Ah + (size_t)b * HW * K2;
    #pragma unroll
    for (int k = 0; k < 4; ++k) {
        int row = ty + k * 8;
        float v = X[((size_t)b * HW + m0 + row) * CH + c0 + tx];
        T[row][tx] = v;
        __half hi = __float2half(v);
        __half lo = __float2half(v - __half2float(hi));
        Ar[(size_t)(m0 + row) * K2 + c0 + tx]      = hi;
        Ar[(size_t)(m0 + row) * K2 + CH + c0 + tx] = lo;
    }
    __syncthreads();

    __half* At = g_AhT + (size_t)b * K2 * HW;
    #pragma unroll
    for (int k = 0; k < 4; ++k) {
        int c = ty + k * 8;
        float v = T[tx][c];
        __half hi = __float2half(v);
        __half lo = __float2half(v - __half2float(hi));
        At[(size_t)(c0 + c) * HW + m0 + tx]      = hi;
        At[(size_t)(c0 + c + CH) * HW + m0 + tx] = lo;
    }
}

// ---------------------------------------------------------------------------
// gram_mma: G_part[slice][b], 3-term fp16 over m slice (18 chunk iters)
// ---------------------------------------------------------------------------
__global__ __launch_bounds__(256, 2) void gram_mma_kernel()
{
    extern __shared__ char smem[];
    const uint32_t smem_base = smem_u32(smem);
    const int tid  = threadIdx.x;
    const int wid  = tid >> 5;
    const int lane = tid & 31;

    const int b     = blockIdx.z / GSLICES;
    const int slice = blockIdx.z % GSLICES;
    const int c1_0  = blockIdx.y * 128;
    const int c2_0  = blockIdx.x * 128;

    const __half* At = g_AhT + (size_t)b * K2 * HW;

    uint32_t dstoff[8];
    const __half* srcp[8];
    bool isA[8];
    #pragma unroll
    for (int it = 0; it < 8; ++it) {
        int idx = it * 256 + tid;
        int li  = idx & 1023;
        int row = li >> 3;
        int seg = li & 7;
        isA[it] = (idx < 1024);
        dstoff[it] = (isA[it] ? 0u : (uint32_t)CHUNK_BYTES)
                   + sw128((uint32_t)(row * 128 + seg * 16));
        srcp[it] = At + (size_t)((isA[it] ? c1_0 : c2_0) + row) * HW + seg * 8;
    }

    const int NIT = 18;   // 3 terms x 6 chunks of 64 within GK=384
    auto load_chunk = [&](int it, int buf) {
        const int term = it / 6, kc = it - term * 6;
        const size_t aoff = (size_t)(term == 1 ? CH : 0) * HW + slice * GK + kc * 64;
        const size_t boff = (size_t)(term == 2 ? CH : 0) * HW + slice * GK + kc * 64;
        const uint32_t base = smem_base + buf * BUF_BYTES;
        #pragma unroll
        for (int s = 0; s < 8; ++s)
            cp_async16(base + dstoff[s], srcp[s] + (isA[s] ? aoff : boff));
        cp_commit();
    };

    const int wm = (wid & 3) * 32;
    const int wn = (wid >> 2) * 64;
    float acc[2][8][4] = {};

    load_chunk(0, 0);
    load_chunk(1, 1);
    for (int c = 0; c < NIT; ++c) {
        if (c < NIT - 1) cp_wait<1>(); else cp_wait<0>();
        __syncthreads();
        const uint32_t aBase = smem_base + (c % NSTAGE) * BUF_BYTES;
        mma_chunk(aBase, aBase + CHUNK_BYTES, wm, wn, lane, acc);
        if (c + 2 < NIT) load_chunk(c + 2, (c + 2) % NSTAGE);
    }

    const int r    = lane >> 2;
    const int cpos = (lane & 3) * 2;
    #pragma unroll
    for (int mi = 0; mi < 2; ++mi) {
        const int row = c1_0 + wm + mi * 16 + r;
        float* o0 = &g_Gpart[slice][b][row][c2_0 + wn];
        float* o1 = o0 + 8 * CH;
        #pragma unroll
        for (int nj = 0; nj < 8; ++nj) {
            *(float2*)&o0[nj * 8 + cpos] = make_float2(acc[mi][nj][0], acc[mi][nj][1]);
            *(float2*)&o1[nj * 8 + cpos] = make_float2(acc[mi][nj][2], acc[mi][nj][3]);
        }
    }
}

// ---------------------------------------------------------------------------
// greduce: G = sum partials, write fp16 hi/lo split directly
// ---------------------------------------------------------------------------
__global__ __launch_bounds__(256) void greduce_kernel()
{
    const int total = BATCH * CH * CH;
    const float* p = &g_Gpart[0][0][0][0];
    for (int i = blockIdx.x * blockDim.x + threadIdx.x; i < total;
         i += gridDim.x * blockDim.x) {
        float s = 0.f;
        #pragma unroll
        for (int k = 0; k < GSLICES; ++k) s += p[k * total + i];
        int b  = i / (CH * CH);
        int li = i - b * CH * CH;
        int c  = li >> 8;
        int c2 = li & 255;
        __half hi = __float2half(s);
        __half lo = __float2half(s - __half2float(hi));
        g_Gh[((size_t)b * K2 + c) * CH + c2]      = hi;
        g_Gh[((size_t)b * K2 + CH + c) * CH + c2] = lo;
    }
}

// ---------------------------------------------------------------------------
// qrow_mma: V = U G (3-term fp16), fused epilogue q_part = rowsum(V .* U_fp32)
// ---------------------------------------------------------------------------
__global__ __launch_bounds__(256, 2) void qrow_mma_kernel(const float* __restrict__ Bin)
{
    extern __shared__ char smem[];
    const uint32_t smem_base = smem_u32(smem);
    const int tid  = threadIdx.x;
    const int wid  = tid >> 5;
    const int lane = tid & 31;

    const int ctile = blockIdx.x;
    const int n0    = blockIdx.y * 128;
    const int b     = blockIdx.z;

    const __half* Ub = g_Bh + ((size_t)b * HW + n0) * K2;
    const __half* Gb = g_Gh + (size_t)b * K2 * CH + (size_t)ctile * 128 * CH;

    uint32_t dstoff[8];
    const __half* srcp[8];
    bool isA[8];
    #pragma unroll
    for (int it = 0; it < 8; ++it) {
        int idx = it * 256 + tid;
        int li  = idx & 1023;
        int row = li >> 3;
        int seg = li & 7;
        isA[it] = (idx < 1024);
        dstoff[it] = (isA[it] ? 0u : (uint32_t)CHUNK_BYTES)
                   + sw128((uint32_t)(row * 128 + seg * 16));
        srcp[it] = (isA[it] ? Ub + (size_t)row * K2 : Gb + (size_t)row * CH) + seg * 8;
    }

    const int NIT = 12;
    auto load_chunk = [&](int it, int buf) {
        const int term = it >> 2, kc = it & 3;
        const size_t uoff = (size_t)(term == 1 ? CH : 0) + kc * 64;
        const size_t goff = (size_t)(term == 2 ? CH : 0) * CH + kc * 64;
        const uint32_t base = smem_base + buf * BUF_BYTES;
        #pragma unroll
        for (int s = 0; s < 8; ++s)
            cp_async16(base + dstoff[s], srcp[s] + (isA[s] ? uoff : goff));
        cp_commit();
    };

    const int wm = (wid & 3) * 32;
    const int wn = (wid >> 2) * 64;
    float acc[2][8][4] = {};

    load_chunk(0, 0);
    load_chunk(1, 1);
    for (int c = 0; c < NIT; ++c) {
        if (c < NIT - 1) cp_wait<1>(); else cp_wait<0>();
        __syncthreads();
        const uint32_t aBase = smem_base + (c % NSTAGE) * BUF_BYTES;
        mma_chunk(aBase, aBase + CHUNK_BYTES, wm, wn, lane, acc);
        if (c + 2 < NIT) load_chunk(c + 2, (c + 2) % NSTAGE);
    }
    __syncthreads();

    float* qs = (float*)smem;
    const int r    = lane >> 2;
    const int cpos = (lane & 3) * 2;

    float rs[2][2] = {};
    #pragma unroll
    for (int mi = 0; mi < 2; ++mi) {
        const size_t row0 = (size_t)b * HW + n0 + wm + mi * 16 + r;
        #pragma unroll
        for (int nj = 0; nj < 8; ++nj) {
            const int cc = ctile * 128 + wn + nj * 8 + cpos;
            float2 u0 = *(const float2*)&Bin[row0 * CH + cc];
            float2 u1 = *(const float2*)&Bin[(row0 + 8) * CH + cc];
            rs[mi][0] += acc[mi][nj][0] * u0.x + acc[mi][nj][1] * u0.y;
            rs[mi][1] += acc[mi][nj][2] * u1.x + acc[mi][nj][3] * u1.y;
        }
    }
    #pragma unroll
    for (int mi = 0; mi < 2; ++mi)
        #pragma unroll
        for (int h = 0; h < 2; ++h) {
            float v = rs[mi][h];
            v += __shfl_xor_sync(0xffffffffu, v, 1);
            v += __shfl_xor_sync(0xffffffffu, v, 2);
            rs[mi][h] = v;
        }
    if ((lane & 3) == 0) {
        #pragma unroll
        for (int mi = 0; mi < 2; ++mi)
            #pragma unroll
            for (int h = 0; h < 2; ++h)
                qs[(wid >> 2) * 128 + wm + mi * 16 + r + h * 8] = rs[mi][h];
    }
    __syncthreads();
    if (tid < 128)
        g_Qpart[b][ctile][n0 + tid] = qs[tid] + qs[128 + tid];
}

// ---------------------------------------------------------------------------
// corr_mma: 128x128 CTA tile, 8 warps (4x2), occ 2, 3-stage pipeline.
// 2-term fp16 split: 8 K-chunks — A {hi,lo}, B {hi,hi}. Fused rsqrt-scale.
// ---------------------------------------------------------------------------
#define NCHUNK 8
__global__ __launch_bounds__(256, 2) void corr_mma_kernel(float* __restrict__ out)
{
    extern __shared__ char smem[];
    const uint32_t smem_base = smem_u32(smem);
    const int tid  = threadIdx.x;
    const int wid  = tid >> 5;
    const int lane = tid & 31;

    const int b  = blockIdx.z;
    const int m0 = blockIdx.y * 128;
    const int n0 = blockIdx.x * 128;

    const __half* Ab = g_Ah + ((size_t)b * HW + m0) * K2;
    const __half* Bb = g_Bh + ((size_t)b * HW + n0) * K2;

    // A: hi then lo; B: hi twice (2-term split, Ahi*Blo dropped)
    const int a_k0[NCHUNK] = {0,64,128,192, 256,320,384,448};
    const int b_k0[NCHUNK] = {0,64,128,192, 0,64,128,192};

    uint32_t dstoff[8];
    const __half* srcp[8];
    bool isA[8];
    #pragma unroll
    for (int it = 0; it < 8; ++it) {
        int idx = it * 256 + tid;
        int li  = idx & 1023;
        int row = li >> 3;
        int seg = li & 7;
        isA[it] = (idx < 1024);
        dstoff[it] = (isA[it] ? 0u : (uint32_t)CHUNK_BYTES)
                   + sw128((uint32_t)(row * 128 + seg * 16));
        srcp[it] = (isA[it] ? Ab : Bb) + (size_t)row * K2 + seg * 8;
    }

    auto load_chunk = [&](int c, int buf) {
        const uint32_t base = smem_base + buf * BUF_BYTES;
        const int ao = a_k0[c], bo = b_k0[c];
        #pragma unroll
        for (int it = 0; it < 8; ++it)
            cp_async16(base + dstoff[it], srcp[it] + (isA[it] ? ao : bo));
        cp_commit();
    };

    const int wm = (wid & 3) * 32;
    const int wn = (wid >> 2) * 64;
    float acc[2][8][4] = {};

    load_chunk(0, 0);
    load_chunk(1, 1);
    for (int c = 0; c < NCHUNK; ++c) {
        if (c < NCHUNK - 1) cp_wait<1>(); else cp_wait<0>();
        __syncthreads();
        const uint32_t aBase = smem_base + (c % NSTAGE) * BUF_BYTES;
        mma_chunk(aBase, aBase + CHUNK_BYTES, wm, wn, lane, acc);
        if (c + 2 < NCHUNK) load_chunk(c + 2, (c + 2) % NSTAGE);
    }
    __syncthreads();

    // fused scale: s = rsqrt(qp0+qp1), staged in smem
    float* sSc = (float*)smem;
    if (tid < 128)
        sSc[tid] = rsqrtf(g_Qpart[b][0][n0 + tid] + g_Qpart[b][1][n0 + tid]);
    __syncthreads();

    const int r    = lane >> 2;
    const int cpos = (lane & 3) * 2;
    #pragma unroll
    for (int mi = 0; mi < 2; ++mi) {
        const int mrow = m0 + wm + mi * 16 + r;
        float* o0 = out + ((size_t)b * HW + mrow) * HW + n0 + wn;
        float* o1 = o0 + (size_t)8 * HW;
        #pragma unroll
        for (int nj = 0; nj < 8; ++nj) {
            const int nc = wn + nj * 8 + cpos;
            const float s0 = sSc[nc], s1 = sSc[nc + 1];
            float2 v0 = make_float2(acc[mi][nj][0] * s0, acc[mi][nj][1] * s1);
            float2 v1 = make_float2(acc[mi][nj][2] * s0, acc[mi][nj][3] * s1);
            *(float2*)&o0[nj * 8 + cpos] = v0;
            *(float2*)&o1[nj * 8 + cpos] = v1;
        }
    }
}

// ---------------------------------------------------------------------------
extern "C" void kernel_launch(void* const* d_in, const int* in_sizes, int n_in,
                              void* d_out, int out_size)
{
    const float* A = (const float*)d_in[0];
    const float* B = (const float*)d_in[1];
    float* out = (float*)d_out;

    static __half* bh_ptr = nullptr;
    if (!bh_ptr) {
        cudaGetSymbolAddress((void**)&bh_ptr, g_Bh);
        cudaFuncSetAttribute(corr_mma_kernel,
                             cudaFuncAttributeMaxDynamicSharedMemorySize, SMEM_AUX);
        cudaFuncSetAttribute(gram_mma_kernel,
                             cudaFuncAttributeMaxDynamicSharedMemorySize, SMEM_AUX);
        cudaFuncSetAttribute(qrow_mma_kernel,
                             cudaFuncAttributeMaxDynamicSharedMemorySize, SMEM_AUX);
    }

    convert_kernel<<<1024, 256>>>(B, bh_ptr);
    convertA_kernel<<<dim3(HW / 32, CH / 32, BATCH), 256>>>(A);
    gram_mma_kernel<<<dim3(2, 2, BATCH * GSLICES), 256, SMEM_AUX>>>();
    greduce_kernel<<<1024, 256>>>();
    qrow_mma_kernel<<<dim3(2, HW / 128, BATCH), 256, SMEM_AUX>>>(B);
    corr_mma_kernel<<<dim3(HW / 128, HW / 128, BATCH), 256, SMEM_AUX>>>(out);
}

// round 11
// speedup vs baseline: 3.4452x; 1.1106x over previous
#include <cuda_runtime.h>
#include <cuda_fp16.h>
#include <cstdint>

#define BATCH 8
#define HW    2304        // 48*48
#define CH    256
#define K2    512         // scratch layout: [hi(256) | lo(256)]
#define GSLICES 6
#define GK     (HW / GSLICES)   // 384

// ---------------- scratch (device globals: allocation-free rule) -----------
__device__ float g_Gpart[GSLICES][BATCH][CH][CH];   // 12 MB (tile (1,0) unused)
__device__ float g_Qpart[BATCH][2][HW];             // 147 KB
__device__ __half g_Ah[(size_t)BATCH * HW * K2];    // 18.9 MB
__device__ __half g_Bh[(size_t)BATCH * HW * K2];    // 18.9 MB
__device__ __half g_AhT[(size_t)BATCH * K2 * HW];   // 18.9 MB  [c(hi|lo)][m]
__device__ __half g_Gh[(size_t)BATCH * K2 * CH];    // 2 MB     [c(hi|lo)][c2]

__device__ __forceinline__ uint32_t smem_u32(const void* p) {
    return (uint32_t)__cvta_generic_to_shared((void*)p);
}
__device__ __forceinline__ uint32_t sw128(uint32_t off) {
    return off ^ ((off >> 3) & 0x70);
}

__device__ __forceinline__ void ldsm_x4(uint32_t* r, uint32_t addr) {
    asm volatile("ldmatrix.sync.aligned.m8n8.x4.shared.b16 {%0,%1,%2,%3}, [%4];"
                 : "=r"(r[0]), "=r"(r[1]), "=r"(r[2]), "=r"(r[3]) : "r"(addr));
}
__device__ __forceinline__ void mma16816(float* c, const uint32_t* a,
                                         uint32_t b0, uint32_t b1) {
    asm volatile("mma.sync.aligned.m16n8k16.row.col.f32.f16.f16.f32 "
                 "{%0,%1,%2,%3}, {%4,%5,%6,%7}, {%8,%9}, {%0,%1,%2,%3};"
                 : "+f"(c[0]), "+f"(c[1]), "+f"(c[2]), "+f"(c[3])
                 : "r"(a[0]), "r"(a[1]), "r"(a[2]), "r"(a[3]), "r"(b0), "r"(b1));
}
__device__ __forceinline__ void cp_async16(uint32_t dst, const void* src) {
    asm volatile("cp.async.cg.shared.global [%0], [%1], 16;" :: "r"(dst), "l"(src));
}
__device__ __forceinline__ void cp_commit() {
    asm volatile("cp.async.commit_group;" ::: "memory");
}
template <int N> __device__ __forceinline__ void cp_wait() {
    asm volatile("cp.async.wait_group %0;" :: "n"(N) : "memory");
}

// ---- shared 128x128-tile GEMM pieces (8 warps, 4x2) -----------------------
#define CHUNK_BYTES 16384
#define BUF_BYTES   (2 * CHUNK_BYTES)
#define NSTAGE      3
#define SMEM_AUX    (NSTAGE * BUF_BYTES)    // 98304

__device__ __forceinline__ void mma_chunk(uint32_t aBase, uint32_t bBase,
                                          int wm, int wn, int lane,
                                          float acc[2][8][4])
{
    const int i8 = lane & 7;
    const int g  = lane >> 3;
    #pragma unroll
    for (int ks = 0; ks < 4; ++ks) {
        const int kb = ks * 32;
        uint32_t afr[2][4];
        #pragma unroll
        for (int mi = 0; mi < 2; ++mi) {
            int row = wm + mi * 16 + i8 + (g & 1) * 8;
            int col = kb + (g >> 1) * 16;
            ldsm_x4(afr[mi], aBase + sw128((uint32_t)(row * 128 + col)));
        }
        uint32_t bfr[4][4];
        #pragma unroll
        for (int p = 0; p < 4; ++p) {
            int row = wn + p * 16 + i8 + (g >> 1) * 8;
            int col = kb + (g & 1) * 16;
            ldsm_x4(bfr[p], bBase + sw128((uint32_t)(row * 128 + col)));
        }
        #pragma unroll
        for (int mi = 0; mi < 2; ++mi)
            #pragma unroll
            for (int nj = 0; nj < 8; ++nj)
                mma16816(acc[mi][nj], afr[mi],
                         bfr[nj >> 1][(nj & 1) * 2],
                         bfr[nj >> 1][(nj & 1) * 2 + 1]);
    }
}

// ---------------------------------------------------------------------------
// convertAB: one pass. B: fp32 -> fp16 [hi|lo] row-major.
//            A: fp32 -> fp16 [hi|lo] row-major AND channel-transposed.
// ---------------------------------------------------------------------------
__global__ __launch_bounds__(256) void convertAB_kernel(const float* __restrict__ Ax,
                                                        const float* __restrict__ Bx)
{
    __shared__ float T[32][33];
    const int b  = blockIdx.z;
    const int m0 = blockIdx.x * 32;
    const int c0 = blockIdx.y * 32;
    const int tx = threadIdx.x & 31;
    const int ty = threadIdx.x >> 5;

    // ---- B: straight split convert ----
    __half* Br = g_Bh + (size_t)b * HW * K2;
    #pragma unroll
    for (int k = 0; k < 4; ++k) {
        int row = ty + k * 8;
        float v = Bx[((size_t)b * HW + m0 + row) * CH + c0 + tx];
        __half hi = __float2half(v);
        __half lo = __float2half(v - __half2float(hi));
        Br[(size_t)(m0 + row) * K2 + c0 + tx]      = hi;
        Br[(size_t)(m0 + row) * K2 + CH + c0 + tx] = lo;
    }

    // ---- A: split convert + transpose ----
    __half* Ar = g_Ah + (size_t)b * HW * K2;
    #pragma unroll
    for (int k = 0; k < 4; ++k) {
        int row = ty + k * 8;
        float v = Ax[((size_t)b * HW + m0 + row) * CH + c0 + tx];
        T[row][tx] = v;
        __half hi = __float2half(v);
        __half lo = __float2half(v - __half2float(hi));
        Ar[(size_t)(m0 + row) * K2 + c0 + tx]      = hi;
        Ar[(size_t)(m0 + row) * K2 + CH + c0 + tx] = lo;
    }
    __syncthreads();

    __half* At = g_AhT + (size_t)b * K2 * HW;
    #pragma unroll
    for (int k = 0; k < 4; ++k) {
        int c = ty + k * 8;
        float v = T[tx][c];
        __half hi = __float2half(v);
        __half lo = __float2half(v - __half2float(hi));
        At[(size_t)(c0 + c) * HW + m0 + tx]      = hi;
        At[(size_t)(c0 + c + CH) * HW + m0 + tx] = lo;
    }
}

// ---------------------------------------------------------------------------
// gram_mma: symmetric — only tiles (0,0),(1,1),(0,1) of the 2x2 tile grid.
// 3-term fp16 over m slice (18 chunk iters).
// ---------------------------------------------------------------------------
__global__ __launch_bounds__(256, 2) void gram_mma_kernel()
{
    extern __shared__ char smem[];
    const uint32_t smem_base = smem_u32(smem);
    const int tid  = threadIdx.x;
    const int wid  = tid >> 5;
    const int lane = tid & 31;

    const int b     = blockIdx.z / GSLICES;
    const int slice = blockIdx.z % GSLICES;
    const int t     = blockIdx.x;                 // 0:(0,0) 1:(128,128) 2:(0,128)
    const int c1_0  = (t == 1) ? 128 : 0;
    const int c2_0  = (t == 0) ? 0 : 128;

    const __half* At = g_AhT + (size_t)b * K2 * HW;

    uint32_t dstoff[8];
    const __half* srcp[8];
    bool isA[8];
    #pragma unroll
    for (int it = 0; it < 8; ++it) {
        int idx = it * 256 + tid;
        int li  = idx & 1023;
        int row = li >> 3;
        int seg = li & 7;
        isA[it] = (idx < 1024);
        dstoff[it] = (isA[it] ? 0u : (uint32_t)CHUNK_BYTES)
                   + sw128((uint32_t)(row * 128 + seg * 16));
        srcp[it] = At + (size_t)((isA[it] ? c1_0 : c2_0) + row) * HW + seg * 8;
    }

    const int NIT = 18;   // 3 terms x 6 chunks of 64 within GK=384
    auto load_chunk = [&](int it, int buf) {
        const int term = it / 6, kc = it - term * 6;
        const size_t aoff = (size_t)(term == 1 ? CH : 0) * HW + slice * GK + kc * 64;
        const size_t boff = (size_t)(term == 2 ? CH : 0) * HW + slice * GK + kc * 64;
        const uint32_t base = smem_base + buf * BUF_BYTES;
        #pragma unroll
        for (int s = 0; s < 8; ++s)
            cp_async16(base + dstoff[s], srcp[s] + (isA[s] ? aoff : boff));
        cp_commit();
    };

    const int wm = (wid & 3) * 32;
    const int wn = (wid >> 2) * 64;
    float acc[2][8][4] = {};

    load_chunk(0, 0);
    load_chunk(1, 1);
    for (int c = 0; c < NIT; ++c) {
        if (c < NIT - 1) cp_wait<1>(); else cp_wait<0>();
        __syncthreads();
        const uint32_t aBase = smem_base + (c % NSTAGE) * BUF_BYTES;
        mma_chunk(aBase, aBase + CHUNK_BYTES, wm, wn, lane, acc);
        if (c + 2 < NIT) load_chunk(c + 2, (c + 2) % NSTAGE);
    }

    const int r    = lane >> 2;
    const int cpos = (lane & 3) * 2;
    #pragma unroll
    for (int mi = 0; mi < 2; ++mi) {
        const int row = c1_0 + wm + mi * 16 + r;
        float* o0 = &g_Gpart[slice][b][row][c2_0 + wn];
        float* o1 = o0 + 8 * CH;
        #pragma unroll
        for (int nj = 0; nj < 8; ++nj) {
            *(float2*)&o0[nj * 8 + cpos] = make_float2(acc[mi][nj][0], acc[mi][nj][1]);
            *(float2*)&o1[nj * 8 + cpos] = make_float2(acc[mi][nj][2], acc[mi][nj][3]);
        }
    }
}

// ---------------------------------------------------------------------------
// greduce: sum partial slices over computed tiles, write fp16 hi/lo split;
// mirror the off-diagonal tile (G symmetric).
// ---------------------------------------------------------------------------
__global__ __launch_bounds__(256) void greduce_kernel()
{
    const int per_b = 3 * 128 * 128;          // 3 computed tiles
    const int total = BATCH * per_b;
    const int full  = BATCH * CH * CH;
    const float* p = &g_Gpart[0][0][0][0];
    for (int i = blockIdx.x * blockDim.x + threadIdx.x; i < total;
         i += gridDim.x * blockDim.x) {
        int b   = i / per_b;
        int rem = i - b * per_b;
        int t   = rem >> 14;                  // tile 0,1,2
        int r   = (rem >> 7) & 127;
        int cc  = rem & 127;
        int c   = ((t == 1) ? 128 : 0) + r;
        int c2  = ((t == 0) ? 0 : 128) + cc;

        size_t off = (size_t)b * CH * CH + (size_t)c * CH + c2;
        float s = 0.f;
        #pragma unroll
        for (int k = 0; k < GSLICES; ++k) s += p[(size_t)k * full + off];

        __half hi = __float2half(s);
        __half lo = __float2half(s - __half2float(hi));
        g_Gh[((size_t)b * K2 + c) * CH + c2]      = hi;
        g_Gh[((size_t)b * K2 + CH + c) * CH + c2] = lo;
        if (t == 2) {   // mirror into tile (1,0)
            g_Gh[((size_t)b * K2 + c2) * CH + c]      = hi;
            g_Gh[((size_t)b * K2 + CH + c2) * CH + c] = lo;
        }
    }
}

// ---------------------------------------------------------------------------
// qrow_mma: V = U G (2-term fp16: Uhi*Ghi + Ulo*Ghi; U*Glo dropped, ~1e-4 on q),
// fused epilogue q_part = rowsum(V .* U_fp32)
// ---------------------------------------------------------------------------
__global__ __launch_bounds__(256, 2) void qrow_mma_kernel(const float* __restrict__ Bin)
{
    extern __shared__ char smem[];
    const uint32_t smem_base = smem_u32(smem);
    const int tid  = threadIdx.x;
    const int wid  = tid >> 5;
    const int lane = tid & 31;

    const int ctile = blockIdx.x;
    const int n0    = blockIdx.y * 128;
    const int b     = blockIdx.z;

    const __half* Ub = g_Bh + ((size_t)b * HW + n0) * K2;
    const __half* Gb = g_Gh + (size_t)b * K2 * CH + (size_t)ctile * 128 * CH;

    uint32_t dstoff[8];
    const __half* srcp[8];
    bool isA[8];
    #pragma unroll
    for (int it = 0; it < 8; ++it) {
        int idx = it * 256 + tid;
        int li  = idx & 1023;
        int row = li >> 3;
        int seg = li & 7;
        isA[it] = (idx < 1024);
        dstoff[it] = (isA[it] ? 0u : (uint32_t)CHUNK_BYTES)
                   + sw128((uint32_t)(row * 128 + seg * 16));
        srcp[it] = (isA[it] ? Ub + (size_t)row * K2 : Gb + (size_t)row * CH) + seg * 8;
    }

    const int NIT = 8;   // 2 terms x 4 chunks
    auto load_chunk = [&](int it, int buf) {
        const int term = it >> 2, kc = it & 3;
        const size_t uoff = (size_t)(term == 1 ? CH : 0) + kc * 64;
        const size_t goff = (size_t)kc * 64;          // always G-hi
        const uint32_t base = smem_base + buf * BUF_BYTES;
        #pragma unroll
        for (int s = 0; s < 8; ++s)
            cp_async16(base + dstoff[s], srcp[s] + (isA[s] ? uoff : goff));
        cp_commit();
    };

    const int wm = (wid & 3) * 32;
    const int wn = (wid >> 2) * 64;
    float acc[2][8][4] = {};

    load_chunk(0, 0);
    load_chunk(1, 1);
    for (int c = 0; c < NIT; ++c) {
        if (c < NIT - 1) cp_wait<1>(); else cp_wait<0>();
        __syncthreads();
        const uint32_t aBase = smem_base + (c % NSTAGE) * BUF_BYTES;
        mma_chunk(aBase, aBase + CHUNK_BYTES, wm, wn, lane, acc);
        if (c + 2 < NIT) load_chunk(c + 2, (c + 2) % NSTAGE);
    }
    __syncthreads();

    float* qs = (float*)smem;
    const int r    = lane >> 2;
    const int cpos = (lane & 3) * 2;

    float rs[2][2] = {};
    #pragma unroll
    for (int mi = 0; mi < 2; ++mi) {
        const size_t row0 = (size_t)b * HW + n0 + wm + mi * 16 + r;
        #pragma unroll
        for (int nj = 0; nj < 8; ++nj) {
            const int cc = ctile * 128 + wn + nj * 8 + cpos;
            float2 u0 = *(const float2*)&Bin[row0 * CH + cc];
            float2 u1 = *(const float2*)&Bin[(row0 + 8) * CH + cc];
            rs[mi][0] += acc[mi][nj][0] * u0.x + acc[mi][nj][1] * u0.y;
            rs[mi][1] += acc[mi][nj][2] * u1.x + acc[mi][nj][3] * u1.y;
        }
    }
    #pragma unroll
    for (int mi = 0; mi < 2; ++mi)
        #pragma unroll
        for (int h = 0; h < 2; ++h) {
            float v = rs[mi][h];
            v += __shfl_xor_sync(0xffffffffu, v, 1);
            v += __shfl_xor_sync(0xffffffffu, v, 2);
            rs[mi][h] = v;
        }
    if ((lane & 3) == 0) {
        #pragma unroll
        for (int mi = 0; mi < 2; ++mi)
            #pragma unroll
            for (int h = 0; h < 2; ++h)
                qs[(wid >> 2) * 128 + wm + mi * 16 + r + h * 8] = rs[mi][h];
    }
    __syncthreads();
    if (tid < 128)
        g_Qpart[b][ctile][n0 + tid] = qs[tid] + qs[128 + tid];
}

// ---------------------------------------------------------------------------
// corr_mma: 128x128 CTA tile, 8 warps (4x2), 3-stage pipeline.
// 2-term fp16 split: 8 K-chunks — A {hi,lo}, B {hi,hi}. Fused rsqrt-scale.
// ---------------------------------------------------------------------------
#define NCHUNK 8
__global__ __launch_bounds__(256, 2) void corr_mma_kernel(float* __restrict__ out)
{
    extern __shared__ char smem[];
    const uint32_t smem_base = smem_u32(smem);
    const int tid  = threadIdx.x;
    const int wid  = tid >> 5;
    const int lane = tid & 31;

    const int b  = blockIdx.z;
    const int m0 = blockIdx.y * 128;
    const int n0 = blockIdx.x * 128;

    const __half* Ab = g_Ah + ((size_t)b * HW + m0) * K2;
    const __half* Bb = g_Bh + ((size_t)b * HW + n0) * K2;

    const int a_k0[NCHUNK] = {0,64,128,192, 256,320,384,448};
    const int b_k0[NCHUNK] = {0,64,128,192, 0,64,128,192};

    uint32_t dstoff[8];
    const __half* srcp[8];
    bool isA[8];
    #pragma unroll
    for (int it = 0; it < 8; ++it) {
        int idx = it * 256 + tid;
        int li  = idx & 1023;
        int row = li >> 3;
        int seg = li & 7;
        isA[it] = (idx < 1024);
        dstoff[it] = (isA[it] ? 0u : (uint32_t)CHUNK_BYTES)
                   + sw128((uint32_t)(row * 128 + seg * 16));
        srcp[it] = (isA[it] ? Ab : Bb) + (size_t)row * K2 + seg * 8;
    }

    auto load_chunk = [&](int c, int buf) {
        const uint32_t base = smem_base + buf * BUF_BYTES;
        const int ao = a_k0[c], bo = b_k0[c];
        #pragma unroll
        for (int it = 0; it < 8; ++it)
            cp_async16(base + dstoff[it], srcp[it] + (isA[it] ? ao : bo));
        cp_commit();
    };

    const int wm = (wid & 3) * 32;
    const int wn = (wid >> 2) * 64;
    float acc[2][8][4] = {};

    load_chunk(0, 0);
    load_chunk(1, 1);
    for (int c = 0; c < NCHUNK; ++c) {
        if (c < NCHUNK - 1) cp_wait<1>(); else cp_wait<0>();
        __syncthreads();
        const uint32_t aBase = smem_base + (c % NSTAGE) * BUF_BYTES;
        mma_chunk(aBase, aBase + CHUNK_BYTES, wm, wn, lane, acc);
        if (c + 2 < NCHUNK) load_chunk(c + 2, (c + 2) % NSTAGE);
    }
    __syncthreads();

    // fused scale: s = rsqrt(qp0+qp1), staged in smem
    float* sSc = (float*)smem;
    if (tid < 128)
        sSc[tid] = rsqrtf(g_Qpart[b][0][n0 + tid] + g_Qpart[b][1][n0 + tid]);
    __syncthreads();

    const int r    = lane >> 2;
    const int cpos = (lane & 3) * 2;
    #pragma unroll
    for (int mi = 0; mi < 2; ++mi) {
        const int mrow = m0 + wm + mi * 16 + r;
        float* o0 = out + ((size_t)b * HW + mrow) * HW + n0 + wn;
        float* o1 = o0 + (size_t)8 * HW;
        #pragma unroll
        for (int nj = 0; nj < 8; ++nj) {
            const int nc = wn + nj * 8 + cpos;
            const float s0 = sSc[nc], s1 = sSc[nc + 1];
            float2 v0 = make_float2(acc[mi][nj][0] * s0, acc[mi][nj][1] * s1);
            float2 v1 = make_float2(acc[mi][nj][2] * s0, acc[mi][nj][3] * s1);
            *(float2*)&o0[nj * 8 + cpos] = v0;
            *(float2*)&o1[nj * 8 + cpos] = v1;
        }
    }
}

// ---------------------------------------------------------------------------
extern "C" void kernel_launch(void* const* d_in, const int* in_sizes, int n_in,
                              void* d_out, int out_size)
{
    const float* A = (const float*)d_in[0];
    const float* B = (const float*)d_in[1];
    float* out = (float*)d_out;

    static bool init = false;
    if (!init) {
        init = true;
        cudaFuncSetAttribute(corr_mma_kernel,
                             cudaFuncAttributeMaxDynamicSharedMemorySize, SMEM_AUX);
        cudaFuncSetAttribute(gram_mma_kernel,
                             cudaFuncAttributeMaxDynamicSharedMemorySize, SMEM_AUX);
        cudaFuncSetAttribute(qrow_mma_kernel,
                             cudaFuncAttributeMaxDynamicSharedMemorySize, SMEM_AUX);
    }

    convertAB_kernel<<<dim3(HW / 32, CH / 32, BATCH), 256>>>(A, B);
    gram_mma_kernel<<<dim3(3, 1, BATCH * GSLICES), 256, SMEM_AUX>>>();
    greduce_kernel<<<1024, 256>>>();
    qrow_mma_kernel<<<dim3(2, HW / 128, BATCH), 256, SMEM_AUX>>>(B);
    corr_mma_kernel<<<dim3(HW / 128, HW / 128, BATCH), 256, SMEM_AUX>>>(out);
}

// round 12
// speedup vs baseline: 4.7905x; 1.3905x over previous
#include <cuda_runtime.h>
#include <cuda_fp16.h>
#include <cstdint>

#define BATCH 8
#define HW    2304        // 48*48
#define CH    256
#define K2    512         // scratch layout: [hi(256) | lo(256)]
#define GSLICES 6
#define GK     (HW / GSLICES)   // 384

// ---------------- scratch (device globals: allocation-free rule) -----------
__device__ float g_Gpart[GSLICES][BATCH][CH][CH];   // 12 MB (tile (1,0) unused)
__device__ float g_Qpart[BATCH][2][HW];             // 147 KB
__device__ __half g_Ah[(size_t)BATCH * HW * K2];    // 18.9 MB (lo half unused)
__device__ __half g_Bh[(size_t)BATCH * HW * K2];    // 18.9 MB
__device__ __half g_AhT[(size_t)BATCH * K2 * HW];   // 18.9 MB  [c(hi|lo)][m]
__device__ __half g_Gh[(size_t)BATCH * K2 * CH];    // 2 MB     [c(hi|lo)][c2]

__device__ __forceinline__ uint32_t smem_u32(const void* p) {
    return (uint32_t)__cvta_generic_to_shared((void*)p);
}
__device__ __forceinline__ uint32_t sw128(uint32_t off) {
    return off ^ ((off >> 3) & 0x70);
}

__device__ __forceinline__ void ldsm_x4(uint32_t* r, uint32_t addr) {
    asm volatile("ldmatrix.sync.aligned.m8n8.x4.shared.b16 {%0,%1,%2,%3}, [%4];"
                 : "=r"(r[0]), "=r"(r[1]), "=r"(r[2]), "=r"(r[3]) : "r"(addr));
}
__device__ __forceinline__ void mma16816(float* c, const uint32_t* a,
                                         uint32_t b0, uint32_t b1) {
    asm volatile("mma.sync.aligned.m16n8k16.row.col.f32.f16.f16.f32 "
                 "{%0,%1,%2,%3}, {%4,%5,%6,%7}, {%8,%9}, {%0,%1,%2,%3};"
                 : "+f"(c[0]), "+f"(c[1]), "+f"(c[2]), "+f"(c[3])
                 : "r"(a[0]), "r"(a[1]), "r"(a[2]), "r"(a[3]), "r"(b0), "r"(b1));
}
__device__ __forceinline__ void cp_async16(uint32_t dst, const void* src) {
    asm volatile("cp.async.cg.shared.global [%0], [%1], 16;" :: "r"(dst), "l"(src));
}
__device__ __forceinline__ void cp_commit() {
    asm volatile("cp.async.commit_group;" ::: "memory");
}
template <int N> __device__ __forceinline__ void cp_wait() {
    asm volatile("cp.async.wait_group %0;" :: "n"(N) : "memory");
}

// ---- shared 128x128-tile GEMM pieces (8 warps, 4x2) -----------------------
#define CHUNK_BYTES 16384
#define BUF_BYTES   (2 * CHUNK_BYTES)
#define NSTAGE      3
#define SMEM_AUX    (NSTAGE * BUF_BYTES)    // 98304

__device__ __forceinline__ void mma_chunk(uint32_t aBase, uint32_t bBase,
                                          int wm, int wn, int lane,
                                          float acc[2][8][4])
{
    const int i8 = lane & 7;
    const int g  = lane >> 3;
    #pragma unroll
    for (int ks = 0; ks < 4; ++ks) {
        const int kb = ks * 32;
        uint32_t afr[2][4];
        #pragma unroll
        for (int mi = 0; mi < 2; ++mi) {
            int row = wm + mi * 16 + i8 + (g & 1) * 8;
            int col = kb + (g >> 1) * 16;
            ldsm_x4(afr[mi], aBase + sw128((uint32_t)(row * 128 + col)));
        }
        uint32_t bfr[4][4];
        #pragma unroll
        for (int p = 0; p < 4; ++p) {
            int row = wn + p * 16 + i8 + (g >> 1) * 8;
            int col = kb + (g & 1) * 16;
            ldsm_x4(bfr[p], bBase + sw128((uint32_t)(row * 128 + col)));
        }
        #pragma unroll
        for (int mi = 0; mi < 2; ++mi)
            #pragma unroll
            for (int nj = 0; nj < 8; ++nj)
                mma16816(acc[mi][nj], afr[mi],
                         bfr[nj >> 1][(nj & 1) * 2],
                         bfr[nj >> 1][(nj & 1) * 2 + 1]);
    }
}

// ---------------------------------------------------------------------------
// convertAB: one pass. B: fp32 -> fp16 [hi|lo] row-major.
//            A: fp32 -> fp16 hi row-major (lo unused by corr) AND
//               [hi|lo] channel-transposed (for gram).
// ---------------------------------------------------------------------------
__global__ __launch_bounds__(256) void convertAB_kernel(const float* __restrict__ Ax,
                                                        const float* __restrict__ Bx)
{
    __shared__ float T[32][33];
    const int b  = blockIdx.z;
    const int m0 = blockIdx.x * 32;
    const int c0 = blockIdx.y * 32;
    const int tx = threadIdx.x & 31;
    const int ty = threadIdx.x >> 5;

    // ---- B: straight split convert ----
    __half* Br = g_Bh + (size_t)b * HW * K2;
    #pragma unroll
    for (int k = 0; k < 4; ++k) {
        int row = ty + k * 8;
        float v = Bx[((size_t)b * HW + m0 + row) * CH + c0 + tx];
        __half hi = __float2half(v);
        __half lo = __float2half(v - __half2float(hi));
        Br[(size_t)(m0 + row) * K2 + c0 + tx]      = hi;
        Br[(size_t)(m0 + row) * K2 + CH + c0 + tx] = lo;
    }

    // ---- A: hi convert + transpose ----
    __half* Ar = g_Ah + (size_t)b * HW * K2;
    #pragma unroll
    for (int k = 0; k < 4; ++k) {
        int row = ty + k * 8;
        float v = Ax[((size_t)b * HW + m0 + row) * CH + c0 + tx];
        T[row][tx] = v;
        Ar[(size_t)(m0 + row) * K2 + c0 + tx] = __float2half(v);
    }
    __syncthreads();

    __half* At = g_AhT + (size_t)b * K2 * HW;
    #pragma unroll
    for (int k = 0; k < 4; ++k) {
        int c = ty + k * 8;
        float v = T[tx][c];
        __half hi = __float2half(v);
        __half lo = __float2half(v - __half2float(hi));
        At[(size_t)(c0 + c) * HW + m0 + tx]      = hi;
        At[(size_t)(c0 + c + CH) * HW + m0 + tx] = lo;
    }
}

// ---------------------------------------------------------------------------
// gram_mma: symmetric — tiles (0,0),(1,1),(0,1). 3-term fp16 (18 chunk iters).
// ---------------------------------------------------------------------------
__global__ __launch_bounds__(256, 2) void gram_mma_kernel()
{
    extern __shared__ char smem[];
    const uint32_t smem_base = smem_u32(smem);
    const int tid  = threadIdx.x;
    const int wid  = tid >> 5;
    const int lane = tid & 31;

    const int b     = blockIdx.z / GSLICES;
    const int slice = blockIdx.z % GSLICES;
    const int t     = blockIdx.x;                 // 0:(0,0) 1:(128,128) 2:(0,128)
    const int c1_0  = (t == 1) ? 128 : 0;
    const int c2_0  = (t == 0) ? 0 : 128;

    const __half* At = g_AhT + (size_t)b * K2 * HW;

    uint32_t dstoff[8];
    const __half* srcp[8];
    bool isA[8];
    #pragma unroll
    for (int it = 0; it < 8; ++it) {
        int idx = it * 256 + tid;
        int li  = idx & 1023;
        int row = li >> 3;
        int seg = li & 7;
        isA[it] = (idx < 1024);
        dstoff[it] = (isA[it] ? 0u : (uint32_t)CHUNK_BYTES)
                   + sw128((uint32_t)(row * 128 + seg * 16));
        srcp[it] = At + (size_t)((isA[it] ? c1_0 : c2_0) + row) * HW + seg * 8;
    }

    const int NIT = 18;
    auto load_chunk = [&](int it, int buf) {
        const int term = it / 6, kc = it - term * 6;
        const size_t aoff = (size_t)(term == 1 ? CH : 0) * HW + slice * GK + kc * 64;
        const size_t boff = (size_t)(term == 2 ? CH : 0) * HW + slice * GK + kc * 64;
        const uint32_t base = smem_base + buf * BUF_BYTES;
        #pragma unroll
        for (int s = 0; s < 8; ++s)
            cp_async16(base + dstoff[s], srcp[s] + (isA[s] ? aoff : boff));
        cp_commit();
    };

    const int wm = (wid & 3) * 32;
    const int wn = (wid >> 2) * 64;
    float acc[2][8][4] = {};

    load_chunk(0, 0);
    load_chunk(1, 1);
    for (int c = 0; c < NIT; ++c) {
        if (c < NIT - 1) cp_wait<1>(); else cp_wait<0>();
        __syncthreads();
        const uint32_t aBase = smem_base + (c % NSTAGE) * BUF_BYTES;
        mma_chunk(aBase, aBase + CHUNK_BYTES, wm, wn, lane, acc);
        if (c + 2 < NIT) load_chunk(c + 2, (c + 2) % NSTAGE);
    }

    const int r    = lane >> 2;
    const int cpos = (lane & 3) * 2;
    #pragma unroll
    for (int mi = 0; mi < 2; ++mi) {
        const int row = c1_0 + wm + mi * 16 + r;
        float* o0 = &g_Gpart[slice][b][row][c2_0 + wn];
        float* o1 = o0 + 8 * CH;
        #pragma unroll
        for (int nj = 0; nj < 8; ++nj) {
            *(float2*)&o0[nj * 8 + cpos] = make_float2(acc[mi][nj][0], acc[mi][nj][1]);
            *(float2*)&o1[nj * 8 + cpos] = make_float2(acc[mi][nj][2], acc[mi][nj][3]);
        }
    }
}

// ---------------------------------------------------------------------------
// greduce: sum partials over computed tiles, write fp16 hi/lo; mirror (1,0).
// ---------------------------------------------------------------------------
__global__ __launch_bounds__(256) void greduce_kernel()
{
    const int per_b = 3 * 128 * 128;
    const int total = BATCH * per_b;
    const int full  = BATCH * CH * CH;
    const float* p = &g_Gpart[0][0][0][0];
    for (int i = blockIdx.x * blockDim.x + threadIdx.x; i < total;
         i += gridDim.x * blockDim.x) {
        int b   = i / per_b;
        int rem = i - b * per_b;
        int t   = rem >> 14;
        int r   = (rem >> 7) & 127;
        int cc  = rem & 127;
        int c   = ((t == 1) ? 128 : 0) + r;
        int c2  = ((t == 0) ? 0 : 128) + cc;

        size_t off = (size_t)b * CH * CH + (size_t)c * CH + c2;
        float s = 0.f;
        #pragma unroll
        for (int k = 0; k < GSLICES; ++k) s += p[(size_t)k * full + off];

        __half hi = __float2half(s);
        __half lo = __float2half(s - __half2float(hi));
        g_Gh[((size_t)b * K2 + c) * CH + c2]      = hi;
        g_Gh[((size_t)b * K2 + CH + c) * CH + c2] = lo;
        if (t == 2) {
            g_Gh[((size_t)b * K2 + c2) * CH + c]      = hi;
            g_Gh[((size_t)b * K2 + CH + c2) * CH + c] = lo;
        }
    }
}

// ---------------------------------------------------------------------------
// qrow_mma: V = U G (2-term fp16), fused epilogue q_part = rowsum(V .* U_fp32)
// ---------------------------------------------------------------------------
__global__ __launch_bounds__(256, 2) void qrow_mma_kernel(const float* __restrict__ Bin)
{
    extern __shared__ char smem[];
    const uint32_t smem_base = smem_u32(smem);
    const int tid  = threadIdx.x;
    const int wid  = tid >> 5;
    const int lane = tid & 31;

    const int ctile = blockIdx.x;
    const int n0    = blockIdx.y * 128;
    const int b     = blockIdx.z;

    const __half* Ub = g_Bh + ((size_t)b * HW + n0) * K2;
    const __half* Gb = g_Gh + (size_t)b * K2 * CH + (size_t)ctile * 128 * CH;

    uint32_t dstoff[8];
    const __half* srcp[8];
    bool isA[8];
    #pragma unroll
    for (int it = 0; it < 8; ++it) {
        int idx = it * 256 + tid;
        int li  = idx & 1023;
        int row = li >> 3;
        int seg = li & 7;
        isA[it] = (idx < 1024);
        dstoff[it] = (isA[it] ? 0u : (uint32_t)CHUNK_BYTES)
                   + sw128((uint32_t)(row * 128 + seg * 16));
        srcp[it] = (isA[it] ? Ub + (size_t)row * K2 : Gb + (size_t)row * CH) + seg * 8;
    }

    const int NIT = 8;
    auto load_chunk = [&](int it, int buf) {
        const int term = it >> 2, kc = it & 3;
        const size_t uoff = (size_t)(term == 1 ? CH : 0) + kc * 64;
        const size_t goff = (size_t)kc * 64;
        const uint32_t base = smem_base + buf * BUF_BYTES;
        #pragma unroll
        for (int s = 0; s < 8; ++s)
            cp_async16(base + dstoff[s], srcp[s] + (isA[s] ? uoff : goff));
        cp_commit();
    };

    const int wm = (wid & 3) * 32;
    const int wn = (wid >> 2) * 64;
    float acc[2][8][4] = {};

    load_chunk(0, 0);
    load_chunk(1, 1);
    for (int c = 0; c < NIT; ++c) {
        if (c < NIT - 1) cp_wait<1>(); else cp_wait<0>();
        __syncthreads();
        const uint32_t aBase = smem_base + (c % NSTAGE) * BUF_BYTES;
        mma_chunk(aBase, aBase + CHUNK_BYTES, wm, wn, lane, acc);
        if (c + 2 < NIT) load_chunk(c + 2, (c + 2) % NSTAGE);
    }
    __syncthreads();

    float* qs = (float*)smem;
    const int r    = lane >> 2;
    const int cpos = (lane & 3) * 2;

    float rs[2][2] = {};
    #pragma unroll
    for (int mi = 0; mi < 2; ++mi) {
        const size_t row0 = (size_t)b * HW + n0 + wm + mi * 16 + r;
        #pragma unroll
        for (int nj = 0; nj < 8; ++nj) {
            const int cc = ctile * 128 + wn + nj * 8 + cpos;
            float2 u0 = *(const float2*)&Bin[row0 * CH + cc];
            float2 u1 = *(const float2*)&Bin[(row0 + 8) * CH + cc];
            rs[mi][0] += acc[mi][nj][0] * u0.x + acc[mi][nj][1] * u0.y;
            rs[mi][1] += acc[mi][nj][2] * u1.x + acc[mi][nj][3] * u1.y;
        }
    }
    #pragma unroll
    for (int mi = 0; mi < 2; ++mi)
        #pragma unroll
        for (int h = 0; h < 2; ++h) {
            float v = rs[mi][h];
            v += __shfl_xor_sync(0xffffffffu, v, 1);
            v += __shfl_xor_sync(0xffffffffu, v, 2);
            rs[mi][h] = v;
        }
    if ((lane & 3) == 0) {
        #pragma unroll
        for (int mi = 0; mi < 2; ++mi)
            #pragma unroll
            for (int h = 0; h < 2; ++h)
                qs[(wid >> 2) * 128 + wm + mi * 16 + r + h * 8] = rs[mi][h];
    }
    __syncthreads();
    if (tid < 128)
        g_Qpart[b][ctile][n0 + tid] = qs[tid] + qs[128 + tid];
}

// ---------------------------------------------------------------------------
// corr_mma: 128x128 CTA tile, 8 warps (4x2), 3-stage pipeline.
// 1-term fp16: 4 K-chunks (hi . hi). Fused rsqrt-scale epilogue.
// ---------------------------------------------------------------------------
#define NCHUNK 4
__global__ __launch_bounds__(256, 2) void corr_mma_kernel(float* __restrict__ out)
{
    extern __shared__ char smem[];
    const uint32_t smem_base = smem_u32(smem);
    const int tid  = threadIdx.x;
    const int wid  = tid >> 5;
    const int lane = tid & 31;

    const int b  = blockIdx.z;
    const int m0 = blockIdx.y * 128;
    const int n0 = blockIdx.x * 128;

    const __half* Ab = g_Ah + ((size_t)b * HW + m0) * K2;
    const __half* Bb = g_Bh + ((size_t)b * HW + n0) * K2;

    uint32_t dstoff[8];
    const __half* srcp[8];
    bool isA[8];
    #pragma unroll
    for (int it = 0; it < 8; ++it) {
        int idx = it * 256 + tid;
        int li  = idx & 1023;
        int row = li >> 3;
        int seg = li & 7;
        isA[it] = (idx < 1024);
        dstoff[it] = (isA[it] ? 0u : (uint32_t)CHUNK_BYTES)
                   + sw128((uint32_t)(row * 128 + seg * 16));
        srcp[it] = (isA[it] ? Ab : Bb) + (size_t)row * K2 + seg * 8;
    }

    auto load_chunk = [&](int c, int buf) {
        const uint32_t base = smem_base + buf * BUF_BYTES;
        const int ko = c * 64;
        #pragma unroll
        for (int it = 0; it < 8; ++it)
            cp_async16(base + dstoff[it], srcp[it] + ko);
        cp_commit();
    };

    const int wm = (wid & 3) * 32;
    const int wn = (wid >> 2) * 64;
    float acc[2][8][4] = {};

    load_chunk(0, 0);
    load_chunk(1, 1);
    for (int c = 0; c < NCHUNK; ++c) {
        if (c < NCHUNK - 1) cp_wait<1>(); else cp_wait<0>();
        __syncthreads();
        const uint32_t aBase = smem_base + (c % NSTAGE) * BUF_BYTES;
        mma_chunk(aBase, aBase + CHUNK_BYTES, wm, wn, lane, acc);
        if (c + 2 < NCHUNK) load_chunk(c + 2, (c + 2) % NSTAGE);
    }
    __syncthreads();

    // fused scale: s = rsqrt(qp0+qp1), staged in smem
    float* sSc = (float*)smem;
    if (tid < 128)
        sSc[tid] = rsqrtf(g_Qpart[b][0][n0 + tid] + g_Qpart[b][1][n0 + tid]);
    __syncthreads();

    const int r    = lane >> 2;
    const int cpos = (lane & 3) * 2;
    #pragma unroll
    for (int mi = 0; mi < 2; ++mi) {
        const int mrow = m0 + wm + mi * 16 + r;
        float* o0 = out + ((size_t)b * HW + mrow) * HW + n0 + wn;
        float* o1 = o0 + (size_t)8 * HW;
        #pragma unroll
        for (int nj = 0; nj < 8; ++nj) {
            const int nc = wn + nj * 8 + cpos;
            const float s0 = sSc[nc], s1 = sSc[nc + 1];
            float2 v0 = make_float2(acc[mi][nj][0] * s0, acc[mi][nj][1] * s1);
            float2 v1 = make_float2(acc[mi][nj][2] * s0, acc[mi][nj][3] * s1);
            *(float2*)&o0[nj * 8 + cpos] = v0;
            *(float2*)&o1[nj * 8 + cpos] = v1;
        }
    }
}

// ---------------------------------------------------------------------------
extern "C" void kernel_launch(void* const* d_in, const int* in_sizes, int n_in,
                              void* d_out, int out_size)
{
    const float* A = (const float*)d_in[0];
    const float* B = (const float*)d_in[1];
    float* out = (float*)d_out;

    static bool init = false;
    if (!init) {
        init = true;
        cudaFuncSetAttribute(corr_mma_kernel,
                             cudaFuncAttributeMaxDynamicSharedMemorySize, SMEM_AUX);
        cudaFuncSetAttribute(gram_mma_kernel,
                             cudaFuncAttributeMaxDynamicSharedMemorySize, SMEM_AUX);
        cudaFuncSetAttribute(qrow_mma_kernel,
                             cudaFuncAttributeMaxDynamicSharedMemorySize, SMEM_AUX);
    }

    convertAB_kernel<<<dim3(HW / 32, CH / 32, BATCH), 256>>>(A, B);
    gram_mma_kernel<<<dim3(3, 1, BATCH * GSLICES), 256, SMEM_AUX>>>();
    greduce_kernel<<<1024, 256>>>();
    qrow_mma_kernel<<<dim3(2, HW / 128, BATCH), 256, SMEM_AUX>>>(B);
    corr_mma_kernel<<<dim3(HW / 128, HW / 128, BATCH), 256, SMEM_AUX>>>(out);
}

// round 13
// speedup vs baseline: 5.1882x; 1.0830x over previous
#include <cuda_runtime.h>
#include <cuda_fp16.h>
#include <cstdint>

#define BATCH 8
#define HW    2304        // 48*48
#define CH    256
#define K2    512         // scratch layout: [hi(256) | lo(256)]
#define GSLICES 6
#define GK     (HW / GSLICES)   // 384

// ---------------- scratch (device globals: allocation-free rule) -----------
__device__ float g_Gpart[GSLICES][BATCH][CH][CH];   // 12 MB (tile (1,0) unused)
__device__ float g_Qpart[BATCH][2][HW];             // 147 KB
__device__ __half g_Ah[(size_t)BATCH * HW * K2];    // 18.9 MB (lo half unused)
__device__ __half g_Bh[(size_t)BATCH * HW * K2];    // 18.9 MB
__device__ __half g_AhT[(size_t)BATCH * K2 * HW];   // 18.9 MB  [c(hi|lo)][m]
__device__ __half g_Gh[(size_t)BATCH * K2 * CH];    // 2 MB (lo half unused)

__device__ __forceinline__ uint32_t smem_u32(const void* p) {
    return (uint32_t)__cvta_generic_to_shared((void*)p);
}
__device__ __forceinline__ uint32_t sw128(uint32_t off) {
    return off ^ ((off >> 3) & 0x70);
}

__device__ __forceinline__ void ldsm_x4(uint32_t* r, uint32_t addr) {
    asm volatile("ldmatrix.sync.aligned.m8n8.x4.shared.b16 {%0,%1,%2,%3}, [%4];"
                 : "=r"(r[0]), "=r"(r[1]), "=r"(r[2]), "=r"(r[3]) : "r"(addr));
}
__device__ __forceinline__ void mma16816(float* c, const uint32_t* a,
                                         uint32_t b0, uint32_t b1) {
    asm volatile("mma.sync.aligned.m16n8k16.row.col.f32.f16.f16.f32 "
                 "{%0,%1,%2,%3}, {%4,%5,%6,%7}, {%8,%9}, {%0,%1,%2,%3};"
                 : "+f"(c[0]), "+f"(c[1]), "+f"(c[2]), "+f"(c[3])
                 : "r"(a[0]), "r"(a[1]), "r"(a[2]), "r"(a[3]), "r"(b0), "r"(b1));
}
__device__ __forceinline__ void cp_async16(uint32_t dst, const void* src) {
    asm volatile("cp.async.cg.shared.global [%0], [%1], 16;" :: "r"(dst), "l"(src));
}
__device__ __forceinline__ void cp_commit() {
    asm volatile("cp.async.commit_group;" ::: "memory");
}
template <int N> __device__ __forceinline__ void cp_wait() {
    asm volatile("cp.async.wait_group %0;" :: "n"(N) : "memory");
}

// ---- shared 128x128-tile GEMM pieces (8 warps, 4x2) -----------------------
#define CHUNK_BYTES 16384
#define BUF_BYTES   (2 * CHUNK_BYTES)
#define NSTAGE      3
#define SMEM_AUX    (NSTAGE * BUF_BYTES)    // 98304

__device__ __forceinline__ void mma_chunk(uint32_t aBase, uint32_t bBase,
                                          int wm, int wn, int lane,
                                          float acc[2][8][4])
{
    const int i8 = lane & 7;
    const int g  = lane >> 3;
    #pragma unroll
    for (int ks = 0; ks < 4; ++ks) {
        const int kb = ks * 32;
        uint32_t afr[2][4];
        #pragma unroll
        for (int mi = 0; mi < 2; ++mi) {
            int row = wm + mi * 16 + i8 + (g & 1) * 8;
            int col = kb + (g >> 1) * 16;
            ldsm_x4(afr[mi], aBase + sw128((uint32_t)(row * 128 + col)));
        }
        uint32_t bfr[4][4];
        #pragma unroll
        for (int p = 0; p < 4; ++p) {
            int row = wn + p * 16 + i8 + (g >> 1) * 8;
            int col = kb + (g & 1) * 16;
            ldsm_x4(bfr[p], bBase + sw128((uint32_t)(row * 128 + col)));
        }
        #pragma unroll
        for (int mi = 0; mi < 2; ++mi)
            #pragma unroll
            for (int nj = 0; nj < 8; ++nj)
                mma16816(acc[mi][nj], afr[mi],
                         bfr[nj >> 1][(nj & 1) * 2],
                         bfr[nj >> 1][(nj & 1) * 2 + 1]);
    }
}

// ---------------------------------------------------------------------------
// convertAB: one pass. B: fp32 -> fp16 [hi|lo] row-major.
//            A: fp32 -> fp16 hi row-major + [hi|lo] channel-transposed.
// ---------------------------------------------------------------------------
__global__ __launch_bounds__(256) void convertAB_kernel(const float* __restrict__ Ax,
                                                        const float* __restrict__ Bx)
{
    __shared__ float T[32][33];
    const int b  = blockIdx.z;
    const int m0 = blockIdx.x * 32;
    const int c0 = blockIdx.y * 32;
    const int tx = threadIdx.x & 31;
    const int ty = threadIdx.x >> 5;

    __half* Br = g_Bh + (size_t)b * HW * K2;
    #pragma unroll
    for (int k = 0; k < 4; ++k) {
        int row = ty + k * 8;
        float v = Bx[((size_t)b * HW + m0 + row) * CH + c0 + tx];
        __half hi = __float2half(v);
        __half lo = __float2half(v - __half2float(hi));
        Br[(size_t)(m0 + row) * K2 + c0 + tx]      = hi;
        Br[(size_t)(m0 + row) * K2 + CH + c0 + tx] = lo;
    }

    __half* Ar = g_Ah + (size_t)b * HW * K2;
    #pragma unroll
    for (int k = 0; k < 4; ++k) {
        int row = ty + k * 8;
        float v = Ax[((size_t)b * HW + m0 + row) * CH + c0 + tx];
        T[row][tx] = v;
        Ar[(size_t)(m0 + row) * K2 + c0 + tx] = __float2half(v);
    }
    __syncthreads();

    __half* At = g_AhT + (size_t)b * K2 * HW;
    #pragma unroll
    for (int k = 0; k < 4; ++k) {
        int c = ty + k * 8;
        float v = T[tx][c];
        __half hi = __float2half(v);
        __half lo = __float2half(v - __half2float(hi));
        At[(size_t)(c0 + c) * HW + m0 + tx]      = hi;
        At[(size_t)(c0 + c + CH) * HW + m0 + tx] = lo;
    }
}

// ---------------------------------------------------------------------------
// gram_mma: symmetric — tiles (0,0),(1,1),(0,1).
// 2-term fp16: hi.hi + lo.hi (12 chunk iters); hi.lo term dropped.
// ---------------------------------------------------------------------------
__global__ __launch_bounds__(256, 2) void gram_mma_kernel()
{
    extern __shared__ char smem[];
    const uint32_t smem_base = smem_u32(smem);
    const int tid  = threadIdx.x;
    const int wid  = tid >> 5;
    const int lane = tid & 31;

    const int b     = blockIdx.z / GSLICES;
    const int slice = blockIdx.z % GSLICES;
    const int t     = blockIdx.x;                 // 0:(0,0) 1:(128,128) 2:(0,128)
    const int c1_0  = (t == 1) ? 128 : 0;
    const int c2_0  = (t == 0) ? 0 : 128;

    const __half* At = g_AhT + (size_t)b * K2 * HW;

    uint32_t dstoff[8];
    const __half* srcp[8];
    bool isA[8];
    #pragma unroll
    for (int it = 0; it < 8; ++it) {
        int idx = it * 256 + tid;
        int li  = idx & 1023;
        int row = li >> 3;
        int seg = li & 7;
        isA[it] = (idx < 1024);
        dstoff[it] = (isA[it] ? 0u : (uint32_t)CHUNK_BYTES)
                   + sw128((uint32_t)(row * 128 + seg * 16));
        srcp[it] = At + (size_t)((isA[it] ? c1_0 : c2_0) + row) * HW + seg * 8;
    }

    const int NIT = 12;   // 2 terms x 6 chunks of 64 within GK=384
    auto load_chunk = [&](int it, int buf) {
        const int term = it / 6, kc = it - term * 6;
        const size_t aoff = (size_t)(term == 1 ? CH : 0) * HW + slice * GK + kc * 64;
        const size_t boff = (size_t)(slice * GK + kc * 64);
        const uint32_t base = smem_base + buf * BUF_BYTES;
        #pragma unroll
        for (int s = 0; s < 8; ++s)
            cp_async16(base + dstoff[s], srcp[s] + (isA[s] ? aoff : boff));
        cp_commit();
    };

    const int wm = (wid & 3) * 32;
    const int wn = (wid >> 2) * 64;
    float acc[2][8][4] = {};

    load_chunk(0, 0);
    load_chunk(1, 1);
    for (int c = 0; c < NIT; ++c) {
        if (c < NIT - 1) cp_wait<1>(); else cp_wait<0>();
        __syncthreads();
        const uint32_t aBase = smem_base + (c % NSTAGE) * BUF_BYTES;
        mma_chunk(aBase, aBase + CHUNK_BYTES, wm, wn, lane, acc);
        if (c + 2 < NIT) load_chunk(c + 2, (c + 2) % NSTAGE);
    }

    const int r    = lane >> 2;
    const int cpos = (lane & 3) * 2;
    #pragma unroll
    for (int mi = 0; mi < 2; ++mi) {
        const int row = c1_0 + wm + mi * 16 + r;
        float* o0 = &g_Gpart[slice][b][row][c2_0 + wn];
        float* o1 = o0 + 8 * CH;
        #pragma unroll
        for (int nj = 0; nj < 8; ++nj) {
            *(float2*)&o0[nj * 8 + cpos] = make_float2(acc[mi][nj][0], acc[mi][nj][1]);
            *(float2*)&o1[nj * 8 + cpos] = make_float2(acc[mi][nj][2], acc[mi][nj][3]);
        }
    }
}

// ---------------------------------------------------------------------------
// greduce: sum partials over computed tiles, write fp16 hi; mirror (1,0).
// ---------------------------------------------------------------------------
__global__ __launch_bounds__(256) void greduce_kernel()
{
    const int per_b = 3 * 128 * 128;
    const int total = BATCH * per_b;
    const int full  = BATCH * CH * CH;
    const float* p = &g_Gpart[0][0][0][0];
    for (int i = blockIdx.x * blockDim.x + threadIdx.x; i < total;
         i += gridDim.x * blockDim.x) {
        int b   = i / per_b;
        int rem = i - b * per_b;
        int t   = rem >> 14;
        int r   = (rem >> 7) & 127;
        int cc  = rem & 127;
        int c   = ((t == 1) ? 128 : 0) + r;
        int c2  = ((t == 0) ? 0 : 128) + cc;

        size_t off = (size_t)b * CH * CH + (size_t)c * CH + c2;
        float s = 0.f;
        #pragma unroll
        for (int k = 0; k < GSLICES; ++k) s += p[(size_t)k * full + off];

        __half hi = __float2half(s);
        g_Gh[((size_t)b * K2 + c) * CH + c2] = hi;
        if (t == 2)
            g_Gh[((size_t)b * K2 + c2) * CH + c] = hi;
    }
}

// ---------------------------------------------------------------------------
// qrow_mma: V = Uhi Ghi (1-term fp16, 4 chunk iters),
// fused epilogue q_part = rowsum(V .* U_fp32)
// ---------------------------------------------------------------------------
__global__ __launch_bounds__(256, 2) void qrow_mma_kernel(const float* __restrict__ Bin)
{
    extern __shared__ char smem[];
    const uint32_t smem_base = smem_u32(smem);
    const int tid  = threadIdx.x;
    const int wid  = tid >> 5;
    const int lane = tid & 31;

    const int ctile = blockIdx.x;
    const int n0    = blockIdx.y * 128;
    const int b     = blockIdx.z;

    const __half* Ub = g_Bh + ((size_t)b * HW + n0) * K2;
    const __half* Gb = g_Gh + (size_t)b * K2 * CH + (size_t)ctile * 128 * CH;

    uint32_t dstoff[8];
    const __half* srcp[8];
    bool isA[8];
    #pragma unroll
    for (int it = 0; it < 8; ++it) {
        int idx = it * 256 + tid;
        int li  = idx & 1023;
        int row = li >> 3;
        int seg = li & 7;
        isA[it] = (idx < 1024);
        dstoff[it] = (isA[it] ? 0u : (uint32_t)CHUNK_BYTES)
                   + sw128((uint32_t)(row * 128 + seg * 16));
        srcp[it] = (isA[it] ? Ub + (size_t)row * K2 : Gb + (size_t)row * CH) + seg * 8;
    }

    const int NIT = 4;   // 1 term x 4 chunks (U-hi . G-hi)
    auto load_chunk = [&](int it, int buf) {
        const size_t off = (size_t)it * 64;
        const uint32_t base = smem_base + buf * BUF_BYTES;
        #pragma unroll
        for (int s = 0; s < 8; ++s)
            cp_async16(base + dstoff[s], srcp[s] + off);
        cp_commit();
    };

    const int wm = (wid & 3) * 32;
    const int wn = (wid >> 2) * 64;
    float acc[2][8][4] = {};

    load_chunk(0, 0);
    load_chunk(1, 1);
    for (int c = 0; c < NIT; ++c) {
        if (c < NIT - 1) cp_wait<1>(); else cp_wait<0>();
        __syncthreads();
        const uint32_t aBase = smem_base + (c % NSTAGE) * BUF_BYTES;
        mma_chunk(aBase, aBase + CHUNK_BYTES, wm, wn, lane, acc);
        if (c + 2 < NIT) load_chunk(c + 2, (c + 2) % NSTAGE);
    }
    __syncthreads();

    float* qs = (float*)smem;
    const int r    = lane >> 2;
    const int cpos = (lane & 3) * 2;

    float rs[2][2] = {};
    #pragma unroll
    for (int mi = 0; mi < 2; ++mi) {
        const size_t row0 = (size_t)b * HW + n0 + wm + mi * 16 + r;
        #pragma unroll
        for (int nj = 0; nj < 8; ++nj) {
            const int cc = ctile * 128 + wn + nj * 8 + cpos;
            float2 u0 = *(const float2*)&Bin[row0 * CH + cc];
            float2 u1 = *(const float2*)&Bin[(row0 + 8) * CH + cc];
            rs[mi][0] += acc[mi][nj][0] * u0.x + acc[mi][nj][1] * u0.y;
            rs[mi][1] += acc[mi][nj][2] * u1.x + acc[mi][nj][3] * u1.y;
        }
    }
    #pragma unroll
    for (int mi = 0; mi < 2; ++mi)
        #pragma unroll
        for (int h = 0; h < 2; ++h) {
            float v = rs[mi][h];
            v += __shfl_xor_sync(0xffffffffu, v, 1);
            v += __shfl_xor_sync(0xffffffffu, v, 2);
            rs[mi][h] = v;
        }
    if ((lane & 3) == 0) {
        #pragma unroll
        for (int mi = 0; mi < 2; ++mi)
            #pragma unroll
            for (int h = 0; h < 2; ++h)
                qs[(wid >> 2) * 128 + wm + mi * 16 + r + h * 8] = rs[mi][h];
    }
    __syncthreads();
    if (tid < 128)
        g_Qpart[b][ctile][n0 + tid] = qs[tid] + qs[128 + tid];
}

// ---------------------------------------------------------------------------
// corr_mma: 128x128 CTA tile, 8 warps (4x2), 3-stage pipeline.
// 1-term fp16: 4 K-chunks (hi . hi). Fused rsqrt-scale epilogue.
// ---------------------------------------------------------------------------
#define NCHUNK 4
__global__ __launch_bounds__(256, 2) void corr_mma_kernel(float* __restrict__ out)
{
    extern __shared__ char smem[];
    const uint32_t smem_base = smem_u32(smem);
    const int tid  = threadIdx.x;
    const int wid  = tid >> 5;
    const int lane = tid & 31;

    const int b  = blockIdx.z;
    const int m0 = blockIdx.y * 128;
    const int n0 = blockIdx.x * 128;

    const __half* Ab = g_Ah + ((size_t)b * HW + m0) * K2;
    const __half* Bb = g_Bh + ((size_t)b * HW + n0) * K2;

    uint32_t dstoff[8];
    const __half* srcp[8];
    #pragma unroll
    for (int it = 0; it < 8; ++it) {
        int idx = it * 256 + tid;
        int li  = idx & 1023;
        int row = li >> 3;
        int seg = li & 7;
        bool isA = (idx < 1024);
        dstoff[it] = (isA ? 0u : (uint32_t)CHUNK_BYTES)
                   + sw128((uint32_t)(row * 128 + seg * 16));
        srcp[it] = (isA ? Ab : Bb) + (size_t)row * K2 + seg * 8;
    }

    auto load_chunk = [&](int c, int buf) {
        const uint32_t base = smem_base + buf * BUF_BYTES;
        const int ko = c * 64;
        #pragma unroll
        for (int it = 0; it < 8; ++it)
            cp_async16(base + dstoff[it], srcp[it] + ko);
        cp_commit();
    };

    const int wm = (wid & 3) * 32;
    const int wn = (wid >> 2) * 64;
    float acc[2][8][4] = {};

    load_chunk(0, 0);
    load_chunk(1, 1);
    for (int c = 0; c < NCHUNK; ++c) {
        if (c < NCHUNK - 1) cp_wait<1>(); else cp_wait<0>();
        __syncthreads();
        const uint32_t aBase = smem_base + (c % NSTAGE) * BUF_BYTES;
        mma_chunk(aBase, aBase + CHUNK_BYTES, wm, wn, lane, acc);
        if (c + 2 < NCHUNK) load_chunk(c + 2, (c + 2) % NSTAGE);
    }
    __syncthreads();

    // fused scale: s = rsqrt(qp0+qp1), staged in smem
    float* sSc = (float*)smem;
    if (tid < 128)
        sSc[tid] = rsqrtf(g_Qpart[b][0][n0 + tid] + g_Qpart[b][1][n0 + tid]);
    __syncthreads();

    const int r    = lane >> 2;
    const int cpos = (lane & 3) * 2;
    #pragma unroll
    for (int mi = 0; mi < 2; ++mi) {
        const int mrow = m0 + wm + mi * 16 + r;
        float* o0 = out + ((size_t)b * HW + mrow) * HW + n0 + wn;
        float* o1 = o0 + (size_t)8 * HW;
        #pragma unroll
        for (int nj = 0; nj < 8; ++nj) {
            const int nc = wn + nj * 8 + cpos;
            const float s0 = sSc[nc], s1 = sSc[nc + 1];
            float2 v0 = make_float2(acc[mi][nj][0] * s0, acc[mi][nj][1] * s1);
            float2 v1 = make_float2(acc[mi][nj][2] * s0, acc[mi][nj][3] * s1);
            *(float2*)&o0[nj * 8 + cpos] = v0;
            *(float2*)&o1[nj * 8 + cpos] = v1;
        }
    }
}

// ---------------------------------------------------------------------------
extern "C" void kernel_launch(void* const* d_in, const int* in_sizes, int n_in,
                              void* d_out, int out_size)
{
    const float* A = (const float*)d_in[0];
    const float* B = (const float*)d_in[1];
    float* out = (float*)d_out;

    static bool init = false;
    if (!init) {
        init = true;
        cudaFuncSetAttribute(corr_mma_kernel,
                             cudaFuncAttributeMaxDynamicSharedMemorySize, SMEM_AUX);
        cudaFuncSetAttribute(gram_mma_kernel,
                             cudaFuncAttributeMaxDynamicSharedMemorySize, SMEM_AUX);
        cudaFuncSetAttribute(qrow_mma_kernel,
                             cudaFuncAttributeMaxDynamicSharedMemorySize, SMEM_AUX);
    }

    convertAB_kernel<<<dim3(HW / 32, CH / 32, BATCH), 256>>>(A, B);
    gram_mma_kernel<<<dim3(3, 1, BATCH * GSLICES), 256, SMEM_AUX>>>();
    greduce_kernel<<<1024, 256>>>();
    qrow_mma_kernel<<<dim3(2, HW / 128, BATCH), 256, SMEM_AUX>>>(B);
    corr_mma_kernel<<<dim3(HW / 128, HW / 128, BATCH), 256, SMEM_AUX>>>(out);
}

// round 14
// speedup vs baseline: 5.3225x; 1.0259x over previous
#include <cuda_runtime.h>
#include <cuda_fp16.h>
#include <cstdint>

#define BATCH 8
#define HW    2304        // 48*48
#define CH    256
#define K2    512         // AhT layout: [hi(256) | lo(256)]
#define KH    256         // Ah/Bh hi-only row stride
#define GSLICES 6
#define GK     (HW / GSLICES)   // 384

// ---------------- scratch (device globals: allocation-free rule) -----------
__device__ float g_Gpart[GSLICES][BATCH][CH][CH];   // 12 MB (tile (1,0) unused)
__device__ float g_Qpart[BATCH][2][HW];             // 147 KB
__device__ __half g_Ah[(size_t)BATCH * HW * KH];    // 9.4 MB (hi only)
__device__ __half g_Bh[(size_t)BATCH * HW * KH];    // 9.4 MB (hi only)
__device__ __half g_AhT[(size_t)BATCH * K2 * HW];   // 18.9 MB  [c(hi|lo)][m]
__device__ __half g_Gh[(size_t)BATCH * CH * CH];    // 1 MB (hi only)

__device__ __forceinline__ uint32_t smem_u32(const void* p) {
    return (uint32_t)__cvta_generic_to_shared((void*)p);
}
__device__ __forceinline__ uint32_t sw128(uint32_t off) {
    return off ^ ((off >> 3) & 0x70);
}

__device__ __forceinline__ void ldsm_x4(uint32_t* r, uint32_t addr) {
    asm volatile("ldmatrix.sync.aligned.m8n8.x4.shared.b16 {%0,%1,%2,%3}, [%4];"
                 : "=r"(r[0]), "=r"(r[1]), "=r"(r[2]), "=r"(r[3]) : "r"(addr));
}
__device__ __forceinline__ void mma16816(float* c, const uint32_t* a,
                                         uint32_t b0, uint32_t b1) {
    asm volatile("mma.sync.aligned.m16n8k16.row.col.f32.f16.f16.f32 "
                 "{%0,%1,%2,%3}, {%4,%5,%6,%7}, {%8,%9}, {%0,%1,%2,%3};"
                 : "+f"(c[0]), "+f"(c[1]), "+f"(c[2]), "+f"(c[3])
                 : "r"(a[0]), "r"(a[1]), "r"(a[2]), "r"(a[3]), "r"(b0), "r"(b1));
}
__device__ __forceinline__ void cp_async16(uint32_t dst, const void* src) {
    asm volatile("cp.async.cg.shared.global [%0], [%1], 16;" :: "r"(dst), "l"(src));
}
__device__ __forceinline__ void cp_commit() {
    asm volatile("cp.async.commit_group;" ::: "memory");
}
template <int N> __device__ __forceinline__ void cp_wait() {
    asm volatile("cp.async.wait_group %0;" :: "n"(N) : "memory");
}

// ---- shared 128x128-tile GEMM pieces (8 warps, 4x2) -----------------------
#define CHUNK_BYTES 16384
#define BUF_BYTES   (2 * CHUNK_BYTES)
#define NSTAGE      3
#define SMEM_AUX    (NSTAGE * BUF_BYTES)    // 98304

__device__ __forceinline__ void mma_chunk(uint32_t aBase, uint32_t bBase,
                                          int wm, int wn, int lane,
                                          float acc[2][8][4])
{
    const int i8 = lane & 7;
    const int g  = lane >> 3;
    #pragma unroll
    for (int ks = 0; ks < 4; ++ks) {
        const int kb = ks * 32;
        uint32_t afr[2][4];
        #pragma unroll
        for (int mi = 0; mi < 2; ++mi) {
            int row = wm + mi * 16 + i8 + (g & 1) * 8;
            int col = kb + (g >> 1) * 16;
            ldsm_x4(afr[mi], aBase + sw128((uint32_t)(row * 128 + col)));
        }
        uint32_t bfr[4][4];
        #pragma unroll
        for (int p = 0; p < 4; ++p) {
            int row = wn + p * 16 + i8 + (g >> 1) * 8;
            int col = kb + (g & 1) * 16;
            ldsm_x4(bfr[p], bBase + sw128((uint32_t)(row * 128 + col)));
        }
        #pragma unroll
        for (int mi = 0; mi < 2; ++mi)
            #pragma unroll
            for (int nj = 0; nj < 8; ++nj)
                mma16816(acc[mi][nj], afr[mi],
                         bfr[nj >> 1][(nj & 1) * 2],
                         bfr[nj >> 1][(nj & 1) * 2 + 1]);
    }
}

// ---------------------------------------------------------------------------
// convertAB: vectorized one pass, 32m x 64c blocks.
//   B -> g_Bh hi (stride 256);  A -> g_Ah hi (stride 256) + g_AhT [hi|lo].
// ---------------------------------------------------------------------------
__global__ __launch_bounds__(256) void convertAB_kernel(const float* __restrict__ Ax,
                                                        const float* __restrict__ Bx)
{
    __shared__ float T[32][65];
    const int b   = blockIdx.z;
    const int m0  = blockIdx.x * 32;
    const int c0  = blockIdx.y * 64;
    const int tid = threadIdx.x;
    const int tx  = tid & 31;
    const int w   = tid >> 5;

    __half* Br = g_Bh + (size_t)b * HW * KH;
    __half* Ar = g_Ah + (size_t)b * HW * KH;
    #pragma unroll
    for (int k = 0; k < 4; ++k) {
        int m = w + k * 8;
        size_t grow = ((size_t)b * HW + m0 + m) * CH + c0 + tx * 2;
        float2 bv = *(const float2*)&Bx[grow];
        *(__half2*)&Br[(size_t)(m0 + m) * KH + c0 + tx * 2] =
            __halves2half2(__float2half(bv.x), __float2half(bv.y));
        float2 av = *(const float2*)&Ax[grow];
        T[m][tx * 2]     = av.x;
        T[m][tx * 2 + 1] = av.y;
        *(__half2*)&Ar[(size_t)(m0 + m) * KH + c0 + tx * 2] =
            __halves2half2(__float2half(av.x), __float2half(av.y));
    }
    __syncthreads();

    // transpose A -> AhT hi+lo: thread -> m-pair p = tid&15, c = (tid>>4)+16j
    __half* At = g_AhT + (size_t)b * K2 * HW;
    const int p  = tid & 15;
    const int cb = tid >> 4;
    #pragma unroll
    for (int j = 0; j < 4; ++j) {
        int c = cb + 16 * j;
        float v0 = T[p * 2][c], v1 = T[p * 2 + 1][c];
        __half h0 = __float2half(v0), h1 = __float2half(v1);
        __half l0 = __float2half(v0 - __half2float(h0));
        __half l1 = __float2half(v1 - __half2float(h1));
        *(__half2*)&At[(size_t)(c0 + c) * HW + m0 + p * 2]      = __halves2half2(h0, h1);
        *(__half2*)&At[(size_t)(c0 + c + CH) * HW + m0 + p * 2] = __halves2half2(l0, l1);
    }
}

// ---------------------------------------------------------------------------
// gram_mma: symmetric — tiles (0,0),(1,1),(0,1).
// 2-term fp16: hi.hi + lo.hi (12 chunk iters).
// ---------------------------------------------------------------------------
__global__ __launch_bounds__(256, 2) void gram_mma_kernel()
{
    extern __shared__ char smem[];
    const uint32_t smem_base = smem_u32(smem);
    const int tid  = threadIdx.x;
    const int wid  = tid >> 5;
    const int lane = tid & 31;

    const int b     = blockIdx.z / GSLICES;
    const int slice = blockIdx.z % GSLICES;
    const int t     = blockIdx.x;                 // 0:(0,0) 1:(128,128) 2:(0,128)
    const int c1_0  = (t == 1) ? 128 : 0;
    const int c2_0  = (t == 0) ? 0 : 128;

    const __half* At = g_AhT + (size_t)b * K2 * HW;

    uint32_t dstoff[8];
    const __half* srcp[8];
    bool isA[8];
    #pragma unroll
    for (int it = 0; it < 8; ++it) {
        int idx = it * 256 + tid;
        int li  = idx & 1023;
        int row = li >> 3;
        int seg = li & 7;
        isA[it] = (idx < 1024);
        dstoff[it] = (isA[it] ? 0u : (uint32_t)CHUNK_BYTES)
                   + sw128((uint32_t)(row * 128 + seg * 16));
        srcp[it] = At + (size_t)((isA[it] ? c1_0 : c2_0) + row) * HW + seg * 8;
    }

    const int NIT = 12;   // 2 terms x 6 chunks of 64 within GK=384
    auto load_chunk = [&](int it, int buf) {
        const int term = it / 6, kc = it - term * 6;
        const size_t aoff = (size_t)(term == 1 ? CH : 0) * HW + slice * GK + kc * 64;
        const size_t boff = (size_t)(slice * GK + kc * 64);
        const uint32_t base = smem_base + buf * BUF_BYTES;
        #pragma unroll
        for (int s = 0; s < 8; ++s)
            cp_async16(base + dstoff[s], srcp[s] + (isA[s] ? aoff : boff));
        cp_commit();
    };

    const int wm = (wid & 3) * 32;
    const int wn = (wid >> 2) * 64;
    float acc[2][8][4] = {};

    load_chunk(0, 0);
    load_chunk(1, 1);
    for (int c = 0; c < NIT; ++c) {
        if (c < NIT - 1) cp_wait<1>(); else cp_wait<0>();
        __syncthreads();
        const uint32_t aBase = smem_base + (c % NSTAGE) * BUF_BYTES;
        mma_chunk(aBase, aBase + CHUNK_BYTES, wm, wn, lane, acc);
        if (c + 2 < NIT) load_chunk(c + 2, (c + 2) % NSTAGE);
    }

    const int r    = lane >> 2;
    const int cpos = (lane & 3) * 2;
    #pragma unroll
    for (int mi = 0; mi < 2; ++mi) {
        const int row = c1_0 + wm + mi * 16 + r;
        float* o0 = &g_Gpart[slice][b][row][c2_0 + wn];
        float* o1 = o0 + 8 * CH;
        #pragma unroll
        for (int nj = 0; nj < 8; ++nj) {
            *(float2*)&o0[nj * 8 + cpos] = make_float2(acc[mi][nj][0], acc[mi][nj][1]);
            *(float2*)&o1[nj * 8 + cpos] = make_float2(acc[mi][nj][2], acc[mi][nj][3]);
        }
    }
}

// ---------------------------------------------------------------------------
// greduce: float4-vectorized sum of partials; write fp16 hi; mirror (1,0).
// ---------------------------------------------------------------------------
__global__ __launch_bounds__(256) void greduce_kernel()
{
    const int per_b = 3 * 128 * 32;           // float4 units per batch
    const int total = BATCH * per_b;          // 98304
    const int full  = BATCH * CH * CH;
    const float* p = &g_Gpart[0][0][0][0];
    for (int i = blockIdx.x * blockDim.x + threadIdx.x; i < total;
         i += gridDim.x * blockDim.x) {
        int b   = i / per_b;
        int rem = i - b * per_b;
        int t   = rem >> 12;
        int r2  = rem & 4095;
        int r   = r2 >> 5;
        int cc  = (r2 & 31) * 4;
        int c   = ((t == 1) ? 128 : 0) + r;
        int c2  = ((t == 0) ? 0 : 128) + cc;

        size_t off = (size_t)b * CH * CH + (size_t)c * CH + c2;
        float4 s = make_float4(0.f, 0.f, 0.f, 0.f);
        #pragma unroll
        for (int k = 0; k < GSLICES; ++k) {
            float4 v = *(const float4*)&p[(size_t)k * full + off];
            s.x += v.x; s.y += v.y; s.z += v.z; s.w += v.w;
        }
        __half h0 = __float2half(s.x), h1 = __float2half(s.y);
        __half h2 = __float2half(s.z), h3 = __float2half(s.w);
        *(__half2*)&g_Gh[((size_t)b * CH + c) * CH + c2]     = __halves2half2(h0, h1);
        *(__half2*)&g_Gh[((size_t)b * CH + c) * CH + c2 + 2] = __halves2half2(h2, h3);
        if (t == 2) {
            g_Gh[((size_t)b * CH + c2 + 0) * CH + c] = h0;
            g_Gh[((size_t)b * CH + c2 + 1) * CH + c] = h1;
            g_Gh[((size_t)b * CH + c2 + 2) * CH + c] = h2;
            g_Gh[((size_t)b * CH + c2 + 3) * CH + c] = h3;
        }
    }
}

// ---------------------------------------------------------------------------
// qrow_mma: V = Uhi Ghi (1-term fp16, 4 chunk iters),
// fused epilogue q_part = rowsum(V .* U_fp32)
// ---------------------------------------------------------------------------
__global__ __launch_bounds__(256, 2) void qrow_mma_kernel(const float* __restrict__ Bin)
{
    extern __shared__ char smem[];
    const uint32_t smem_base = smem_u32(smem);
    const int tid  = threadIdx.x;
    const int wid  = tid >> 5;
    const int lane = tid & 31;

    const int ctile = blockIdx.x;
    const int n0    = blockIdx.y * 128;
    const int b     = blockIdx.z;

    const __half* Ub = g_Bh + ((size_t)b * HW + n0) * KH;
    const __half* Gb = g_Gh + (size_t)b * CH * CH + (size_t)ctile * 128 * CH;

    uint32_t dstoff[8];
    const __half* srcp[8];
    #pragma unroll
    for (int it = 0; it < 8; ++it) {
        int idx = it * 256 + tid;
        int li  = idx & 1023;
        int row = li >> 3;
        int seg = li & 7;
        bool isA = (idx < 1024);
        dstoff[it] = (isA ? 0u : (uint32_t)CHUNK_BYTES)
                   + sw128((uint32_t)(row * 128 + seg * 16));
        srcp[it] = (isA ? Ub + (size_t)row * KH : Gb + (size_t)row * CH) + seg * 8;
    }

    const int NIT = 4;   // 1 term x 4 chunks (U-hi . G-hi)
    auto load_chunk = [&](int it, int buf) {
        const size_t off = (size_t)it * 64;
        const uint32_t base = smem_base + buf * BUF_BYTES;
        #pragma unroll
        for (int s = 0; s < 8; ++s)
            cp_async16(base + dstoff[s], srcp[s] + off);
        cp_commit();
    };

    const int wm = (wid & 3) * 32;
    const int wn = (wid >> 2) * 64;
    float acc[2][8][4] = {};

    load_chunk(0, 0);
    load_chunk(1, 1);
    for (int c = 0; c < NIT; ++c) {
        if (c < NIT - 1) cp_wait<1>(); else cp_wait<0>();
        __syncthreads();
        const uint32_t aBase = smem_base + (c % NSTAGE) * BUF_BYTES;
        mma_chunk(aBase, aBase + CHUNK_BYTES, wm, wn, lane, acc);
        if (c + 2 < NIT) load_chunk(c + 2, (c + 2) % NSTAGE);
    }
    __syncthreads();

    float* qs = (float*)smem;
    const int r    = lane >> 2;
    const int cpos = (lane & 3) * 2;

    float rs[2][2] = {};
    #pragma unroll
    for (int mi = 0; mi < 2; ++mi) {
        const size_t row0 = (size_t)b * HW + n0 + wm + mi * 16 + r;
        #pragma unroll
        for (int nj = 0; nj < 8; ++nj) {
            const int cc = ctile * 128 + wn + nj * 8 + cpos;
            float2 u0 = *(const float2*)&Bin[row0 * CH + cc];
            float2 u1 = *(const float2*)&Bin[(row0 + 8) * CH + cc];
            rs[mi][0] += acc[mi][nj][0] * u0.x + acc[mi][nj][1] * u0.y;
            rs[mi][1] += acc[mi][nj][2] * u1.x + acc[mi][nj][3] * u1.y;
        }
    }
    #pragma unroll
    for (int mi = 0; mi < 2; ++mi)
        #pragma unroll
        for (int h = 0; h < 2; ++h) {
            float v = rs[mi][h];
            v += __shfl_xor_sync(0xffffffffu, v, 1);
            v += __shfl_xor_sync(0xffffffffu, v, 2);
            rs[mi][h] = v;
        }
    if ((lane & 3) == 0) {
        #pragma unroll
        for (int mi = 0; mi < 2; ++mi)
            #pragma unroll
            for (int h = 0; h < 2; ++h)
                qs[(wid >> 2) * 128 + wm + mi * 16 + r + h * 8] = rs[mi][h];
    }
    __syncthreads();
    if (tid < 128)
        g_Qpart[b][ctile][n0 + tid] = qs[tid] + qs[128 + tid];
}

// ---------------------------------------------------------------------------
// corr_mma: 128x128 CTA tile, 8 warps (4x2), 3-stage pipeline.
// 1-term fp16: 4 K-chunks (hi . hi). Prefetched rsqrt-scale epilogue.
// ---------------------------------------------------------------------------
#define NCHUNK 4
__global__ __launch_bounds__(256, 2) void corr_mma_kernel(float* __restrict__ out)
{
    extern __shared__ char smem[];
    const uint32_t smem_base = smem_u32(smem);
    const int tid  = threadIdx.x;
    const int wid  = tid >> 5;
    const int lane = tid & 31;

    const int b  = blockIdx.z;
    const int m0 = blockIdx.y * 128;
    const int n0 = blockIdx.x * 128;

    // prefetch scale early (hides the global-read latency behind the mainloop)
    float spre = 0.f;
    if (tid < 128)
        spre = rsqrtf(g_Qpart[b][0][n0 + tid] + g_Qpart[b][1][n0 + tid]);

    const __half* Ab = g_Ah + ((size_t)b * HW + m0) * KH;
    const __half* Bb = g_Bh + ((size_t)b * HW + n0) * KH;

    uint32_t dstoff[8];
    const __half* srcp[8];
    #pragma unroll
    for (int it = 0; it < 8; ++it) {
        int idx = it * 256 + tid;
        int li  = idx & 1023;
        int row = li >> 3;
        int seg = li & 7;
        bool isA = (idx < 1024);
        dstoff[it] = (isA ? 0u : (uint32_t)CHUNK_BYTES)
                   + sw128((uint32_t)(row * 128 + seg * 16));
        srcp[it] = (isA ? Ab : Bb) + (size_t)row * KH + seg * 8;
    }

    auto load_chunk = [&](int c, int buf) {
        const uint32_t base = smem_base + buf * BUF_BYTES;
        const int ko = c * 64;
        #pragma unroll
        for (int it = 0; it < 8; ++it)
            cp_async16(base + dstoff[it], srcp[it] + ko);
        cp_commit();
    };

    const int wm = (wid & 3) * 32;
    const int wn = (wid >> 2) * 64;
    float acc[2][8][4] = {};

    load_chunk(0, 0);
    load_chunk(1, 1);
    for (int c = 0; c < NCHUNK; ++c) {
        if (c < NCHUNK - 1) cp_wait<1>(); else cp_wait<0>();
        __syncthreads();
        const uint32_t aBase = smem_base + (c % NSTAGE) * BUF_BYTES;
        mma_chunk(aBase, aBase + CHUNK_BYTES, wm, wn, lane, acc);
        if (c + 2 < NCHUNK) load_chunk(c + 2, (c + 2) % NSTAGE);
    }
    __syncthreads();

    float* sSc = (float*)smem;
    if (tid < 128) sSc[tid] = spre;
    __syncthreads();

    const int r    = lane >> 2;
    const int cpos = (lane & 3) * 2;
    #pragma unroll
    for (int mi = 0; mi < 2; ++mi) {
        const int mrow = m0 + wm + mi * 16 + r;
        float* o0 = out + ((size_t)b * HW + mrow) * HW + n0 + wn;
        float* o1 = o0 + (size_t)8 * HW;
        #pragma unroll
        for (int nj = 0; nj < 8; ++nj) {
            const int nc = wn + nj * 8 + cpos;
            const float s0 = sSc[nc], s1 = sSc[nc + 1];
            float2 v0 = make_float2(acc[mi][nj][0] * s0, acc[mi][nj][1] * s1);
            float2 v1 = make_float2(acc[mi][nj][2] * s0, acc[mi][nj][3] * s1);
            *(float2*)&o0[nj * 8 + cpos] = v0;
            *(float2*)&o1[nj * 8 + cpos] = v1;
        }
    }
}

// ---------------------------------------------------------------------------
extern "C" void kernel_launch(void* const* d_in, const int* in_sizes, int n_in,
                              void* d_out, int out_size)
{
    const float* A = (const float*)d_in[0];
    const float* B = (const float*)d_in[1];
    float* out = (float*)d_out;

    static bool init = false;
    if (!init) {
        init = true;
        cudaFuncSetAttribute(corr_mma_kernel,
                             cudaFuncAttributeMaxDynamicSharedMemorySize, SMEM_AUX);
        cudaFuncSetAttribute(gram_mma_kernel,
                             cudaFuncAttributeMaxDynamicSharedMemorySize, SMEM_AUX);
        cudaFuncSetAttribute(qrow_mma_kernel,
                             cudaFuncAttributeMaxDynamicSharedMemorySize, SMEM_AUX);
    }

    convertAB_kernel<<<dim3(HW / 32, CH / 64, BATCH), 256>>>(A, B);
    gram_mma_kernel<<<dim3(3, 1, BATCH * GSLICES), 256, SMEM_AUX>>>();
    greduce_kernel<<<384, 256>>>();
    qrow_mma_kernel<<<dim3(2, HW / 128, BATCH), 256, SMEM_AUX>>>(B);
    corr_mma_kernel<<<dim3(HW / 128, HW / 128, BATCH), 256, SMEM_AUX>>>(out);
}